// round 1
// baseline (speedup 1.0000x reference)
#include <cuda_runtime.h>

#define NN 4096
#define FDIM 256
#define ALPHA_LR 0.01f
#define NEG_INF_V -9.0e15f

// Scratch (allocation-free rule: __device__ globals)
__device__ __align__(16) float g_h[NN * FDIM];
__device__ __align__(16) float g_Wh[NN * FDIM];
__device__ float g_f1[NN];
__device__ float g_f2[NN];

// ---------------------------------------------------------------------------
// GEMM: C[4096,256] = A[4096,256] @ B[256,256]  (fp32, 64x64 tiles, 4x4 micro)
// ---------------------------------------------------------------------------
__global__ void gemm_kernel(const float* __restrict__ A,
                            const float* __restrict__ B,
                            float* __restrict__ C) {
    __shared__ __align__(16) float As[16][64];
    __shared__ __align__(16) float Bs[16][64];
    const int tid = threadIdx.x;
    const int tx = tid & 15;
    const int ty = tid >> 4;
    const int blockRow = blockIdx.y * 64;
    const int blockCol = blockIdx.x * 64;

    float acc[4][4] = {};

    for (int kk = 0; kk < FDIM; kk += 16) {
        // A tile 64x16 -> As[k][row] (transposed store)
        {
            int r  = tid >> 2;          // 0..63
            int kq = (tid & 3) * 4;     // 0,4,8,12
            float4 v = *reinterpret_cast<const float4*>(
                &A[(blockRow + r) * FDIM + kk + kq]);
            As[kq + 0][r] = v.x;
            As[kq + 1][r] = v.y;
            As[kq + 2][r] = v.z;
            As[kq + 3][r] = v.w;
        }
        // B tile 16x64 -> Bs[k][col]
        {
            int k = tid >> 4;           // 0..15
            int c = (tid & 15) * 4;
            *reinterpret_cast<float4*>(&Bs[k][c]) =
                *reinterpret_cast<const float4*>(
                    &B[(kk + k) * FDIM + blockCol + c]);
        }
        __syncthreads();
        #pragma unroll
        for (int k = 0; k < 16; k++) {
            float4 av = *reinterpret_cast<float4*>(&As[k][ty * 4]);
            float4 bv = *reinterpret_cast<float4*>(&Bs[k][tx * 4]);
            float a4[4] = {av.x, av.y, av.z, av.w};
            float b4[4] = {bv.x, bv.y, bv.z, bv.w};
            #pragma unroll
            for (int i = 0; i < 4; i++)
                #pragma unroll
                for (int j = 0; j < 4; j++)
                    acc[i][j] += a4[i] * b4[j];
        }
        __syncthreads();
    }
    #pragma unroll
    for (int i = 0; i < 4; i++) {
        float4 v = make_float4(acc[i][0], acc[i][1], acc[i][2], acc[i][3]);
        *reinterpret_cast<float4*>(
            &C[(blockRow + ty * 4 + i) * FDIM + blockCol + tx * 4]) = v;
    }
}

// ---------------------------------------------------------------------------
// f1[i] = Wh[i,:] . a[0:256],  f2[i] = Wh[i,:] . a[256:512]   (1 warp / row)
// ---------------------------------------------------------------------------
__global__ void fvec_kernel(const float* __restrict__ Wh,
                            const float* __restrict__ a,
                            float* __restrict__ f1,
                            float* __restrict__ f2) {
    const int warp = threadIdx.x >> 5;
    const int lane = threadIdx.x & 31;
    const int row  = blockIdx.x * 8 + warp;
    float s1 = 0.f, s2 = 0.f;
    #pragma unroll
    for (int k = lane; k < FDIM; k += 32) {
        float w = Wh[row * FDIM + k];
        s1 += w * a[k];
        s2 += w * a[FDIM + k];
    }
    #pragma unroll
    for (int off = 16; off; off >>= 1) {
        s1 += __shfl_xor_sync(0xffffffffu, s1, off);
        s2 += __shfl_xor_sync(0xffffffffu, s2, off);
    }
    if (lane == 0) { f1[row] = s1; f2[row] = s2; }
}

// ---------------------------------------------------------------------------
// Fused masked-softmax attention + ELU:
//   out[i,:] = ELU( softmax_j( mask(leaky(f1_i+f2_j)) ) @ Wh )
// CTA: 32 rows x 128 features (blockIdx.y = feature half), j tiles of 64.
// Online softmax; Wh tile + probabilities staged in SMEM. 256 threads,
// each thread owns a 4 rows x 4 feats micro tile.
// ---------------------------------------------------------------------------
__global__ void attn_kernel(const float* __restrict__ Wh,
                            const int* __restrict__ adj,
                            const float* __restrict__ f1,
                            const float* __restrict__ f2,
                            float* __restrict__ out) {
    __shared__ float4 Wh_s[64 * 32];     // [j][c4]  32 KB
    __shared__ float  p_s[32][64];       // scores / probs  8 KB
    __shared__ float  m_s[32], l_s[32], corr_s[32];

    const int tid  = threadIdx.x;
    const int tx   = tid & 31;           // feature group (float4 index)
    const int ty   = tid >> 5;           // row group 0..7
    const int row0 = blockIdx.x * 32;
    const int fb4  = blockIdx.y * 32;    // float4 offset of feature block
    const float4* whg = reinterpret_cast<const float4*>(Wh);

    if (tid < 32) { m_s[tid] = -3.0e38f; l_s[tid] = 0.f; }
    float acc[4][4] = {};
    __syncthreads();

    for (int j0 = 0; j0 < NN; j0 += 64) {
        // Stage Wh tile: 64 j x 32 float4 (coalesced, L2-resident)
        #pragma unroll
        for (int idx = tid; idx < 64 * 32; idx += 256) {
            int j = idx >> 5, c = idx & 31;
            Wh_s[idx] = whg[(j0 + j) * (FDIM / 4) + fb4 + c];
        }
        // Raw masked scores: 32 rows x 64 j
        #pragma unroll
        for (int idx = tid; idx < 2048; idx += 256) {
            int r = idx >> 6, j = idx & 63;
            int ad = adj[(row0 + r) * NN + j0 + j];
            float sr = f1[row0 + r] + f2[j0 + j];
            float e = sr > 0.f ? sr : ALPHA_LR * sr;
            p_s[r][j] = (ad > 0) ? e : NEG_INF_V;
        }
        __syncthreads();

        // Per-row online softmax update (one lane per row)
        if (tid < 32) {
            const int r = tid;
            float mt = -3.0e38f;
            #pragma unroll 8
            for (int j = 0; j < 64; j++) mt = fmaxf(mt, p_s[r][j]);
            float mo = m_s[r];
            float mn = fmaxf(mo, mt);
            float corr = __expf(mo - mn);
            float ls = 0.f;
            #pragma unroll 8
            for (int j = 0; j < 64; j++) {
                float pv = __expf(p_s[r][j] - mn);
                p_s[r][j] = pv;
                ls += pv;
            }
            m_s[r] = mn;
            corr_s[r] = corr;
            l_s[r] = l_s[r] * corr + ls;
        }
        __syncthreads();

        // Rescale + accumulate: acc += P[32x64] @ Wh_s[64x128]
        #pragma unroll
        for (int i = 0; i < 4; i++) {
            float c = corr_s[ty * 4 + i];
            acc[i][0] *= c; acc[i][1] *= c; acc[i][2] *= c; acc[i][3] *= c;
        }
        #pragma unroll 4
        for (int j = 0; j < 64; j++) {
            float4 wv = Wh_s[j * 32 + tx];
            #pragma unroll
            for (int i = 0; i < 4; i++) {
                float pv = p_s[ty * 4 + i][j];       // warp-broadcast LDS
                acc[i][0] += pv * wv.x;
                acc[i][1] += pv * wv.y;
                acc[i][2] += pv * wv.z;
                acc[i][3] += pv * wv.w;
            }
        }
        __syncthreads();
    }

    // Epilogue: normalize, ELU, store
    #pragma unroll
    for (int i = 0; i < 4; i++) {
        int r = row0 + ty * 4 + i;
        float inv = 1.f / l_s[ty * 4 + i];
        float4 v;
        v.x = acc[i][0] * inv;
        v.y = acc[i][1] * inv;
        v.z = acc[i][2] * inv;
        v.w = acc[i][3] * inv;
        v.x = v.x > 0.f ? v.x : expm1f(v.x);
        v.y = v.y > 0.f ? v.y : expm1f(v.y);
        v.z = v.z > 0.f ? v.z : expm1f(v.z);
        v.w = v.w > 0.f ? v.w : expm1f(v.w);
        reinterpret_cast<float4*>(out)[r * (FDIM / 4) + fb4 + tx] = v;
    }
}

// ---------------------------------------------------------------------------
extern "C" void kernel_launch(void* const* d_in, const int* in_sizes, int n_in,
                              void* d_out, int out_size) {
    const float* input = (const float*)d_in[0];
    const int*   adj   = (const int*)  d_in[1];
    const float* W0    = (const float*)d_in[2];
    const float* Wl[3] = {(const float*)d_in[3], (const float*)d_in[5],
                          (const float*)d_in[7]};
    const float* al[3] = {(const float*)d_in[4], (const float*)d_in[6],
                          (const float*)d_in[8]};
    float* out = (float*)d_out;

    float *h, *Wh, *f1, *f2;
    cudaGetSymbolAddress((void**)&h,  g_h);
    cudaGetSymbolAddress((void**)&Wh, g_Wh);
    cudaGetSymbolAddress((void**)&f1, g_f1);
    cudaGetSymbolAddress((void**)&f2, g_f2);

    dim3 gemmGrid(FDIM / 64, NN / 64);   // (4, 64)
    dim3 attnGrid(NN / 32, 2);           // (128, 2)

    // h = input @ W0
    gemm_kernel<<<gemmGrid, 256>>>(input, W0, h);

    for (int l = 0; l < 3; l++) {
        gemm_kernel<<<gemmGrid, 256>>>(h, Wl[l], Wh);
        fvec_kernel<<<NN / 8, 256>>>(Wh, al[l], f1, f2);
        float* dst = (l == 2) ? out : h;
        attn_kernel<<<attnGrid, 256>>>(Wh, adj, f1, f2, dst);
    }
}

// round 4
// speedup vs baseline: 2.1011x; 2.1011x over previous
#include <cuda_runtime.h>

#define NN 4096
#define FDIM 256
#define ALPHA_LR 0.01f
#define NEG_INF_V -9.0e15f

// Scratch (allocation-free rule: __device__ globals)
__device__ __align__(16) float g_h[NN * FDIM];
__device__ __align__(16) float g_Wh[NN * FDIM];
__device__ float g_f1[NN];
__device__ float g_f2[NN];
__device__ float g_m[NN];

union F4U { float4 f; ulonglong2 u; };

__device__ __forceinline__ void fma2(unsigned long long& d,
                                     unsigned long long a,
                                     unsigned long long b) {
    asm("fma.rn.f32x2 %0, %1, %2, %0;" : "+l"(d) : "l"(a), "l"(b));
}

// ---------------------------------------------------------------------------
// GEMM: C[4096,256] = A[4096,256] @ B[256,256]
// ---------------------------------------------------------------------------
__global__ void gemm_kernel(const float* __restrict__ A,
                            const float* __restrict__ B,
                            float* __restrict__ C) {
    __shared__ __align__(16) float As[16][64];
    __shared__ __align__(16) float Bs[16][64];
    const int tid = threadIdx.x;
    const int tx = tid & 15;
    const int ty = tid >> 4;
    const int blockRow = blockIdx.y * 64;
    const int blockCol = blockIdx.x * 64;

    float acc[4][4] = {};

    for (int kk = 0; kk < FDIM; kk += 16) {
        {
            int r  = tid >> 2;
            int kq = (tid & 3) * 4;
            float4 v = *reinterpret_cast<const float4*>(
                &A[(blockRow + r) * FDIM + kk + kq]);
            As[kq + 0][r] = v.x;
            As[kq + 1][r] = v.y;
            As[kq + 2][r] = v.z;
            As[kq + 3][r] = v.w;
        }
        {
            int k = tid >> 4;
            int c = (tid & 15) * 4;
            *reinterpret_cast<float4*>(&Bs[k][c]) =
                *reinterpret_cast<const float4*>(
                    &B[(kk + k) * FDIM + blockCol + c]);
        }
        __syncthreads();
        #pragma unroll
        for (int k = 0; k < 16; k++) {
            float4 av = *reinterpret_cast<float4*>(&As[k][ty * 4]);
            float4 bv = *reinterpret_cast<float4*>(&Bs[k][tx * 4]);
            float a4[4] = {av.x, av.y, av.z, av.w};
            float b4[4] = {bv.x, bv.y, bv.z, bv.w};
            #pragma unroll
            for (int i = 0; i < 4; i++)
                #pragma unroll
                for (int j = 0; j < 4; j++)
                    acc[i][j] += a4[i] * b4[j];
        }
        __syncthreads();
    }
    #pragma unroll
    for (int i = 0; i < 4; i++) {
        float4 v = make_float4(acc[i][0], acc[i][1], acc[i][2], acc[i][3]);
        *reinterpret_cast<float4*>(
            &C[(blockRow + ty * 4 + i) * FDIM + blockCol + tx * 4]) = v;
    }
}

// ---------------------------------------------------------------------------
// f1[i] = Wh[i,:] . a[0:256],  f2[i] = Wh[i,:] . a[256:512]
// ---------------------------------------------------------------------------
__global__ void fvec_kernel(const float* __restrict__ Wh,
                            const float* __restrict__ a,
                            float* __restrict__ f1,
                            float* __restrict__ f2) {
    const int warp = threadIdx.x >> 5;
    const int lane = threadIdx.x & 31;
    const int row  = blockIdx.x * 8 + warp;
    float s1 = 0.f, s2 = 0.f;
    #pragma unroll
    for (int k = lane; k < FDIM; k += 32) {
        float w = Wh[row * FDIM + k];
        s1 += w * a[k];
        s2 += w * a[FDIM + k];
    }
    #pragma unroll
    for (int off = 16; off; off >>= 1) {
        s1 += __shfl_xor_sync(0xffffffffu, s1, off);
        s2 += __shfl_xor_sync(0xffffffffu, s2, off);
    }
    if (lane == 0) { f1[row] = s1; f2[row] = s2; }
}

// ---------------------------------------------------------------------------
// Row max of masked leaky scores (exact): m[i] = max_j score(i,j).
// ---------------------------------------------------------------------------
__global__ void rowmax_kernel(const int* __restrict__ adj,
                              const float* __restrict__ f1,
                              const float* __restrict__ f2,
                              float* __restrict__ m) {
    const int warp = threadIdx.x >> 5;
    const int lane = threadIdx.x & 31;
    const int row  = blockIdx.x * 8 + warp;
    const float f1r = f1[row];
    float mx = NEG_INF_V;
    #pragma unroll 4
    for (int it = 0; it < NN / 128; it++) {
        int j = it * 128 + lane * 4;
        int4   a  = *reinterpret_cast<const int4*>(&adj[row * NN + j]);
        float4 fv = *reinterpret_cast<const float4*>(&f2[j]);
        float s, e;
        s = f1r + fv.x; e = s > 0.f ? s : ALPHA_LR * s; if (a.x > 0) mx = fmaxf(mx, e);
        s = f1r + fv.y; e = s > 0.f ? s : ALPHA_LR * s; if (a.y > 0) mx = fmaxf(mx, e);
        s = f1r + fv.z; e = s > 0.f ? s : ALPHA_LR * s; if (a.z > 0) mx = fmaxf(mx, e);
        s = f1r + fv.w; e = s > 0.f ? s : ALPHA_LR * s; if (a.w > 0) mx = fmaxf(mx, e);
    }
    #pragma unroll
    for (int off = 16; off; off >>= 1)
        mx = fmaxf(mx, __shfl_xor_sync(0xffffffffu, mx, off));
    if (lane == 0) m[row] = mx;
}

// ---------------------------------------------------------------------------
// Fused attention with precomputed row max. CTA: 32 rows x 128 feats.
// No online correction; l accumulates in warp registers. Packed f32x2 FMA.
// ---------------------------------------------------------------------------
__global__ __launch_bounds__(256, 2)
void attn_kernel(const float* __restrict__ Wh,
                 const int* __restrict__ adj,
                 const float* __restrict__ f1,
                 const float* __restrict__ f2,
                 const float* __restrict__ m,
                 float* __restrict__ out) {
    __shared__ __align__(16) float4 Wh_s[64 * 32];   // [j][c4]  32 KB
    __shared__ __align__(16) float  p_d[32][128];    // duplicated p  16 KB

    const int tid  = threadIdx.x;
    const int lane = tid & 31;
    const int warp = tid >> 5;
    const int row0 = blockIdx.x * 32;
    const int fb4  = blockIdx.y * 32;
    const float4* whg = reinterpret_cast<const float4*>(Wh);

    float f1r[4], mr[4];
    #pragma unroll
    for (int i = 0; i < 4; i++) {
        int r = row0 + warp * 4 + i;
        f1r[i] = f1[r];
        mr[i]  = m[r];
    }

    float ls[4] = {0.f, 0.f, 0.f, 0.f};
    unsigned long long acc[4][2] = {};

    // Prefetch tile 0
    float4 whv[8];
    int2   adjv[4];
    float2 f2v;
    #pragma unroll
    for (int k = 0; k < 8; k++) {
        int idx = k * 256 + tid;
        whv[k] = whg[(idx >> 5) * (FDIM / 4) + fb4 + (idx & 31)];
    }
    #pragma unroll
    for (int i = 0; i < 4; i++)
        adjv[i] = *reinterpret_cast<const int2*>(
            &adj[(row0 + warp * 4 + i) * NN + 2 * lane]);
    f2v = *reinterpret_cast<const float2*>(&f2[2 * lane]);

    for (int t = 0; t < NN / 64; t++) {
        __syncthreads();   // previous FMA phase done reading smem
        // Store Wh tile
        #pragma unroll
        for (int k = 0; k < 8; k++) Wh_s[k * 256 + tid] = whv[k];
        // Compute p (each warp owns its 4 rows); lane handles j = 2*lane, 2*lane+1
        #pragma unroll
        for (int i = 0; i < 4; i++) {
            float s0 = f1r[i] + f2v.x;
            float e0 = s0 > 0.f ? s0 : ALPHA_LR * s0;
            float sc0 = (adjv[i].x > 0) ? e0 : NEG_INF_V;
            float p0 = __expf(sc0 - mr[i]);
            float s1 = f1r[i] + f2v.y;
            float e1 = s1 > 0.f ? s1 : ALPHA_LR * s1;
            float sc1 = (adjv[i].y > 0) ? e1 : NEG_INF_V;
            float p1 = __expf(sc1 - mr[i]);
            ls[i] += p0 + p1;
            *reinterpret_cast<float4*>(&p_d[warp * 4 + i][lane * 4]) =
                make_float4(p0, p0, p1, p1);
        }
        // Prefetch next tile (wrap; last iteration's prefetch is discarded)
        int j0n = ((t + 1) & (NN / 64 - 1)) * 64;
        #pragma unroll
        for (int k = 0; k < 8; k++) {
            int idx = k * 256 + tid;
            whv[k] = whg[(j0n + (idx >> 5)) * (FDIM / 4) + fb4 + (idx & 31)];
        }
        #pragma unroll
        for (int i = 0; i < 4; i++)
            adjv[i] = *reinterpret_cast<const int2*>(
                &adj[(row0 + warp * 4 + i) * NN + j0n + 2 * lane]);
        f2v = *reinterpret_cast<const float2*>(&f2[j0n + 2 * lane]);
        __syncthreads();   // Wh_s / p_d ready

        // acc += P[32x64] @ Wh_s[64x128] with packed f32x2.
        // float4-index q of p_d holds (p_{2q},p_{2q},p_{2q+1},p_{2q+1});
        // j-group g (j=4g..4g+3) needs q=2g and q=2g+1.
        #pragma unroll
        for (int g = 0; g < 16; g++) {
            F4U wv0, wv1, wv2, wv3;
            wv0.f = Wh_s[(4 * g + 0) * 32 + lane];
            wv1.f = Wh_s[(4 * g + 1) * 32 + lane];
            wv2.f = Wh_s[(4 * g + 2) * 32 + lane];
            wv3.f = Wh_s[(4 * g + 3) * 32 + lane];
            #pragma unroll
            for (int i = 0; i < 4; i++) {
                const float4* rowp4 =
                    reinterpret_cast<const float4*>(&p_d[warp * 4 + i][0]);
                F4U pa, pb;
                pa.f = rowp4[2 * g + 0];   // (p_{4g},   p_{4g},   p_{4g+1}, p_{4g+1})
                pb.f = rowp4[2 * g + 1];   // (p_{4g+2}, p_{4g+2}, p_{4g+3}, p_{4g+3})
                fma2(acc[i][0], pa.u.x, wv0.u.x);
                fma2(acc[i][1], pa.u.x, wv0.u.y);
                fma2(acc[i][0], pa.u.y, wv1.u.x);
                fma2(acc[i][1], pa.u.y, wv1.u.y);
                fma2(acc[i][0], pb.u.x, wv2.u.x);
                fma2(acc[i][1], pb.u.x, wv2.u.y);
                fma2(acc[i][0], pb.u.y, wv3.u.x);
                fma2(acc[i][1], pb.u.y, wv3.u.y);
            }
        }
    }

    // Reduce l over warp lanes, normalize, ELU, store
    #pragma unroll
    for (int i = 0; i < 4; i++) {
        #pragma unroll
        for (int off = 16; off; off >>= 1)
            ls[i] += __shfl_xor_sync(0xffffffffu, ls[i], off);
    }
    #pragma unroll
    for (int i = 0; i < 4; i++) {
        float inv = 1.f / ls[i];
        F4U a0;
        a0.u.x = acc[i][0]; a0.u.y = acc[i][1];
        float4 v;
        v.x = a0.f.x * inv;
        v.y = a0.f.y * inv;
        v.z = a0.f.z * inv;
        v.w = a0.f.w * inv;
        v.x = v.x > 0.f ? v.x : (__expf(v.x) - 1.f);
        v.y = v.y > 0.f ? v.y : (__expf(v.y) - 1.f);
        v.z = v.z > 0.f ? v.z : (__expf(v.z) - 1.f);
        v.w = v.w > 0.f ? v.w : (__expf(v.w) - 1.f);
        reinterpret_cast<float4*>(out)[(row0 + warp * 4 + i) * (FDIM / 4) +
                                       fb4 + lane] = v;
    }
}

// ---------------------------------------------------------------------------
extern "C" void kernel_launch(void* const* d_in, const int* in_sizes, int n_in,
                              void* d_out, int out_size) {
    const float* input = (const float*)d_in[0];
    const int*   adj   = (const int*)  d_in[1];
    const float* W0    = (const float*)d_in[2];
    const float* Wl[3] = {(const float*)d_in[3], (const float*)d_in[5],
                          (const float*)d_in[7]};
    const float* al[3] = {(const float*)d_in[4], (const float*)d_in[6],
                          (const float*)d_in[8]};
    float* out = (float*)d_out;

    float *h, *Wh, *f1, *f2, *m;
    cudaGetSymbolAddress((void**)&h,  g_h);
    cudaGetSymbolAddress((void**)&Wh, g_Wh);
    cudaGetSymbolAddress((void**)&f1, g_f1);
    cudaGetSymbolAddress((void**)&f2, g_f2);
    cudaGetSymbolAddress((void**)&m,  g_m);

    dim3 gemmGrid(FDIM / 64, NN / 64);   // (4, 64)
    dim3 attnGrid(NN / 32, 2);           // (128, 2)

    gemm_kernel<<<gemmGrid, 256>>>(input, W0, h);

    for (int l = 0; l < 3; l++) {
        gemm_kernel<<<gemmGrid, 256>>>(h, Wl[l], Wh);
        fvec_kernel<<<NN / 8, 256>>>(Wh, al[l], f1, f2);
        rowmax_kernel<<<NN / 8, 256>>>(adj, f1, f2, m);
        float* dst = (l == 2) ? out : h;
        attn_kernel<<<attnGrid, 256>>>(Wh, adj, f1, f2, m, dst);
    }
}

// round 6
// speedup vs baseline: 2.5922x; 1.2337x over previous
#include <cuda_runtime.h>

#define NN 4096
#define FDIM 256
#define ALPHA_LR 0.01f
#define NEG_INF_V -9.0e15f

// Scratch (allocation-free rule: __device__ globals)
__device__ __align__(16) float g_h[NN * FDIM];
__device__ __align__(16) float g_Wh[NN * FDIM];
__device__ float g_f1[NN];
__device__ float g_f2[NN];
__device__ float g_m[NN];

union F4U { float4 f; ulonglong2 u; };

__device__ __forceinline__ void fma2(unsigned long long& d,
                                     unsigned long long a,
                                     unsigned long long b) {
    asm("fma.rn.f32x2 %0, %1, %2, %0;" : "+l"(d) : "l"(a), "l"(b));
}

__device__ __forceinline__ unsigned long long dup2(float b) {
    unsigned long long q;
    asm("mov.b64 %0, {%1, %1};" : "=l"(q) : "r"(__float_as_int(b)));
    return q;
}

// ---------------------------------------------------------------------------
// GEMM: C[4096,256] = A[4096,256] @ B[256,256]
// ---------------------------------------------------------------------------
__global__ void gemm_kernel(const float* __restrict__ A,
                            const float* __restrict__ B,
                            float* __restrict__ C) {
    __shared__ __align__(16) float As[16][64];
    __shared__ __align__(16) float Bs[16][64];
    const int tid = threadIdx.x;
    const int tx = tid & 15;
    const int ty = tid >> 4;
    const int blockRow = blockIdx.y * 64;
    const int blockCol = blockIdx.x * 64;

    float acc[4][4] = {};

    for (int kk = 0; kk < FDIM; kk += 16) {
        {
            int r  = tid >> 2;
            int kq = (tid & 3) * 4;
            float4 v = *reinterpret_cast<const float4*>(
                &A[(blockRow + r) * FDIM + kk + kq]);
            As[kq + 0][r] = v.x;
            As[kq + 1][r] = v.y;
            As[kq + 2][r] = v.z;
            As[kq + 3][r] = v.w;
        }
        {
            int k = tid >> 4;
            int c = (tid & 15) * 4;
            *reinterpret_cast<float4*>(&Bs[k][c]) =
                *reinterpret_cast<const float4*>(
                    &B[(kk + k) * FDIM + blockCol + c]);
        }
        __syncthreads();
        #pragma unroll
        for (int k = 0; k < 16; k++) {
            float4 av = *reinterpret_cast<float4*>(&As[k][ty * 4]);
            float4 bv = *reinterpret_cast<float4*>(&Bs[k][tx * 4]);
            float a4[4] = {av.x, av.y, av.z, av.w};
            float b4[4] = {bv.x, bv.y, bv.z, bv.w};
            #pragma unroll
            for (int i = 0; i < 4; i++)
                #pragma unroll
                for (int j = 0; j < 4; j++)
                    acc[i][j] += a4[i] * b4[j];
        }
        __syncthreads();
    }
    #pragma unroll
    for (int i = 0; i < 4; i++) {
        float4 v = make_float4(acc[i][0], acc[i][1], acc[i][2], acc[i][3]);
        *reinterpret_cast<float4*>(
            &C[(blockRow + ty * 4 + i) * FDIM + blockCol + tx * 4]) = v;
    }
}

// ---------------------------------------------------------------------------
// f1[i] = Wh[i,:] . a[0:256],  f2[i] = Wh[i,:] . a[256:512]
// ---------------------------------------------------------------------------
__global__ void fvec_kernel(const float* __restrict__ Wh,
                            const float* __restrict__ a,
                            float* __restrict__ f1,
                            float* __restrict__ f2) {
    const int warp = threadIdx.x >> 5;
    const int lane = threadIdx.x & 31;
    const int row  = blockIdx.x * 8 + warp;
    float s1 = 0.f, s2 = 0.f;
    #pragma unroll
    for (int k = lane; k < FDIM; k += 32) {
        float w = Wh[row * FDIM + k];
        s1 += w * a[k];
        s2 += w * a[FDIM + k];
    }
    #pragma unroll
    for (int off = 16; off; off >>= 1) {
        s1 += __shfl_xor_sync(0xffffffffu, s1, off);
        s2 += __shfl_xor_sync(0xffffffffu, s2, off);
    }
    if (lane == 0) { f1[row] = s1; f2[row] = s2; }
}

// ---------------------------------------------------------------------------
// Row max of masked leaky scores (exact): m[i] = max_j score(i,j).
// ---------------------------------------------------------------------------
__global__ void rowmax_kernel(const int* __restrict__ adj,
                              const float* __restrict__ f1,
                              const float* __restrict__ f2,
                              float* __restrict__ m) {
    const int warp = threadIdx.x >> 5;
    const int lane = threadIdx.x & 31;
    const int row  = blockIdx.x * 8 + warp;
    const float f1r = f1[row];
    float mx = NEG_INF_V;
    #pragma unroll 4
    for (int it = 0; it < NN / 128; it++) {
        int j = it * 128 + lane * 4;
        int4   a  = *reinterpret_cast<const int4*>(&adj[row * NN + j]);
        float4 fv = *reinterpret_cast<const float4*>(&f2[j]);
        float s, e;
        s = f1r + fv.x; e = s > 0.f ? s : ALPHA_LR * s; if (a.x > 0) mx = fmaxf(mx, e);
        s = f1r + fv.y; e = s > 0.f ? s : ALPHA_LR * s; if (a.y > 0) mx = fmaxf(mx, e);
        s = f1r + fv.z; e = s > 0.f ? s : ALPHA_LR * s; if (a.z > 0) mx = fmaxf(mx, e);
        s = f1r + fv.w; e = s > 0.f ? s : ALPHA_LR * s; if (a.w > 0) mx = fmaxf(mx, e);
    }
    #pragma unroll
    for (int off = 16; off; off >>= 1)
        mx = fmaxf(mx, __shfl_xor_sync(0xffffffffu, mx, off));
    if (lane == 0) m[row] = mx;
}

// ---------------------------------------------------------------------------
// Fused attention, precomputed row max. CTA: 8 warps, 64 rows x 128 feats.
// Warp owns 8 rows; p lives in registers, distributed via shfl (no smem p).
// Packed f32x2 FMA; Wh tile staged in smem with register prefetch.
// ---------------------------------------------------------------------------
__global__ __launch_bounds__(256, 1)
void attn_kernel(const float* __restrict__ Wh,
                 const int* __restrict__ adj,
                 const float* __restrict__ f1,
                 const float* __restrict__ f2,
                 const float* __restrict__ m,
                 float* __restrict__ out) {
    __shared__ __align__(16) float4 Wh_s[64 * 32];   // [j][c4]  32 KB

    const int tid  = threadIdx.x;
    const int lane = tid & 31;
    const int warp = tid >> 5;
    const int row0 = blockIdx.x * 64;                // CTA rows
    const int wrow = row0 + warp * 8;                // warp's first row
    const int fb4  = blockIdx.y * 32;                // float4 feature offset
    const float4* whg = reinterpret_cast<const float4*>(Wh);

    float f1r[8], mr[8];
    #pragma unroll
    for (int i = 0; i < 8; i++) {
        f1r[i] = f1[wrow + i];
        mr[i]  = m[wrow + i];
    }

    float ls[8] = {};
    unsigned long long acc[8][2] = {};

    // Prefetch tile 0
    float4 whv[8];
    int2   adjv[8];
    float2 f2v;
    #pragma unroll
    for (int k = 0; k < 8; k++) {
        int idx = k * 256 + tid;
        whv[k] = whg[(idx >> 5) * (FDIM / 4) + fb4 + (idx & 31)];
    }
    #pragma unroll
    for (int i = 0; i < 8; i++)
        adjv[i] = *reinterpret_cast<const int2*>(&adj[(wrow + i) * NN + 2 * lane]);
    f2v = *reinterpret_cast<const float2*>(&f2[2 * lane]);

    for (int t = 0; t < NN / 64; t++) {
        __syncthreads();   // previous FMA phase done reading Wh_s
        #pragma unroll
        for (int k = 0; k < 8; k++) Wh_s[k * 256 + tid] = whv[k];

        // p for this warp's 8 rows, lane's two j's: j = 2*lane, 2*lane+1
        float pA[8], pB[8];
        #pragma unroll
        for (int i = 0; i < 8; i++) {
            float s0 = f1r[i] + f2v.x;
            float e0 = s0 > 0.f ? s0 : ALPHA_LR * s0;
            float sc0 = (adjv[i].x > 0) ? e0 : NEG_INF_V;
            pA[i] = __expf(sc0 - mr[i]);
            float s1 = f1r[i] + f2v.y;
            float e1 = s1 > 0.f ? s1 : ALPHA_LR * s1;
            float sc1 = (adjv[i].y > 0) ? e1 : NEG_INF_V;
            pB[i] = __expf(sc1 - mr[i]);
            ls[i] += pA[i] + pB[i];
        }

        // Prefetch next tile (wrap; final prefetch discarded)
        int j0n = ((t + 1) & (NN / 64 - 1)) * 64;
        #pragma unroll
        for (int k = 0; k < 8; k++) {
            int idx = k * 256 + tid;
            whv[k] = whg[(j0n + (idx >> 5)) * (FDIM / 4) + fb4 + (idx & 31)];
        }
        #pragma unroll
        for (int i = 0; i < 8; i++)
            adjv[i] = *reinterpret_cast<const int2*>(
                &adj[(wrow + i) * NN + j0n + 2 * lane]);
        f2v = *reinterpret_cast<const float2*>(&f2[j0n + 2 * lane]);
        __syncthreads();   // Wh_s ready

        // acc += P[8x64] @ Wh_s[64x128]; p broadcast via shfl, packed fma2.
        #pragma unroll 4
        for (int g = 0; g < 16; g++) {
            F4U wv0, wv1, wv2, wv3;
            wv0.f = Wh_s[(4 * g + 0) * 32 + lane];
            wv1.f = Wh_s[(4 * g + 1) * 32 + lane];
            wv2.f = Wh_s[(4 * g + 2) * 32 + lane];
            wv3.f = Wh_s[(4 * g + 3) * 32 + lane];
            #pragma unroll
            for (int i = 0; i < 8; i++) {
                float b0 = __shfl_sync(0xffffffffu, pA[i], 2 * g);
                float b1 = __shfl_sync(0xffffffffu, pB[i], 2 * g);
                float b2 = __shfl_sync(0xffffffffu, pA[i], 2 * g + 1);
                float b3 = __shfl_sync(0xffffffffu, pB[i], 2 * g + 1);
                unsigned long long q0 = dup2(b0);
                unsigned long long q1 = dup2(b1);
                unsigned long long q2 = dup2(b2);
                unsigned long long q3 = dup2(b3);
                fma2(acc[i][0], q0, wv0.u.x);
                fma2(acc[i][1], q0, wv0.u.y);
                fma2(acc[i][0], q1, wv1.u.x);
                fma2(acc[i][1], q1, wv1.u.y);
                fma2(acc[i][0], q2, wv2.u.x);
                fma2(acc[i][1], q2, wv2.u.y);
                fma2(acc[i][0], q3, wv3.u.x);
                fma2(acc[i][1], q3, wv3.u.y);
            }
        }
    }

    // Reduce l over warp lanes, normalize, ELU, store
    #pragma unroll
    for (int i = 0; i < 8; i++) {
        #pragma unroll
        for (int off = 16; off; off >>= 1)
            ls[i] += __shfl_xor_sync(0xffffffffu, ls[i], off);
    }
    #pragma unroll
    for (int i = 0; i < 8; i++) {
        float inv = 1.f / ls[i];
        F4U a0;
        a0.u.x = acc[i][0]; a0.u.y = acc[i][1];
        float4 v;
        v.x = a0.f.x * inv;
        v.y = a0.f.y * inv;
        v.z = a0.f.z * inv;
        v.w = a0.f.w * inv;
        v.x = v.x > 0.f ? v.x : (__expf(v.x) - 1.f);
        v.y = v.y > 0.f ? v.y : (__expf(v.y) - 1.f);
        v.z = v.z > 0.f ? v.z : (__expf(v.z) - 1.f);
        v.w = v.w > 0.f ? v.w : (__expf(v.w) - 1.f);
        reinterpret_cast<float4*>(out)[(wrow + i) * (FDIM / 4) + fb4 + lane] = v;
    }
}

// ---------------------------------------------------------------------------
extern "C" void kernel_launch(void* const* d_in, const int* in_sizes, int n_in,
                              void* d_out, int out_size) {
    const float* input = (const float*)d_in[0];
    const int*   adj   = (const int*)  d_in[1];
    const float* W0    = (const float*)d_in[2];
    const float* Wl[3] = {(const float*)d_in[3], (const float*)d_in[5],
                          (const float*)d_in[7]};
    const float* al[3] = {(const float*)d_in[4], (const float*)d_in[6],
                          (const float*)d_in[8]};
    float* out = (float*)d_out;

    float *h, *Wh, *f1, *f2, *m;
    cudaGetSymbolAddress((void**)&h,  g_h);
    cudaGetSymbolAddress((void**)&Wh, g_Wh);
    cudaGetSymbolAddress((void**)&f1, g_f1);
    cudaGetSymbolAddress((void**)&f2, g_f2);
    cudaGetSymbolAddress((void**)&m,  g_m);

    dim3 gemmGrid(FDIM / 64, NN / 64);   // (4, 64)
    dim3 attnGrid(NN / 64, 2);           // (64, 2) = 128 CTAs

    gemm_kernel<<<gemmGrid, 256>>>(input, W0, h);

    for (int l = 0; l < 3; l++) {
        gemm_kernel<<<gemmGrid, 256>>>(h, Wl[l], Wh);
        fvec_kernel<<<NN / 8, 256>>>(Wh, al[l], f1, f2);
        rowmax_kernel<<<NN / 8, 256>>>(adj, f1, f2, m);
        float* dst = (l == 2) ? out : h;
        attn_kernel<<<attnGrid, 256>>>(Wh, adj, f1, f2, m, dst);
    }
}

// round 8
// speedup vs baseline: 2.7737x; 1.0700x over previous
#include <cuda_runtime.h>
#include <cstdint>

#define NN 4096
#define FDIM 256
#define ALPHA_LR 0.01f
#define NEG_INF_V -9.0e15f

// Scratch (allocation-free rule: __device__ globals)
__device__ __align__(16) float g_h[NN * FDIM];
__device__ __align__(16) float g_Wh[NN * FDIM];
__device__ float g_f1[NN];
__device__ float g_f2[NN];
__device__ float g_m[NN];

union F4U { float4 f; ulonglong2 u; };

__device__ __forceinline__ void fma2(unsigned long long& d,
                                     unsigned long long a,
                                     unsigned long long b) {
    asm("fma.rn.f32x2 %0, %1, %2, %0;" : "+l"(d) : "l"(a), "l"(b));
}

__device__ __forceinline__ unsigned long long dup2(float b) {
    unsigned long long q;
    asm("mov.b64 %0, {%1, %1};" : "=l"(q) : "r"(__float_as_int(b)));
    return q;
}

__device__ __forceinline__ uint32_t smem_u32(const void* p) {
    uint32_t a;
    asm("{ .reg .u64 t; cvta.to.shared.u64 t, %1; cvt.u32.u64 %0, t; }"
        : "=r"(a) : "l"(p));
    return a;
}

__device__ __forceinline__ void cp_async16(uint32_t s, const void* g) {
    asm volatile("cp.async.cg.shared.global [%0], [%1], 16;" :: "r"(s), "l"(g));
}
#define CP_COMMIT() asm volatile("cp.async.commit_group;" ::: "memory")
#define CP_WAIT1()  asm volatile("cp.async.wait_group 1;" ::: "memory")
#define CP_WAIT0()  asm volatile("cp.async.wait_group 0;" ::: "memory")

// ---------------------------------------------------------------------------
// GEMM: C[4096,256] = A[4096,256] @ B[256,256]  (packed fma2 micro-kernel)
// ---------------------------------------------------------------------------
__global__ void gemm_kernel(const float* __restrict__ A,
                            const float* __restrict__ B,
                            float* __restrict__ C) {
    __shared__ __align__(16) float As[16][64];
    __shared__ __align__(16) float Bs[16][64];
    const int tid = threadIdx.x;
    const int tx = tid & 15;
    const int ty = tid >> 4;
    const int blockRow = blockIdx.y * 64;
    const int blockCol = blockIdx.x * 64;

    unsigned long long acc2[4][2] = {};

    for (int kk = 0; kk < FDIM; kk += 16) {
        {
            int r  = tid >> 2;
            int kq = (tid & 3) * 4;
            float4 v = *reinterpret_cast<const float4*>(
                &A[(blockRow + r) * FDIM + kk + kq]);
            As[kq + 0][r] = v.x;
            As[kq + 1][r] = v.y;
            As[kq + 2][r] = v.z;
            As[kq + 3][r] = v.w;
        }
        {
            int k = tid >> 4;
            int c = (tid & 15) * 4;
            *reinterpret_cast<float4*>(&Bs[k][c]) =
                *reinterpret_cast<const float4*>(
                    &B[(kk + k) * FDIM + blockCol + c]);
        }
        __syncthreads();
        #pragma unroll
        for (int k = 0; k < 16; k++) {
            F4U av, bv;
            av.f = *reinterpret_cast<float4*>(&As[k][ty * 4]);
            bv.f = *reinterpret_cast<float4*>(&Bs[k][tx * 4]);
            unsigned long long a0 = dup2(av.f.x);
            unsigned long long a1 = dup2(av.f.y);
            unsigned long long a2 = dup2(av.f.z);
            unsigned long long a3 = dup2(av.f.w);
            fma2(acc2[0][0], a0, bv.u.x); fma2(acc2[0][1], a0, bv.u.y);
            fma2(acc2[1][0], a1, bv.u.x); fma2(acc2[1][1], a1, bv.u.y);
            fma2(acc2[2][0], a2, bv.u.x); fma2(acc2[2][1], a2, bv.u.y);
            fma2(acc2[3][0], a3, bv.u.x); fma2(acc2[3][1], a3, bv.u.y);
        }
        __syncthreads();
    }
    #pragma unroll
    for (int i = 0; i < 4; i++) {
        F4U v;
        v.u.x = acc2[i][0];
        v.u.y = acc2[i][1];
        *reinterpret_cast<float4*>(
            &C[(blockRow + ty * 4 + i) * FDIM + blockCol + tx * 4]) = v.f;
    }
}

// ---------------------------------------------------------------------------
// f1[i] = Wh[i,:] . a[0:256],  f2[i] = Wh[i,:] . a[256:512]
// ---------------------------------------------------------------------------
__global__ void fvec_kernel(const float* __restrict__ Wh,
                            const float* __restrict__ a,
                            float* __restrict__ f1,
                            float* __restrict__ f2) {
    const int warp = threadIdx.x >> 5;
    const int lane = threadIdx.x & 31;
    const int row  = blockIdx.x * 8 + warp;
    float s1 = 0.f, s2 = 0.f;
    #pragma unroll
    for (int k = lane; k < FDIM; k += 32) {
        float w = Wh[row * FDIM + k];
        s1 += w * a[k];
        s2 += w * a[FDIM + k];
    }
    #pragma unroll
    for (int off = 16; off; off >>= 1) {
        s1 += __shfl_xor_sync(0xffffffffu, s1, off);
        s2 += __shfl_xor_sync(0xffffffffu, s2, off);
    }
    if (lane == 0) { f1[row] = s1; f2[row] = s2; }
}

// ---------------------------------------------------------------------------
// Exact row max of masked leaky scores.
// ---------------------------------------------------------------------------
__global__ void rowmax_kernel(const int* __restrict__ adj,
                              const float* __restrict__ f1,
                              const float* __restrict__ f2,
                              float* __restrict__ m) {
    const int warp = threadIdx.x >> 5;
    const int lane = threadIdx.x & 31;
    const int row  = blockIdx.x * 8 + warp;
    const float f1r = f1[row];
    float mx = NEG_INF_V;
    #pragma unroll 4
    for (int it = 0; it < NN / 128; it++) {
        int j = it * 128 + lane * 4;
        int4   a  = *reinterpret_cast<const int4*>(&adj[(size_t)row * NN + j]);
        float4 fv = *reinterpret_cast<const float4*>(&f2[j]);
        float s, e;
        s = f1r + fv.x; e = s > 0.f ? s : ALPHA_LR * s; if (a.x > 0) mx = fmaxf(mx, e);
        s = f1r + fv.y; e = s > 0.f ? s : ALPHA_LR * s; if (a.y > 0) mx = fmaxf(mx, e);
        s = f1r + fv.z; e = s > 0.f ? s : ALPHA_LR * s; if (a.z > 0) mx = fmaxf(mx, e);
        s = f1r + fv.w; e = s > 0.f ? s : ALPHA_LR * s; if (a.w > 0) mx = fmaxf(mx, e);
    }
    #pragma unroll
    for (int off = 16; off; off >>= 1)
        mx = fmaxf(mx, __shfl_xor_sync(0xffffffffu, mx, off));
    if (lane == 0) m[row] = mx;
}

// ---------------------------------------------------------------------------
// Fused attention, precomputed row max. CTA: 8 warps, 32 rows x 256 feats.
// Warp owns 4 rows; p in registers, broadcast via shfl; packed f32x2 FMA.
// Wh tile (64 j x 256 f, 64KB) double-buffered via cp.async.
// Lane f-slots: feats [4*lane .. 4*lane+3] and [128+4*lane .. 128+4*lane+3].
// ---------------------------------------------------------------------------
__global__ __launch_bounds__(256, 1)
void attn_kernel(const float* __restrict__ Wh,
                 const int* __restrict__ adj,
                 const float* __restrict__ f1,
                 const float* __restrict__ f2,
                 const float* __restrict__ m,
                 float* __restrict__ out) {
    extern __shared__ __align__(16) float4 whs[];    // [2][64 j][64 float4]

    const int tid  = threadIdx.x;
    const int lane = tid & 31;
    const int warp = tid >> 5;
    const int row0 = blockIdx.x * 32;
    const int wrow = row0 + warp * 4;
    const float4* whg = reinterpret_cast<const float4*>(Wh);
    const uint32_t sbase = smem_u32(whs);

    float f1r[4], mr[4];
    #pragma unroll
    for (int i = 0; i < 4; i++) {
        f1r[i] = f1[wrow + i];
        mr[i]  = m[wrow + i];
    }

    float ls[4] = {};
    unsigned long long acc[4][4] = {};

    // Stage tile 0 (4096 float4s, contiguous: chunk c -> j=c>>6, f4=c&63)
    {
        const float4* src = whg;                     // j0 = 0
        #pragma unroll
        for (int k = 0; k < 16; k++) {
            int c = k * 256 + tid;
            cp_async16(sbase + c * 16, src + c);
        }
        CP_COMMIT();
    }
    // Register prefetch tile 0 (adj, f2)
    int2   adjv[4];
    float2 f2v;
    #pragma unroll
    for (int i = 0; i < 4; i++)
        adjv[i] = *reinterpret_cast<const int2*>(
            &adj[(size_t)(wrow + i) * NN + 2 * lane]);
    f2v = *reinterpret_cast<const float2*>(&f2[2 * lane]);

    for (int t = 0; t < 64; t++) {
        // Issue cp.async for tile t+1 into buf (t+1)&1.
        // (Safe: last readers of that buf finished at FMA(t-1), separated by
        //  the end-of-iteration __syncthreads.)
        if (t < 63) {
            const float4* src = whg + (size_t)(t + 1) * 64 * 64;
            uint32_t dst = sbase + ((t + 1) & 1) * 65536u;
            #pragma unroll
            for (int k = 0; k < 16; k++) {
                int c = k * 256 + tid;
                cp_async16(dst + c * 16, src + c);
            }
            CP_COMMIT();
        }
        if (t < 63) CP_WAIT1(); else CP_WAIT0();     // tile t landed
        __syncthreads();

        // p for warp's 4 rows, lane's two j's (j = 2*lane, 2*lane+1 of tile)
        float pA[4], pB[4];
        #pragma unroll
        for (int i = 0; i < 4; i++) {
            float s0 = f1r[i] + f2v.x;
            float e0 = s0 > 0.f ? s0 : ALPHA_LR * s0;
            float sc0 = (adjv[i].x > 0) ? e0 : NEG_INF_V;
            pA[i] = __expf(sc0 - mr[i]);
            float s1 = f1r[i] + f2v.y;
            float e1 = s1 > 0.f ? s1 : ALPHA_LR * s1;
            float sc1 = (adjv[i].y > 0) ? e1 : NEG_INF_V;
            pB[i] = __expf(sc1 - mr[i]);
            ls[i] += pA[i] + pB[i];
        }
        // Register prefetch for tile t+1 (wrap; final discarded)
        int j0n = ((t + 1) & 63) * 64;
        #pragma unroll
        for (int i = 0; i < 4; i++)
            adjv[i] = *reinterpret_cast<const int2*>(
                &adj[(size_t)(wrow + i) * NN + j0n + 2 * lane]);
        f2v = *reinterpret_cast<const float2*>(&f2[j0n + 2 * lane]);

        // acc += P[4x64] @ Wh_s[64x256]
        const float4* wb = whs + (t & 1) * 4096;
        #pragma unroll 2
        for (int g = 0; g < 16; g++) {
            F4U w0a, w0b, w1a, w1b, w2a, w2b, w3a, w3b;
            w0a.f = wb[(4 * g + 0) * 64 + lane];
            w0b.f = wb[(4 * g + 0) * 64 + 32 + lane];
            w1a.f = wb[(4 * g + 1) * 64 + lane];
            w1b.f = wb[(4 * g + 1) * 64 + 32 + lane];
            w2a.f = wb[(4 * g + 2) * 64 + lane];
            w2b.f = wb[(4 * g + 2) * 64 + 32 + lane];
            w3a.f = wb[(4 * g + 3) * 64 + lane];
            w3b.f = wb[(4 * g + 3) * 64 + 32 + lane];
            #pragma unroll
            for (int i = 0; i < 4; i++) {
                float b0 = __shfl_sync(0xffffffffu, pA[i], 2 * g);
                float b1 = __shfl_sync(0xffffffffu, pB[i], 2 * g);
                float b2 = __shfl_sync(0xffffffffu, pA[i], 2 * g + 1);
                float b3 = __shfl_sync(0xffffffffu, pB[i], 2 * g + 1);
                unsigned long long q0 = dup2(b0);
                unsigned long long q1 = dup2(b1);
                unsigned long long q2 = dup2(b2);
                unsigned long long q3 = dup2(b3);
                fma2(acc[i][0], q0, w0a.u.x);
                fma2(acc[i][1], q0, w0a.u.y);
                fma2(acc[i][2], q0, w0b.u.x);
                fma2(acc[i][3], q0, w0b.u.y);
                fma2(acc[i][0], q1, w1a.u.x);
                fma2(acc[i][1], q1, w1a.u.y);
                fma2(acc[i][2], q1, w1b.u.x);
                fma2(acc[i][3], q1, w1b.u.y);
                fma2(acc[i][0], q2, w2a.u.x);
                fma2(acc[i][1], q2, w2a.u.y);
                fma2(acc[i][2], q2, w2b.u.x);
                fma2(acc[i][3], q2, w2b.u.y);
                fma2(acc[i][0], q3, w3a.u.x);
                fma2(acc[i][1], q3, w3a.u.y);
                fma2(acc[i][2], q3, w3b.u.x);
                fma2(acc[i][3], q3, w3b.u.y);
            }
        }
        __syncthreads();   // all lanes done reading buf t&1
    }

    // Reduce l over lanes; normalize, ELU, store (two float4 slots per row)
    #pragma unroll
    for (int i = 0; i < 4; i++) {
        #pragma unroll
        for (int off = 16; off; off >>= 1)
            ls[i] += __shfl_xor_sync(0xffffffffu, ls[i], off);
    }
    #pragma unroll
    for (int i = 0; i < 4; i++) {
        float inv = 1.f / ls[i];
        F4U a0, a1;
        a0.u.x = acc[i][0]; a0.u.y = acc[i][1];
        a1.u.x = acc[i][2]; a1.u.y = acc[i][3];
        float4 v0, v1;
        v0.x = a0.f.x * inv; v0.y = a0.f.y * inv;
        v0.z = a0.f.z * inv; v0.w = a0.f.w * inv;
        v1.x = a1.f.x * inv; v1.y = a1.f.y * inv;
        v1.z = a1.f.z * inv; v1.w = a1.f.w * inv;
        v0.x = v0.x > 0.f ? v0.x : (__expf(v0.x) - 1.f);
        v0.y = v0.y > 0.f ? v0.y : (__expf(v0.y) - 1.f);
        v0.z = v0.z > 0.f ? v0.z : (__expf(v0.z) - 1.f);
        v0.w = v0.w > 0.f ? v0.w : (__expf(v0.w) - 1.f);
        v1.x = v1.x > 0.f ? v1.x : (__expf(v1.x) - 1.f);
        v1.y = v1.y > 0.f ? v1.y : (__expf(v1.y) - 1.f);
        v1.z = v1.z > 0.f ? v1.z : (__expf(v1.z) - 1.f);
        v1.w = v1.w > 0.f ? v1.w : (__expf(v1.w) - 1.f);
        float4* orow = reinterpret_cast<float4*>(out) + (size_t)(wrow + i) * 64;
        orow[lane]      = v0;
        orow[32 + lane] = v1;
    }
}

// ---------------------------------------------------------------------------
extern "C" void kernel_launch(void* const* d_in, const int* in_sizes, int n_in,
                              void* d_out, int out_size) {
    const float* input = (const float*)d_in[0];
    const int*   adj   = (const int*)  d_in[1];
    const float* W0    = (const float*)d_in[2];
    const float* Wl[3] = {(const float*)d_in[3], (const float*)d_in[5],
                          (const float*)d_in[7]};
    const float* al[3] = {(const float*)d_in[4], (const float*)d_in[6],
                          (const float*)d_in[8]};
    float* out = (float*)d_out;

    float *h, *Wh, *f1, *f2, *m;
    cudaGetSymbolAddress((void**)&h,  g_h);
    cudaGetSymbolAddress((void**)&Wh, g_Wh);
    cudaGetSymbolAddress((void**)&f1, g_f1);
    cudaGetSymbolAddress((void**)&f2, g_f2);
    cudaGetSymbolAddress((void**)&m,  g_m);

    const int ATTN_SMEM = 2 * 65536;                 // double-buffered Wh tile
    static bool attr_set = false;
    if (!attr_set) {
        cudaFuncSetAttribute(attn_kernel,
                             cudaFuncAttributeMaxDynamicSharedMemorySize,
                             ATTN_SMEM);
        attr_set = true;
    }

    dim3 gemmGrid(FDIM / 64, NN / 64);   // (4, 64)
    dim3 attnGrid(NN / 32);              // 128 CTAs, one wave

    gemm_kernel<<<gemmGrid, 256>>>(input, W0, h);

    for (int l = 0; l < 3; l++) {
        gemm_kernel<<<gemmGrid, 256>>>(h, Wl[l], Wh);
        fvec_kernel<<<NN / 8, 256>>>(Wh, al[l], f1, f2);
        rowmax_kernel<<<NN / 8, 256>>>(adj, f1, f2, m);
        float* dst = (l == 2) ? out : h;
        attn_kernel<<<attnGrid, 256, ATTN_SMEM>>>(Wh, adj, f1, f2, m, dst);
    }
}

// round 9
// speedup vs baseline: 2.9496x; 1.0634x over previous
#include <cuda_runtime.h>
#include <cstdint>

#define NN 4096
#define FDIM 256
#define ALPHA_LR 0.01f
#define NEG_INF_V -9.0e15f

// Scratch (allocation-free rule: __device__ globals)
__device__ __align__(16) float g_h[NN * FDIM];
__device__ __align__(16) float g_Wh[NN * FDIM];
__device__ float g_f1[NN];
__device__ float g_f2[NN];
__device__ float g_m[NN];

union F4U { float4 f; ulonglong2 u; };
union F2U { float2 f; unsigned long long u; };

__device__ __forceinline__ void fma2(unsigned long long& d,
                                     unsigned long long a,
                                     unsigned long long b) {
    asm("fma.rn.f32x2 %0, %1, %2, %0;" : "+l"(d) : "l"(a), "l"(b));
}

__device__ __forceinline__ unsigned long long dup2(float b) {
    unsigned long long q;
    asm("mov.b64 %0, {%1, %1};" : "=l"(q) : "r"(__float_as_int(b)));
    return q;
}

__device__ __forceinline__ uint32_t smem_u32(const void* p) {
    uint32_t a;
    asm("{ .reg .u64 t; cvta.to.shared.u64 t, %1; cvt.u32.u64 %0, t; }"
        : "=r"(a) : "l"(p));
    return a;
}

__device__ __forceinline__ void cp_async16(uint32_t s, const void* g) {
    asm volatile("cp.async.cg.shared.global [%0], [%1], 16;" :: "r"(s), "l"(g));
}
#define CP_COMMIT() asm volatile("cp.async.commit_group;" ::: "memory")
#define CP_WAIT1()  asm volatile("cp.async.wait_group 1;" ::: "memory")
#define CP_WAIT0()  asm volatile("cp.async.wait_group 0;" ::: "memory")

// ---------------------------------------------------------------------------
// GEMM: C[4096,256] = A[4096,256] @ B[256,256]  (packed fma2 micro-kernel)
// ---------------------------------------------------------------------------
__global__ void gemm_kernel(const float* __restrict__ A,
                            const float* __restrict__ B,
                            float* __restrict__ C) {
    __shared__ __align__(16) float As[16][64];
    __shared__ __align__(16) float Bs[16][64];
    const int tid = threadIdx.x;
    const int tx = tid & 15;
    const int ty = tid >> 4;
    const int blockRow = blockIdx.y * 64;
    const int blockCol = blockIdx.x * 64;

    unsigned long long acc2[4][2] = {};

    for (int kk = 0; kk < FDIM; kk += 16) {
        {
            int r  = tid >> 2;
            int kq = (tid & 3) * 4;
            float4 v = *reinterpret_cast<const float4*>(
                &A[(blockRow + r) * FDIM + kk + kq]);
            As[kq + 0][r] = v.x;
            As[kq + 1][r] = v.y;
            As[kq + 2][r] = v.z;
            As[kq + 3][r] = v.w;
        }
        {
            int k = tid >> 4;
            int c = (tid & 15) * 4;
            *reinterpret_cast<float4*>(&Bs[k][c]) =
                *reinterpret_cast<const float4*>(
                    &B[(kk + k) * FDIM + blockCol + c]);
        }
        __syncthreads();
        #pragma unroll
        for (int k = 0; k < 16; k++) {
            F4U av, bv;
            av.f = *reinterpret_cast<float4*>(&As[k][ty * 4]);
            bv.f = *reinterpret_cast<float4*>(&Bs[k][tx * 4]);
            unsigned long long a0 = dup2(av.f.x);
            unsigned long long a1 = dup2(av.f.y);
            unsigned long long a2 = dup2(av.f.z);
            unsigned long long a3 = dup2(av.f.w);
            fma2(acc2[0][0], a0, bv.u.x); fma2(acc2[0][1], a0, bv.u.y);
            fma2(acc2[1][0], a1, bv.u.x); fma2(acc2[1][1], a1, bv.u.y);
            fma2(acc2[2][0], a2, bv.u.x); fma2(acc2[2][1], a2, bv.u.y);
            fma2(acc2[3][0], a3, bv.u.x); fma2(acc2[3][1], a3, bv.u.y);
        }
        __syncthreads();
    }
    #pragma unroll
    for (int i = 0; i < 4; i++) {
        F4U v;
        v.u.x = acc2[i][0];
        v.u.y = acc2[i][1];
        *reinterpret_cast<float4*>(
            &C[(blockRow + ty * 4 + i) * FDIM + blockCol + tx * 4]) = v.f;
    }
}

// ---------------------------------------------------------------------------
// f1[i] = Wh[i,:] . a[0:256],  f2[i] = Wh[i,:] . a[256:512]
// ---------------------------------------------------------------------------
__global__ void fvec_kernel(const float* __restrict__ Wh,
                            const float* __restrict__ a,
                            float* __restrict__ f1,
                            float* __restrict__ f2) {
    const int warp = threadIdx.x >> 5;
    const int lane = threadIdx.x & 31;
    const int row  = blockIdx.x * 8 + warp;
    float s1 = 0.f, s2 = 0.f;
    #pragma unroll
    for (int k = lane; k < FDIM; k += 32) {
        float w = Wh[row * FDIM + k];
        s1 += w * a[k];
        s2 += w * a[FDIM + k];
    }
    #pragma unroll
    for (int off = 16; off; off >>= 1) {
        s1 += __shfl_xor_sync(0xffffffffu, s1, off);
        s2 += __shfl_xor_sync(0xffffffffu, s2, off);
    }
    if (lane == 0) { f1[row] = s1; f2[row] = s2; }
}

// ---------------------------------------------------------------------------
// Exact row max of masked leaky scores.
// ---------------------------------------------------------------------------
__global__ void rowmax_kernel(const int* __restrict__ adj,
                              const float* __restrict__ f1,
                              const float* __restrict__ f2,
                              float* __restrict__ m) {
    const int warp = threadIdx.x >> 5;
    const int lane = threadIdx.x & 31;
    const int row  = blockIdx.x * 8 + warp;
    const float f1r = f1[row];
    float mx = NEG_INF_V;
    #pragma unroll 4
    for (int it = 0; it < NN / 128; it++) {
        int j = it * 128 + lane * 4;
        int4   a  = *reinterpret_cast<const int4*>(&adj[(size_t)row * NN + j]);
        float4 fv = *reinterpret_cast<const float4*>(&f2[j]);
        float s, e;
        s = f1r + fv.x; e = s > 0.f ? s : ALPHA_LR * s; if (a.x > 0) mx = fmaxf(mx, e);
        s = f1r + fv.y; e = s > 0.f ? s : ALPHA_LR * s; if (a.y > 0) mx = fmaxf(mx, e);
        s = f1r + fv.z; e = s > 0.f ? s : ALPHA_LR * s; if (a.z > 0) mx = fmaxf(mx, e);
        s = f1r + fv.w; e = s > 0.f ? s : ALPHA_LR * s; if (a.w > 0) mx = fmaxf(mx, e);
    }
    #pragma unroll
    for (int off = 16; off; off >>= 1)
        mx = fmaxf(mx, __shfl_xor_sync(0xffffffffu, mx, off));
    if (lane == 0) m[row] = mx;
}

// ---------------------------------------------------------------------------
// Fused attention, precomputed row max. CTA: 8 warps, 32 rows x 256 feats.
// j-SPLIT across warps: warp (rowg = w&1, jg = w>>1) owns 16 rows x 16 j per
// 64-j tile, accumulating partial sums (no redundant cross-warp Wh reads).
// p stored duplicated (p,p) in smem, read via LDS.64 broadcast — no shuffles.
// Wh tile (64 j x 256 f, 64KB) double-buffered via cp.async.
// Epilogue: 4-round partial reduction in smem, then normalize + ELU + store.
// ---------------------------------------------------------------------------
__global__ __launch_bounds__(256)
void attn_kernel(const float* __restrict__ Wh,
                 const int* __restrict__ adj,
                 const float* __restrict__ f1,
                 const float* __restrict__ f2,
                 const float* __restrict__ m,
                 float* __restrict__ out) {
    extern __shared__ __align__(16) float4 whs[];    // [2][64 j][64 f4] 128KB
    __shared__ __align__(16) float p_s[32][128];     // duplicated p, 16KB
    __shared__ float l_s[32];

    const int tid  = threadIdx.x;
    const int lane = tid & 31;
    const int warp = tid >> 5;
    const int rowg = warp & 1;                       // row half (16 rows)
    const int jg   = warp >> 1;                      // j quarter (16 j)
    const int row0 = blockIdx.x * 32;
    const float4* whg = reinterpret_cast<const float4*>(Wh);
    const uint32_t sbase = smem_u32(whs);

    // p-production assignment: thread owns row prow, j's [jb, jb+8) of tile
    const int prow = tid >> 3;                       // 0..31
    const int jb   = (tid & 7) * 8;
    const int growp = row0 + prow;
    const float f1r = f1[growp];
    const float mr  = m[growp];
    float ls = 0.f;

    unsigned long long acc[16][4] = {};              // 16 rows x 8 feats (f32x2)

    // Prologue: stage tile 0 (4096 float4, 16 chunks/thread)
    #pragma unroll
    for (int k = 0; k < 16; k++) {
        int c = k * 256 + tid;
        cp_async16(sbase + c * 16, whg + c);
    }
    CP_COMMIT();
    // Register prefetch tile 0 (adj, f2 for this thread's p slice)
    int4   a0 = *reinterpret_cast<const int4*>(&adj[(size_t)growp * NN + jb]);
    int4   a1 = *reinterpret_cast<const int4*>(&adj[(size_t)growp * NN + jb + 4]);
    float4 fv0 = *reinterpret_cast<const float4*>(&f2[jb]);
    float4 fv1 = *reinterpret_cast<const float4*>(&f2[jb + 4]);

    for (int t = 0; t < 64; t++) {
        // Issue cp.async for tile t+1 into buf (t+1)&1 (WAR-safe: end-of-iter
        // sync of t-1 ordered all reads of that buffer before this point).
        if (t < 63) {
            const float4* src = whg + (size_t)(t + 1) * 4096;
            uint32_t dst = sbase + ((t + 1) & 1) * 65536u;
            #pragma unroll
            for (int k = 0; k < 16; k++) {
                int c = k * 256 + tid;
                cp_async16(dst + c * 16, src + c);
            }
            CP_COMMIT();
        }

        // Compute this thread's 8 p values, store duplicated pairs.
        {
            float pv[8];
            const int av[8] = {a0.x, a0.y, a0.z, a0.w, a1.x, a1.y, a1.z, a1.w};
            const float fv[8] = {fv0.x, fv0.y, fv0.z, fv0.w,
                                 fv1.x, fv1.y, fv1.z, fv1.w};
            #pragma unroll
            for (int q = 0; q < 8; q++) {
                float s = f1r + fv[q];
                float e = s > 0.f ? s : ALPHA_LR * s;
                float sc = (av[q] > 0) ? e : NEG_INF_V;
                pv[q] = __expf(sc - mr);
                ls += pv[q];
            }
            float* dst = &p_s[prow][16 * (tid & 7)];
            #pragma unroll
            for (int q = 0; q < 4; q++) {
                *reinterpret_cast<float4*>(dst + 4 * q) =
                    make_float4(pv[2 * q], pv[2 * q], pv[2 * q + 1], pv[2 * q + 1]);
            }
        }
        // Register prefetch for tile t+1 (wrap; final discarded)
        {
            int j0n = ((t + 1) & 63) * 64;
            a0 = *reinterpret_cast<const int4*>(&adj[(size_t)growp * NN + j0n + jb]);
            a1 = *reinterpret_cast<const int4*>(&adj[(size_t)growp * NN + j0n + jb + 4]);
            fv0 = *reinterpret_cast<const float4*>(&f2[j0n + jb]);
            fv1 = *reinterpret_cast<const float4*>(&f2[j0n + jb + 4]);
        }
        if (t < 63) CP_WAIT1(); else CP_WAIT0();     // tile t landed
        __syncthreads();                             // Wh_s + p_s ready

        // Partial acc += P[16 rows x 16 j] @ Wh_s[16 j x 256 f]
        const float4* wb = whs + (t & 1) * 4096;
        const float2* p2 = reinterpret_cast<const float2*>(p_s);
        #pragma unroll
        for (int jj = 0; jj < 16; jj++) {
            const int j = jg * 16 + jj;
            F4U w0, w1;
            w0.f = wb[j * 64 + lane];
            w1.f = wb[j * 64 + 32 + lane];
            #pragma unroll
            for (int i = 0; i < 16; i++) {
                F2U q;
                q.f = p2[(rowg * 16 + i) * 64 + j];  // LDS.64 broadcast
                fma2(acc[i][0], q.u, w0.u.x);
                fma2(acc[i][1], q.u, w0.u.y);
                fma2(acc[i][2], q.u, w1.u.x);
                fma2(acc[i][3], q.u, w1.u.y);
            }
        }
        __syncthreads();                             // done reading p_s / Wh bufs
    }

    // l: reduce over the 8 threads sharing a p-row (lanes grouped by tid&7)
    ls += __shfl_xor_sync(0xffffffffu, ls, 1);
    ls += __shfl_xor_sync(0xffffffffu, ls, 2);
    ls += __shfl_xor_sync(0xffffffffu, ls, 4);
    if ((tid & 7) == 0) l_s[prow] = ls;
    __syncthreads();

    // Reduce the 4 j-group partials into whs buffer 0 (reused as scratch)
    float4* red = reinterpret_cast<float4*>(whs);    // [32 rows][64 f4] 32KB
    #pragma unroll
    for (int round = 0; round < 4; round++) {
        if (jg == round) {
            #pragma unroll
            for (int i = 0; i < 16; i++) {
                int r = rowg * 16 + i;
                F4U v0, v1;
                v0.u.x = acc[i][0]; v0.u.y = acc[i][1];
                v1.u.x = acc[i][2]; v1.u.y = acc[i][3];
                if (round == 0) {
                    red[r * 64 + lane]      = v0.f;
                    red[r * 64 + 32 + lane] = v1.f;
                } else {
                    float4 o0 = red[r * 64 + lane];
                    float4 o1 = red[r * 64 + 32 + lane];
                    o0.x += v0.f.x; o0.y += v0.f.y; o0.z += v0.f.z; o0.w += v0.f.w;
                    o1.x += v1.f.x; o1.y += v1.f.y; o1.z += v1.f.z; o1.w += v1.f.w;
                    red[r * 64 + lane]      = o0;
                    red[r * 64 + 32 + lane] = o1;
                }
            }
        }
        __syncthreads();
    }

    // Normalize, ELU, store (2048 float4 / 256 threads = 8 each)
    #pragma unroll
    for (int k = 0; k < 8; k++) {
        int c = k * 256 + tid;
        int r = c >> 6;
        float inv = 1.f / l_s[r];
        float4 v = red[c];
        v.x *= inv; v.y *= inv; v.z *= inv; v.w *= inv;
        v.x = v.x > 0.f ? v.x : (__expf(v.x) - 1.f);
        v.y = v.y > 0.f ? v.y : (__expf(v.y) - 1.f);
        v.z = v.z > 0.f ? v.z : (__expf(v.z) - 1.f);
        v.w = v.w > 0.f ? v.w : (__expf(v.w) - 1.f);
        reinterpret_cast<float4*>(out)[(size_t)(row0 + r) * 64 + (c & 63)] = v;
    }
}

// ---------------------------------------------------------------------------
extern "C" void kernel_launch(void* const* d_in, const int* in_sizes, int n_in,
                              void* d_out, int out_size) {
    const float* input = (const float*)d_in[0];
    const int*   adj   = (const int*)  d_in[1];
    const float* W0    = (const float*)d_in[2];
    const float* Wl[3] = {(const float*)d_in[3], (const float*)d_in[5],
                          (const float*)d_in[7]};
    const float* al[3] = {(const float*)d_in[4], (const float*)d_in[6],
                          (const float*)d_in[8]};
    float* out = (float*)d_out;

    float *h, *Wh, *f1, *f2, *m;
    cudaGetSymbolAddress((void**)&h,  g_h);
    cudaGetSymbolAddress((void**)&Wh, g_Wh);
    cudaGetSymbolAddress((void**)&f1, g_f1);
    cudaGetSymbolAddress((void**)&f2, g_f2);
    cudaGetSymbolAddress((void**)&m,  g_m);

    const int ATTN_SMEM = 2 * 65536;                 // double-buffered Wh tile
    static bool attr_set = false;
    if (!attr_set) {
        cudaFuncSetAttribute(attn_kernel,
                             cudaFuncAttributeMaxDynamicSharedMemorySize,
                             ATTN_SMEM);
        attr_set = true;
    }

    dim3 gemmGrid(FDIM / 64, NN / 64);   // (4, 64)
    dim3 attnGrid(NN / 32);              // 128 CTAs, one wave

    gemm_kernel<<<gemmGrid, 256>>>(input, W0, h);

    for (int l = 0; l < 3; l++) {
        gemm_kernel<<<gemmGrid, 256>>>(h, Wl[l], Wh);
        fvec_kernel<<<NN / 8, 256>>>(Wh, al[l], f1, f2);
        rowmax_kernel<<<NN / 8, 256>>>(adj, f1, f2, m);
        float* dst = (l == 2) ? out : h;
        attn_kernel<<<attnGrid, 256, ATTN_SMEM>>>(Wh, adj, f1, f2, m, dst);
    }
}

// round 10
// speedup vs baseline: 2.9539x; 1.0015x over previous
#include <cuda_runtime.h>
#include <cstdint>

#define NN 4096
#define FDIM 256
#define ALPHA_LR 0.01f
#define NEG_INF_V -9.0e15f

// Scratch (allocation-free rule: __device__ globals)
__device__ __align__(16) float g_h[NN * FDIM];
__device__ __align__(16) float g_Wh[NN * FDIM];
__device__ float g_f1[NN];
__device__ float g_f2[NN];
__device__ float g_m[NN];
__device__ __align__(16) uint32_t g_mask[NN * NN / 32];   // 2MB bitmask

union F4U { float4 f; ulonglong2 u; };
union F2U { float2 f; unsigned long long u; };

__device__ __forceinline__ void fma2(unsigned long long& d,
                                     unsigned long long a,
                                     unsigned long long b) {
    asm("fma.rn.f32x2 %0, %1, %2, %0;" : "+l"(d) : "l"(a), "l"(b));
}

__device__ __forceinline__ unsigned long long dup2(float b) {
    unsigned long long q;
    asm("mov.b64 %0, {%1, %1};" : "=l"(q) : "r"(__float_as_int(b)));
    return q;
}

__device__ __forceinline__ uint32_t smem_u32(const void* p) {
    uint32_t a;
    asm("{ .reg .u64 t; cvta.to.shared.u64 t, %1; cvt.u32.u64 %0, t; }"
        : "=r"(a) : "l"(p));
    return a;
}

__device__ __forceinline__ void cp_async16(uint32_t s, const void* g) {
    asm volatile("cp.async.cg.shared.global [%0], [%1], 16;" :: "r"(s), "l"(g));
}
#define CP_COMMIT() asm volatile("cp.async.commit_group;" ::: "memory")
#define CP_WAIT0()  asm volatile("cp.async.wait_group 0;" ::: "memory")

// ---------------------------------------------------------------------------
// Pack adj (int32 0/1) into bitmask: g_mask[row*128 + w], bit (j%32) = adj>0
// ---------------------------------------------------------------------------
__global__ void pack_kernel(const int* __restrict__ adj,
                            uint32_t* __restrict__ mask) {
    const int lane = threadIdx.x & 31;
    const int gw = (blockIdx.x * 256 + threadIdx.x) >> 5;  // warp id, 8192 total
    #pragma unroll 4
    for (int k = 0; k < 64; k++) {
        size_t word = (size_t)gw * 64 + k;
        int v = adj[word * 32 + lane];
        uint32_t b = __ballot_sync(0xffffffffu, v > 0);
        if (lane == 0) mask[word] = b;
    }
}

// ---------------------------------------------------------------------------
// GEMM: C[4096,256] = A[4096,256] @ B[256,256]  (packed fma2 micro-kernel)
// ---------------------------------------------------------------------------
__global__ void gemm_kernel(const float* __restrict__ A,
                            const float* __restrict__ B,
                            float* __restrict__ C) {
    __shared__ __align__(16) float As[16][64];
    __shared__ __align__(16) float Bs[16][64];
    const int tid = threadIdx.x;
    const int tx = tid & 15;
    const int ty = tid >> 4;
    const int blockRow = blockIdx.y * 64;
    const int blockCol = blockIdx.x * 64;

    unsigned long long acc2[4][2] = {};

    for (int kk = 0; kk < FDIM; kk += 16) {
        {
            int r  = tid >> 2;
            int kq = (tid & 3) * 4;
            float4 v = *reinterpret_cast<const float4*>(
                &A[(blockRow + r) * FDIM + kk + kq]);
            As[kq + 0][r] = v.x;
            As[kq + 1][r] = v.y;
            As[kq + 2][r] = v.z;
            As[kq + 3][r] = v.w;
        }
        {
            int k = tid >> 4;
            int c = (tid & 15) * 4;
            *reinterpret_cast<float4*>(&Bs[k][c]) =
                *reinterpret_cast<const float4*>(
                    &B[(kk + k) * FDIM + blockCol + c]);
        }
        __syncthreads();
        #pragma unroll
        for (int k = 0; k < 16; k++) {
            F4U av, bv;
            av.f = *reinterpret_cast<float4*>(&As[k][ty * 4]);
            bv.f = *reinterpret_cast<float4*>(&Bs[k][tx * 4]);
            unsigned long long a0 = dup2(av.f.x);
            unsigned long long a1 = dup2(av.f.y);
            unsigned long long a2 = dup2(av.f.z);
            unsigned long long a3 = dup2(av.f.w);
            fma2(acc2[0][0], a0, bv.u.x); fma2(acc2[0][1], a0, bv.u.y);
            fma2(acc2[1][0], a1, bv.u.x); fma2(acc2[1][1], a1, bv.u.y);
            fma2(acc2[2][0], a2, bv.u.x); fma2(acc2[2][1], a2, bv.u.y);
            fma2(acc2[3][0], a3, bv.u.x); fma2(acc2[3][1], a3, bv.u.y);
        }
        __syncthreads();
    }
    #pragma unroll
    for (int i = 0; i < 4; i++) {
        F4U v;
        v.u.x = acc2[i][0];
        v.u.y = acc2[i][1];
        *reinterpret_cast<float4*>(
            &C[(blockRow + ty * 4 + i) * FDIM + blockCol + tx * 4]) = v.f;
    }
}

// ---------------------------------------------------------------------------
// f1[i] = Wh[i,:] . a[0:256],  f2[i] = Wh[i,:] . a[256:512]
// ---------------------------------------------------------------------------
__global__ void fvec_kernel(const float* __restrict__ Wh,
                            const float* __restrict__ a,
                            float* __restrict__ f1,
                            float* __restrict__ f2) {
    const int warp = threadIdx.x >> 5;
    const int lane = threadIdx.x & 31;
    const int row  = blockIdx.x * 8 + warp;
    float s1 = 0.f, s2 = 0.f;
    #pragma unroll
    for (int k = lane; k < FDIM; k += 32) {
        float w = Wh[row * FDIM + k];
        s1 += w * a[k];
        s2 += w * a[FDIM + k];
    }
    #pragma unroll
    for (int off = 16; off; off >>= 1) {
        s1 += __shfl_xor_sync(0xffffffffu, s1, off);
        s2 += __shfl_xor_sync(0xffffffffu, s2, off);
    }
    if (lane == 0) { f1[row] = s1; f2[row] = s2; }
}

// ---------------------------------------------------------------------------
// Row max via monotonicity: m[i] = leaky(f1[i] + max_{adj(i,j)=1} f2[j]).
// leaky/+f1 are monotone, so this equals max_j leaky(f1+f2[j]) exactly.
// Bitmask-driven; f2 + row masks staged in smem. 8 rows/CTA (1 warp each).
// ---------------------------------------------------------------------------
__global__ __launch_bounds__(256)
void rowmax_kernel(const uint32_t* __restrict__ mask,
                   const float* __restrict__ f1,
                   const float* __restrict__ f2,
                   float* __restrict__ m) {
    __shared__ __align__(16) float f2s[NN];        // 16 KB
    __shared__ uint32_t ms[8][128];                // 4 KB
    const int tid  = threadIdx.x;
    const int lane = tid & 31;
    const int warp = tid >> 5;
    const int row0 = blockIdx.x * 8;

    #pragma unroll
    for (int k = 0; k < 4; k++) {
        int c = k * 256 + tid;                     // float4 index
        reinterpret_cast<float4*>(f2s)[c] =
            reinterpret_cast<const float4*>(f2)[c];
    }
    #pragma unroll
    for (int k = 0; k < 4; k++) {
        int i = k * 256 + tid;                     // 1024 words
        ms[i >> 7][i & 127] = mask[(size_t)(row0 + (i >> 7)) * 128 + (i & 127)];
    }
    __syncthreads();

    float mx = -1.0e30f;
    #pragma unroll 8
    for (int k = 0; k < 128; k++) {
        uint32_t w = ms[warp][k];
        float v = f2s[k * 32 + lane];
        if ((w >> lane) & 1u) mx = fmaxf(mx, v);
    }
    #pragma unroll
    for (int off = 16; off; off >>= 1)
        mx = fmaxf(mx, __shfl_xor_sync(0xffffffffu, mx, off));
    if (lane == 0) {
        int row = row0 + warp;
        if (mx < -1.0e29f) {
            m[row] = NEG_INF_V;                    // no neighbors: match old path
        } else {
            float s = f1[row] + mx;
            m[row] = s > 0.f ? s : ALPHA_LR * s;
        }
    }
}

// ---------------------------------------------------------------------------
// Fused attention, precomputed row max. CTA: 8 warps, 32 rows x 256 feats.
// j-split across warps: warp (rowg = w&1, jg = w>>1) owns 16 rows x 16 j per
// 64-j tile, partial sums (no redundant cross-warp Wh reads).
// adj via 2MB bitmask (1 LDG.32/thread/tile). p_s AND Wh double-buffered ->
// ONE barrier per tile; cp.async copy overlaps the FMA phase.
// ---------------------------------------------------------------------------
__global__ __launch_bounds__(256)
void attn_kernel(const float* __restrict__ Wh,
                 const uint32_t* __restrict__ mask,
                 const float* __restrict__ f1,
                 const float* __restrict__ f2,
                 const float* __restrict__ m,
                 float* __restrict__ out) {
    extern __shared__ __align__(16) float4 whs[];  // [2][64 j][64 f4] 128KB
    __shared__ __align__(16) float p_s[2][32][128]; // duplicated p, 2x16KB
    __shared__ float l_s[32];

    const int tid  = threadIdx.x;
    const int lane = tid & 31;
    const int warp = tid >> 5;
    const int rowg = warp & 1;                     // row half (16 rows)
    const int jg   = warp >> 1;                    // j quarter (16 j)
    const int row0 = blockIdx.x * 32;
    const float4* whg = reinterpret_cast<const float4*>(Wh);
    const uint32_t sbase = smem_u32(whs);

    // p-production assignment: thread owns row prow, j's [jb, jb+8) of tile
    const int prow = tid >> 3;                     // 0..31
    const int jb   = (tid & 7) * 8;
    const int growp = row0 + prow;
    const float f1r = f1[growp];
    const float mr  = m[growp];
    const uint32_t* mrow = mask + (size_t)growp * 128;
    float ls = 0.f;

    unsigned long long acc[16][4] = {};            // 16 rows x 8 feats (f32x2)

    // Prefetched production regs (for tile 'tt')
    float4 fv0, fv1;
    uint32_t mw;

    // ---- prologue: tile 0 ----
    fv0 = *reinterpret_cast<const float4*>(&f2[jb]);
    fv1 = *reinterpret_cast<const float4*>(&f2[jb + 4]);
    mw  = mrow[(jb >> 5)];
    #pragma unroll
    for (int k = 0; k < 16; k++) {
        int c = k * 256 + tid;
        cp_async16(sbase + c * 16, whg + c);
    }
    CP_COMMIT();
    {   // produce p[0]
        uint32_t mbyte = (mw >> (jb & 31)) & 0xffu;
        const float fv[8] = {fv0.x, fv0.y, fv0.z, fv0.w,
                             fv1.x, fv1.y, fv1.z, fv1.w};
        float pv[8];
        #pragma unroll
        for (int q = 0; q < 8; q++) {
            float s = f1r + fv[q];
            float e = s > 0.f ? s : ALPHA_LR * s;
            float sc = ((mbyte >> q) & 1u) ? e : NEG_INF_V;
            pv[q] = __expf(sc - mr);
            ls += pv[q];
        }
        float* dst = &p_s[0][prow][16 * (tid & 7)];
        #pragma unroll
        for (int q = 0; q < 4; q++)
            *reinterpret_cast<float4*>(dst + 4 * q) =
                make_float4(pv[2 * q], pv[2 * q], pv[2 * q + 1], pv[2 * q + 1]);
    }
    // regs for tile 1
    fv0 = *reinterpret_cast<const float4*>(&f2[64 + jb]);
    fv1 = *reinterpret_cast<const float4*>(&f2[64 + jb + 4]);
    mw  = mrow[2 + (jb >> 5)];
    CP_WAIT0();
    __syncthreads();

    for (int t = 0; t < 64; t++) {
        if (t < 63) {
            // stage Wh tile t+1 into buf (t+1)&1 (prev readers ended at t-1)
            const float4* src = whg + (size_t)(t + 1) * 4096;
            uint32_t dst = sbase + ((t + 1) & 1) * 65536u;
            #pragma unroll
            for (int k = 0; k < 16; k++) {
                int c = k * 256 + tid;
                cp_async16(dst + c * 16, src + c);
            }
            CP_COMMIT();
            // produce p[t+1] into p_s[(t+1)&1]
            uint32_t mbyte = (mw >> (jb & 31)) & 0xffu;
            const float fv[8] = {fv0.x, fv0.y, fv0.z, fv0.w,
                                 fv1.x, fv1.y, fv1.z, fv1.w};
            float pv[8];
            #pragma unroll
            for (int q = 0; q < 8; q++) {
                float s = f1r + fv[q];
                float e = s > 0.f ? s : ALPHA_LR * s;
                float sc = ((mbyte >> q) & 1u) ? e : NEG_INF_V;
                pv[q] = __expf(sc - mr);
                ls += pv[q];
            }
            float* pdst = &p_s[(t + 1) & 1][prow][16 * (tid & 7)];
            #pragma unroll
            for (int q = 0; q < 4; q++)
                *reinterpret_cast<float4*>(pdst + 4 * q) =
                    make_float4(pv[2 * q], pv[2 * q], pv[2 * q + 1], pv[2 * q + 1]);
            // regs for tile t+2 (wrap; final discarded)
            int tn = (t + 2) & 63;
            fv0 = *reinterpret_cast<const float4*>(&f2[tn * 64 + jb]);
            fv1 = *reinterpret_cast<const float4*>(&f2[tn * 64 + jb + 4]);
            mw  = mrow[2 * tn + (jb >> 5)];
        }

        // Partial acc += P[16 rows x 16 j] @ Wh_s[16 j x 256 f]
        const float4* wb = whs + (t & 1) * 4096;
        const float2* p2 = reinterpret_cast<const float2*>(p_s[t & 1]);
        #pragma unroll
        for (int jj = 0; jj < 16; jj++) {
            const int j = jg * 16 + jj;
            F4U w0, w1;
            w0.f = wb[j * 64 + lane];
            w1.f = wb[j * 64 + 32 + lane];
            #pragma unroll
            for (int i = 0; i < 16; i++) {
                F2U q;
                q.f = p2[(rowg * 16 + i) * 64 + j];  // LDS.64 broadcast
                fma2(acc[i][0], q.u, w0.u.x);
                fma2(acc[i][1], q.u, w0.u.y);
                fma2(acc[i][2], q.u, w1.u.x);
                fma2(acc[i][3], q.u, w1.u.y);
            }
        }
        if (t < 63) CP_WAIT0();                    // tile t+1 landed (overlapped)
        __syncthreads();
    }

    // l: reduce over the 8 threads sharing a p-row (lanes grouped by tid&7)
    ls += __shfl_xor_sync(0xffffffffu, ls, 1);
    ls += __shfl_xor_sync(0xffffffffu, ls, 2);
    ls += __shfl_xor_sync(0xffffffffu, ls, 4);
    if ((tid & 7) == 0) l_s[prow] = ls;
    __syncthreads();

    // Reduce the 4 j-group partials into whs buffer 0 (reused as scratch)
    float4* red = reinterpret_cast<float4*>(whs);  // [32 rows][64 f4] 32KB
    #pragma unroll
    for (int round = 0; round < 4; round++) {
        if (jg == round) {
            #pragma unroll
            for (int i = 0; i < 16; i++) {
                int r = rowg * 16 + i;
                F4U v0, v1;
                v0.u.x = acc[i][0]; v0.u.y = acc[i][1];
                v1.u.x = acc[i][2]; v1.u.y = acc[i][3];
                if (round == 0) {
                    red[r * 64 + lane]      = v0.f;
                    red[r * 64 + 32 + lane] = v1.f;
                } else {
                    float4 o0 = red[r * 64 + lane];
                    float4 o1 = red[r * 64 + 32 + lane];
                    o0.x += v0.f.x; o0.y += v0.f.y; o0.z += v0.f.z; o0.w += v0.f.w;
                    o1.x += v1.f.x; o1.y += v1.f.y; o1.z += v1.f.z; o1.w += v1.f.w;
                    red[r * 64 + lane]      = o0;
                    red[r * 64 + 32 + lane] = o1;
                }
            }
        }
        __syncthreads();
    }

    // Normalize, ELU, store (2048 float4 / 256 threads = 8 each)
    #pragma unroll
    for (int k = 0; k < 8; k++) {
        int c = k * 256 + tid;
        int r = c >> 6;
        float inv = 1.f / l_s[r];
        float4 v = red[c];
        v.x *= inv; v.y *= inv; v.z *= inv; v.w *= inv;
        v.x = v.x > 0.f ? v.x : (__expf(v.x) - 1.f);
        v.y = v.y > 0.f ? v.y : (__expf(v.y) - 1.f);
        v.z = v.z > 0.f ? v.z : (__expf(v.z) - 1.f);
        v.w = v.w > 0.f ? v.w : (__expf(v.w) - 1.f);
        reinterpret_cast<float4*>(out)[(size_t)(row0 + r) * 64 + (c & 63)] = v;
    }
}

// ---------------------------------------------------------------------------
extern "C" void kernel_launch(void* const* d_in, const int* in_sizes, int n_in,
                              void* d_out, int out_size) {
    const float* input = (const float*)d_in[0];
    const int*   adj   = (const int*)  d_in[1];
    const float* W0    = (const float*)d_in[2];
    const float* Wl[3] = {(const float*)d_in[3], (const float*)d_in[5],
                          (const float*)d_in[7]};
    const float* al[3] = {(const float*)d_in[4], (const float*)d_in[6],
                          (const float*)d_in[8]};
    float* out = (float*)d_out;

    float *h, *Wh, *f1, *f2, *m;
    uint32_t* mask;
    cudaGetSymbolAddress((void**)&h,    g_h);
    cudaGetSymbolAddress((void**)&Wh,   g_Wh);
    cudaGetSymbolAddress((void**)&f1,   g_f1);
    cudaGetSymbolAddress((void**)&f2,   g_f2);
    cudaGetSymbolAddress((void**)&m,    g_m);
    cudaGetSymbolAddress((void**)&mask, g_mask);

    const int ATTN_SMEM = 2 * 65536;               // double-buffered Wh tile
    static bool attr_set = false;
    if (!attr_set) {
        cudaFuncSetAttribute(attn_kernel,
                             cudaFuncAttributeMaxDynamicSharedMemorySize,
                             ATTN_SMEM);
        attr_set = true;
    }

    dim3 gemmGrid(FDIM / 64, NN / 64);   // (4, 64)
    dim3 attnGrid(NN / 32);              // 128 CTAs, one wave

    pack_kernel<<<1024, 256>>>(adj, mask);
    gemm_kernel<<<gemmGrid, 256>>>(input, W0, h);

    for (int l = 0; l < 3; l++) {
        gemm_kernel<<<gemmGrid, 256>>>(h, Wl[l], Wh);
        fvec_kernel<<<NN / 8, 256>>>(Wh, al[l], f1, f2);
        rowmax_kernel<<<NN / 8, 256>>>(mask, f1, f2, m);
        float* dst = (l == 2) ? out : h;
        attn_kernel<<<attnGrid, 256, ATTN_SMEM>>>(Wh, mask, f1, f2, m, dst);
    }
}

// round 11
// speedup vs baseline: 2.9827x; 1.0097x over previous
#include <cuda_runtime.h>
#include <cstdint>

#define NN 4096
#define FDIM 256
#define ALPHA_LR 0.01f
#define NEG_INF_V -9.0e15f
#define ROWS 28                     // rows per attn CTA (147 CTAs ~ 148 SMs)
#define HALF 14

// Scratch (allocation-free rule: __device__ globals)
__device__ __align__(16) float g_h[NN * FDIM];
__device__ __align__(16) float g_Wh[NN * FDIM];
__device__ float g_f1[NN];
__device__ float g_f2[NN];
__device__ float g_m[NN];
__device__ __align__(16) uint32_t g_mask[NN * NN / 32];   // 2MB bitmask

union F4U { float4 f; ulonglong2 u; };

__device__ __forceinline__ void fma2(unsigned long long& d,
                                     unsigned long long a,
                                     unsigned long long b) {
    asm("fma.rn.f32x2 %0, %1, %2, %0;" : "+l"(d) : "l"(a), "l"(b));
}

__device__ __forceinline__ unsigned long long dup2(float b) {
    unsigned long long q;
    asm("mov.b64 %0, {%1, %1};" : "=l"(q) : "r"(__float_as_int(b)));
    return q;
}

__device__ __forceinline__ uint32_t smem_u32(const void* p) {
    uint32_t a;
    asm("{ .reg .u64 t; cvta.to.shared.u64 t, %1; cvt.u32.u64 %0, t; }"
        : "=r"(a) : "l"(p));
    return a;
}

__device__ __forceinline__ void cp_async16(uint32_t s, const void* g) {
    asm volatile("cp.async.cg.shared.global [%0], [%1], 16;" :: "r"(s), "l"(g));
}
#define CP_COMMIT() asm volatile("cp.async.commit_group;" ::: "memory")
#define CP_WAIT0()  asm volatile("cp.async.wait_group 0;" ::: "memory")

// ---------------------------------------------------------------------------
// Pack adj (int32 0/1) into bitmask: g_mask[row*128 + w], bit (j%32) = adj>0
// ---------------------------------------------------------------------------
__global__ void pack_kernel(const int* __restrict__ adj,
                            uint32_t* __restrict__ mask) {
    const int lane = threadIdx.x & 31;
    const int gw = (blockIdx.x * 256 + threadIdx.x) >> 5;  // warp id, 8192 total
    #pragma unroll 4
    for (int k = 0; k < 64; k++) {
        size_t word = (size_t)gw * 64 + k;
        int v = adj[word * 32 + lane];
        uint32_t b = __ballot_sync(0xffffffffu, v > 0);
        if (lane == 0) mask[word] = b;
    }
}

// ---------------------------------------------------------------------------
// GEMM: C[4096,256] = A[4096,256] @ B[256,256]
// 128x64 tiles, 8x4 micro-kernel, packed fma2.
// ---------------------------------------------------------------------------
__global__ __launch_bounds__(256)
void gemm_kernel(const float* __restrict__ A,
                 const float* __restrict__ B,
                 float* __restrict__ C) {
    __shared__ __align__(16) float As[16][128];
    __shared__ __align__(16) float Bs[16][64];
    const int tid = threadIdx.x;
    const int tx = tid & 15;                 // 0..15 -> 4 cols each
    const int ty = tid >> 4;                 // 0..15 -> 8 rows each
    const int blockRow = blockIdx.y * 128;
    const int blockCol = blockIdx.x * 64;

    unsigned long long acc2[8][2] = {};

    for (int kk = 0; kk < FDIM; kk += 16) {
        // A tile 128x16 -> As[k][row] (transposed store); 2 float4/thread
        {
            int r = tid >> 1;                // 0..127
            int cq = (tid & 1) * 2;          // float4 index 0..3 (two each)
            #pragma unroll
            for (int q = 0; q < 2; q++) {
                float4 v = *reinterpret_cast<const float4*>(
                    &A[(size_t)(blockRow + r) * FDIM + kk + (cq + q) * 4]);
                As[(cq + q) * 4 + 0][r] = v.x;
                As[(cq + q) * 4 + 1][r] = v.y;
                As[(cq + q) * 4 + 2][r] = v.z;
                As[(cq + q) * 4 + 3][r] = v.w;
            }
        }
        // B tile 16x64; 1 float4/thread
        {
            int k = tid >> 4;
            int c = (tid & 15) * 4;
            *reinterpret_cast<float4*>(&Bs[k][c]) =
                *reinterpret_cast<const float4*>(
                    &B[(size_t)(kk + k) * FDIM + blockCol + c]);
        }
        __syncthreads();
        #pragma unroll
        for (int k = 0; k < 16; k++) {
            F4U a0, a1, bv;
            a0.f = *reinterpret_cast<float4*>(&As[k][ty * 8]);
            a1.f = *reinterpret_cast<float4*>(&As[k][ty * 8 + 4]);
            bv.f = *reinterpret_cast<float4*>(&Bs[k][tx * 4]);
            unsigned long long q0 = dup2(a0.f.x);
            unsigned long long q1 = dup2(a0.f.y);
            unsigned long long q2 = dup2(a0.f.z);
            unsigned long long q3 = dup2(a0.f.w);
            unsigned long long q4 = dup2(a1.f.x);
            unsigned long long q5 = dup2(a1.f.y);
            unsigned long long q6 = dup2(a1.f.z);
            unsigned long long q7 = dup2(a1.f.w);
            fma2(acc2[0][0], q0, bv.u.x); fma2(acc2[0][1], q0, bv.u.y);
            fma2(acc2[1][0], q1, bv.u.x); fma2(acc2[1][1], q1, bv.u.y);
            fma2(acc2[2][0], q2, bv.u.x); fma2(acc2[2][1], q2, bv.u.y);
            fma2(acc2[3][0], q3, bv.u.x); fma2(acc2[3][1], q3, bv.u.y);
            fma2(acc2[4][0], q4, bv.u.x); fma2(acc2[4][1], q4, bv.u.y);
            fma2(acc2[5][0], q5, bv.u.x); fma2(acc2[5][1], q5, bv.u.y);
            fma2(acc2[6][0], q6, bv.u.x); fma2(acc2[6][1], q6, bv.u.y);
            fma2(acc2[7][0], q7, bv.u.x); fma2(acc2[7][1], q7, bv.u.y);
        }
        __syncthreads();
    }
    #pragma unroll
    for (int i = 0; i < 8; i++) {
        F4U v;
        v.u.x = acc2[i][0];
        v.u.y = acc2[i][1];
        *reinterpret_cast<float4*>(
            &C[(size_t)(blockRow + ty * 8 + i) * FDIM + blockCol + tx * 4]) = v.f;
    }
}

// ---------------------------------------------------------------------------
// f1[i] = Wh[i,:] . a[0:256],  f2[i] = Wh[i,:] . a[256:512]
// ---------------------------------------------------------------------------
__global__ void fvec_kernel(const float* __restrict__ Wh,
                            const float* __restrict__ a,
                            float* __restrict__ f1,
                            float* __restrict__ f2) {
    const int warp = threadIdx.x >> 5;
    const int lane = threadIdx.x & 31;
    const int row  = blockIdx.x * 8 + warp;
    float s1 = 0.f, s2 = 0.f;
    #pragma unroll
    for (int k = lane; k < FDIM; k += 32) {
        float w = Wh[row * FDIM + k];
        s1 += w * a[k];
        s2 += w * a[FDIM + k];
    }
    #pragma unroll
    for (int off = 16; off; off >>= 1) {
        s1 += __shfl_xor_sync(0xffffffffu, s1, off);
        s2 += __shfl_xor_sync(0xffffffffu, s2, off);
    }
    if (lane == 0) { f1[row] = s1; f2[row] = s2; }
}

// ---------------------------------------------------------------------------
// Row max via monotonicity: m[i] = leaky(f1[i] + max_{adj(i,j)=1} f2[j]).
// ---------------------------------------------------------------------------
__global__ __launch_bounds__(256)
void rowmax_kernel(const uint32_t* __restrict__ mask,
                   const float* __restrict__ f1,
                   const float* __restrict__ f2,
                   float* __restrict__ m) {
    __shared__ __align__(16) float f2s[NN];        // 16 KB
    __shared__ uint32_t ms[8][128];                // 4 KB
    const int tid  = threadIdx.x;
    const int lane = tid & 31;
    const int warp = tid >> 5;
    const int row0 = blockIdx.x * 8;

    #pragma unroll
    for (int k = 0; k < 4; k++) {
        int c = k * 256 + tid;
        reinterpret_cast<float4*>(f2s)[c] =
            reinterpret_cast<const float4*>(f2)[c];
    }
    #pragma unroll
    for (int k = 0; k < 4; k++) {
        int i = k * 256 + tid;
        ms[i >> 7][i & 127] = mask[(size_t)(row0 + (i >> 7)) * 128 + (i & 127)];
    }
    __syncthreads();

    float mx = -1.0e30f;
    #pragma unroll 8
    for (int k = 0; k < 128; k++) {
        uint32_t w = ms[warp][k];
        float v = f2s[k * 32 + lane];
        if ((w >> lane) & 1u) mx = fmaxf(mx, v);
    }
    #pragma unroll
    for (int off = 16; off; off >>= 1)
        mx = fmaxf(mx, __shfl_xor_sync(0xffffffffu, mx, off));
    if (lane == 0) {
        int row = row0 + warp;
        if (mx < -1.0e29f) {
            m[row] = NEG_INF_V;
        } else {
            float s = f1[row] + mx;
            m[row] = s > 0.f ? s : ALPHA_LR * s;
        }
    }
}

// ---------------------------------------------------------------------------
// Fused attention, precomputed row max. CTA: 8 warps, 28 rows x 256 feats
// (grid 147 -> fills 148 SMs in one wave). j-split across warps: warp
// (rowg = w&1, jg = w>>1) owns 14 rows x 16 j per 64-j tile, partial sums.
// p stored duplicated (p,p); consumed as LDS.128 broadcast pairs (j,j+1).
// Wh + p double-buffered; one barrier per tile; cp.async overlaps FMA.
// ---------------------------------------------------------------------------
__global__ __launch_bounds__(256)
void attn_kernel(const float* __restrict__ Wh,
                 const uint32_t* __restrict__ mask,
                 const float* __restrict__ f1,
                 const float* __restrict__ f2,
                 const float* __restrict__ m,
                 float* __restrict__ out) {
    extern __shared__ __align__(16) float4 whs[];    // [2][64 j][64 f4] 128KB
    __shared__ __align__(16) float p_s[2][ROWS][128]; // duplicated p
    __shared__ float l_s[ROWS];

    const int tid  = threadIdx.x;
    const int lane = tid & 31;
    const int warp = tid >> 5;
    const int rowg = warp & 1;                     // row half (HALF rows)
    const int jg   = warp >> 1;                    // j quarter (16 j)
    const int row0 = blockIdx.x * ROWS;
    const float4* whg = reinterpret_cast<const float4*>(Wh);
    const uint32_t sbase = smem_u32(whs);

    // p-production: thread owns row prow (if < ROWS), j's [jb, jb+8) of tile
    const int prow = tid >> 3;                     // 0..31
    const bool pact = prow < ROWS;
    const int jb   = (tid & 7) * 8;
    const int growp = min(row0 + prow, NN - 1);
    const float f1r = f1[growp];
    const float mr  = m[growp];
    const uint32_t* mrow = mask + (size_t)growp * 128;
    float ls = 0.f;

    unsigned long long acc[HALF][4] = {};          // 14 rows x 8 feats (f32x2)

    float4 fv0, fv1;
    uint32_t mw;

    // ---- prologue: tile 0 ----
    fv0 = *reinterpret_cast<const float4*>(&f2[jb]);
    fv1 = *reinterpret_cast<const float4*>(&f2[jb + 4]);
    mw  = mrow[(jb >> 5)];
    #pragma unroll
    for (int k = 0; k < 16; k++) {
        int c = k * 256 + tid;
        cp_async16(sbase + c * 16, whg + c);
    }
    CP_COMMIT();
    {   // produce p[0]
        uint32_t mbyte = (mw >> (jb & 31)) & 0xffu;
        const float fv[8] = {fv0.x, fv0.y, fv0.z, fv0.w,
                             fv1.x, fv1.y, fv1.z, fv1.w};
        float pv[8];
        #pragma unroll
        for (int q = 0; q < 8; q++) {
            float s = f1r + fv[q];
            float e = s > 0.f ? s : ALPHA_LR * s;
            float sc = ((mbyte >> q) & 1u) ? e : NEG_INF_V;
            pv[q] = __expf(sc - mr);
            ls += pv[q];
        }
        if (pact) {
            float* dst = &p_s[0][prow][16 * (tid & 7)];
            #pragma unroll
            for (int q = 0; q < 4; q++)
                *reinterpret_cast<float4*>(dst + 4 * q) =
                    make_float4(pv[2 * q], pv[2 * q], pv[2 * q + 1], pv[2 * q + 1]);
        }
    }
    fv0 = *reinterpret_cast<const float4*>(&f2[64 + jb]);
    fv1 = *reinterpret_cast<const float4*>(&f2[64 + jb + 4]);
    mw  = mrow[2 + (jb >> 5)];
    CP_WAIT0();
    __syncthreads();

    for (int t = 0; t < 64; t++) {
        if (t < 63) {
            // stage Wh tile t+1 into buf (t+1)&1
            const float4* src = whg + (size_t)(t + 1) * 4096;
            uint32_t dst = sbase + ((t + 1) & 1) * 65536u;
            #pragma unroll
            for (int k = 0; k < 16; k++) {
                int c = k * 256 + tid;
                cp_async16(dst + c * 16, src + c);
            }
            CP_COMMIT();
            // produce p[t+1]
            uint32_t mbyte = (mw >> (jb & 31)) & 0xffu;
            const float fv[8] = {fv0.x, fv0.y, fv0.z, fv0.w,
                                 fv1.x, fv1.y, fv1.z, fv1.w};
            float pv[8];
            #pragma unroll
            for (int q = 0; q < 8; q++) {
                float s = f1r + fv[q];
                float e = s > 0.f ? s : ALPHA_LR * s;
                float sc = ((mbyte >> q) & 1u) ? e : NEG_INF_V;
                pv[q] = __expf(sc - mr);
                ls += pv[q];
            }
            if (pact) {
                float* pdst = &p_s[(t + 1) & 1][prow][16 * (tid & 7)];
                #pragma unroll
                for (int q = 0; q < 4; q++)
                    *reinterpret_cast<float4*>(pdst + 4 * q) =
                        make_float4(pv[2 * q], pv[2 * q],
                                    pv[2 * q + 1], pv[2 * q + 1]);
            }
            int tn = (t + 2) & 63;
            fv0 = *reinterpret_cast<const float4*>(&f2[tn * 64 + jb]);
            fv1 = *reinterpret_cast<const float4*>(&f2[tn * 64 + jb + 4]);
            mw  = mrow[2 * tn + (jb >> 5)];
        }

        // Partial acc += P[14 rows x 16 j] @ Wh_s[16 j x 256 f]
        // p read as LDS.128 broadcast: float4 index jp holds j pair (2jp,2jp+1)
        const float4* wb = whs + (t & 1) * 4096;
        const float4* p4 = reinterpret_cast<const float4*>(p_s[t & 1]);
        #pragma unroll
        for (int jp = 0; jp < 8; jp++) {
            const int j0 = jg * 16 + 2 * jp;
            F4U w0a, w0b, w1a, w1b;
            w0a.f = wb[j0 * 64 + lane];
            w0b.f = wb[j0 * 64 + 32 + lane];
            w1a.f = wb[(j0 + 1) * 64 + lane];
            w1b.f = wb[(j0 + 1) * 64 + 32 + lane];
            #pragma unroll
            for (int i = 0; i < HALF; i++) {
                F4U q;
                q.f = p4[(rowg * HALF + i) * 32 + jg * 8 + jp];
                fma2(acc[i][0], q.u.x, w0a.u.x);
                fma2(acc[i][1], q.u.x, w0a.u.y);
                fma2(acc[i][2], q.u.x, w0b.u.x);
                fma2(acc[i][3], q.u.x, w0b.u.y);
                fma2(acc[i][0], q.u.y, w1a.u.x);
                fma2(acc[i][1], q.u.y, w1a.u.y);
                fma2(acc[i][2], q.u.y, w1b.u.x);
                fma2(acc[i][3], q.u.y, w1b.u.y);
            }
        }
        if (t < 63) CP_WAIT0();
        __syncthreads();
    }

    // l: reduce over the 8 threads sharing a p-row
    ls += __shfl_xor_sync(0xffffffffu, ls, 1);
    ls += __shfl_xor_sync(0xffffffffu, ls, 2);
    ls += __shfl_xor_sync(0xffffffffu, ls, 4);
    if ((tid & 7) == 0 && pact) l_s[prow] = ls;
    __syncthreads();

    // Reduce the 4 j-group partials into whs buffer 0 (reused as scratch)
    float4* red = reinterpret_cast<float4*>(whs);  // [28 rows][64 f4] 28KB
    #pragma unroll
    for (int round = 0; round < 4; round++) {
        if (jg == round) {
            #pragma unroll
            for (int i = 0; i < HALF; i++) {
                int r = rowg * HALF + i;
                F4U v0, v1;
                v0.u.x = acc[i][0]; v0.u.y = acc[i][1];
                v1.u.x = acc[i][2]; v1.u.y = acc[i][3];
                if (round == 0) {
                    red[r * 64 + lane]      = v0.f;
                    red[r * 64 + 32 + lane] = v1.f;
                } else {
                    float4 o0 = red[r * 64 + lane];
                    float4 o1 = red[r * 64 + 32 + lane];
                    o0.x += v0.f.x; o0.y += v0.f.y; o0.z += v0.f.z; o0.w += v0.f.w;
                    o1.x += v1.f.x; o1.y += v1.f.y; o1.z += v1.f.z; o1.w += v1.f.w;
                    red[r * 64 + lane]      = o0;
                    red[r * 64 + 32 + lane] = o1;
                }
            }
        }
        __syncthreads();
    }

    // Normalize, ELU, store (28*64 = 1792 float4 / 256 threads = 7 each)
    #pragma unroll
    for (int k = 0; k < 7; k++) {
        int c = k * 256 + tid;
        int r = c >> 6;
        int grow = row0 + r;
        if (grow < NN) {
            float inv = 1.f / l_s[r];
            float4 v = red[c];
            v.x *= inv; v.y *= inv; v.z *= inv; v.w *= inv;
            v.x = v.x > 0.f ? v.x : (__expf(v.x) - 1.f);
            v.y = v.y > 0.f ? v.y : (__expf(v.y) - 1.f);
            v.z = v.z > 0.f ? v.z : (__expf(v.z) - 1.f);
            v.w = v.w > 0.f ? v.w : (__expf(v.w) - 1.f);
            reinterpret_cast<float4*>(out)[(size_t)grow * 64 + (c & 63)] = v;
        }
    }
}

// ---------------------------------------------------------------------------
extern "C" void kernel_launch(void* const* d_in, const int* in_sizes, int n_in,
                              void* d_out, int out_size) {
    const float* input = (const float*)d_in[0];
    const int*   adj   = (const int*)  d_in[1];
    const float* W0    = (const float*)d_in[2];
    const float* Wl[3] = {(const float*)d_in[3], (const float*)d_in[5],
                          (const float*)d_in[7]};
    const float* al[3] = {(const float*)d_in[4], (const float*)d_in[6],
                          (const float*)d_in[8]};
    float* out = (float*)d_out;

    float *h, *Wh, *f1, *f2, *m;
    uint32_t* mask;
    cudaGetSymbolAddress((void**)&h,    g_h);
    cudaGetSymbolAddress((void**)&Wh,   g_Wh);
    cudaGetSymbolAddress((void**)&f1,   g_f1);
    cudaGetSymbolAddress((void**)&f2,   g_f2);
    cudaGetSymbolAddress((void**)&m,    g_m);
    cudaGetSymbolAddress((void**)&mask, g_mask);

    const int ATTN_SMEM = 2 * 65536;               // double-buffered Wh tile
    static bool attr_set = false;
    if (!attr_set) {
        cudaFuncSetAttribute(attn_kernel,
                             cudaFuncAttributeMaxDynamicSharedMemorySize,
                             ATTN_SMEM);
        attr_set = true;
    }

    dim3 gemmGrid(FDIM / 64, NN / 128);  // (4, 32)
    dim3 attnGrid((NN + ROWS - 1) / ROWS);  // 147 CTAs, one wave on 148 SMs

    pack_kernel<<<1024, 256>>>(adj, mask);
    gemm_kernel<<<gemmGrid, 256>>>(input, W0, h);

    for (int l = 0; l < 3; l++) {
        gemm_kernel<<<gemmGrid, 256>>>(h, Wl[l], Wh);
        fvec_kernel<<<NN / 8, 256>>>(Wh, al[l], f1, f2);
        rowmax_kernel<<<NN / 8, 256>>>(mask, f1, f2, m);
        float* dst = (l == 2) ? out : h;
        attn_kernel<<<attnGrid, 256, ATTN_SMEM>>>(Wh, mask, f1, f2, m, dst);
    }
}

// round 12
// speedup vs baseline: 3.2088x; 1.0758x over previous
#include <cuda_runtime.h>
#include <cuda_bf16.h>
#include <cstdint>

#define NN 4096
#define FDIM 256
#define ALPHA_LR 0.01f
#define NEG_INF_V -9.0e15f
#define ROWS 32

// Scratch (allocation-free rule: __device__ globals)
__device__ __align__(16) float g_h[NN * FDIM];
__device__ __align__(16) float g_Wh[NN * FDIM];
__device__ float g_f1[NN];
__device__ float g_f2[NN];
__device__ float g_m[NN];
__device__ __align__(16) uint32_t g_mask[NN * NN / 32];   // 2MB bitmask
// WhT packed bf16x2 j-pairs: [f][j/2], hi and lo parts (2MB each)
__device__ __align__(16) uint32_t g_whh[FDIM * NN / 2];
__device__ __align__(16) uint32_t g_whl[FDIM * NN / 2];

union F4U { float4 f; ulonglong2 u; };

__device__ __forceinline__ void fma2(unsigned long long& d,
                                     unsigned long long a,
                                     unsigned long long b) {
    asm("fma.rn.f32x2 %0, %1, %2, %0;" : "+l"(d) : "l"(a), "l"(b));
}

__device__ __forceinline__ unsigned long long dup2(float b) {
    unsigned long long q;
    asm("mov.b64 %0, {%1, %1};" : "=l"(q) : "r"(__float_as_int(b)));
    return q;
}

__device__ __forceinline__ uint32_t smem_u32(const void* p) {
    uint32_t a;
    asm("{ .reg .u64 t; cvta.to.shared.u64 t, %1; cvt.u32.u64 %0, t; }"
        : "=r"(a) : "l"(p));
    return a;
}

__device__ __forceinline__ void cp_async16(uint32_t s, const void* g) {
    asm volatile("cp.async.cg.shared.global [%0], [%1], 16;" :: "r"(s), "l"(g));
}
#define CP_COMMIT() asm volatile("cp.async.commit_group;" ::: "memory")
#define CP_WAIT0()  asm volatile("cp.async.wait_group 0;" ::: "memory")

// bf16 hi/lo split of a float pair, packed bf16x2 (even low, odd high)
__device__ __forceinline__ void split2(float pe, float po,
                                       uint32_t& hw, uint32_t& lw) {
    __nv_bfloat16 he = __float2bfloat16(pe);
    __nv_bfloat16 ho = __float2bfloat16(po);
    float re = pe - __bfloat162float(he);
    float ro = po - __bfloat162float(ho);
    __nv_bfloat162 h2 = __halves2bfloat162(he, ho);
    __nv_bfloat162 l2 = __floats2bfloat162_rn(re, ro);
    hw = *reinterpret_cast<uint32_t*>(&h2);
    lw = *reinterpret_cast<uint32_t*>(&l2);
}

__device__ __forceinline__ void mma_bf16(float& d0, float& d1, float& d2, float& d3,
                                         uint32_t a0, uint32_t a1,
                                         uint32_t a2, uint32_t a3,
                                         uint32_t b0, uint32_t b1) {
    asm volatile(
        "mma.sync.aligned.m16n8k16.row.col.f32.bf16.bf16.f32 "
        "{%0,%1,%2,%3}, {%4,%5,%6,%7}, {%8,%9}, {%0,%1,%2,%3};"
        : "+f"(d0), "+f"(d1), "+f"(d2), "+f"(d3)
        : "r"(a0), "r"(a1), "r"(a2), "r"(a3), "r"(b0), "r"(b1));
}

// ---------------------------------------------------------------------------
// Pack adj (int32 0/1) into bitmask
// ---------------------------------------------------------------------------
__global__ void pack_kernel(const int* __restrict__ adj,
                            uint32_t* __restrict__ mask) {
    const int lane = threadIdx.x & 31;
    const int gw = (blockIdx.x * 256 + threadIdx.x) >> 5;
    #pragma unroll 4
    for (int k = 0; k < 64; k++) {
        size_t word = (size_t)gw * 64 + k;
        int v = adj[word * 32 + lane];
        uint32_t b = __ballot_sync(0xffffffffu, v > 0);
        if (lane == 0) mask[word] = b;
    }
}

// ---------------------------------------------------------------------------
// GEMM: C[4096,256] = A[4096,256] @ B[256,256] (128x64 tiles, fma2)
// ---------------------------------------------------------------------------
__global__ __launch_bounds__(256)
void gemm_kernel(const float* __restrict__ A,
                 const float* __restrict__ B,
                 float* __restrict__ C) {
    __shared__ __align__(16) float As[16][128];
    __shared__ __align__(16) float Bs[16][64];
    const int tid = threadIdx.x;
    const int tx = tid & 15;
    const int ty = tid >> 4;
    const int blockRow = blockIdx.y * 128;
    const int blockCol = blockIdx.x * 64;

    unsigned long long acc2[8][2] = {};

    for (int kk = 0; kk < FDIM; kk += 16) {
        {
            int r = tid >> 1;
            int cq = (tid & 1) * 2;
            #pragma unroll
            for (int q = 0; q < 2; q++) {
                float4 v = *reinterpret_cast<const float4*>(
                    &A[(size_t)(blockRow + r) * FDIM + kk + (cq + q) * 4]);
                As[(cq + q) * 4 + 0][r] = v.x;
                As[(cq + q) * 4 + 1][r] = v.y;
                As[(cq + q) * 4 + 2][r] = v.z;
                As[(cq + q) * 4 + 3][r] = v.w;
            }
        }
        {
            int k = tid >> 4;
            int c = (tid & 15) * 4;
            *reinterpret_cast<float4*>(&Bs[k][c]) =
                *reinterpret_cast<const float4*>(
                    &B[(size_t)(kk + k) * FDIM + blockCol + c]);
        }
        __syncthreads();
        #pragma unroll
        for (int k = 0; k < 16; k++) {
            F4U a0, a1, bv;
            a0.f = *reinterpret_cast<float4*>(&As[k][ty * 8]);
            a1.f = *reinterpret_cast<float4*>(&As[k][ty * 8 + 4]);
            bv.f = *reinterpret_cast<float4*>(&Bs[k][tx * 4]);
            unsigned long long q0 = dup2(a0.f.x);
            unsigned long long q1 = dup2(a0.f.y);
            unsigned long long q2 = dup2(a0.f.z);
            unsigned long long q3 = dup2(a0.f.w);
            unsigned long long q4 = dup2(a1.f.x);
            unsigned long long q5 = dup2(a1.f.y);
            unsigned long long q6 = dup2(a1.f.z);
            unsigned long long q7 = dup2(a1.f.w);
            fma2(acc2[0][0], q0, bv.u.x); fma2(acc2[0][1], q0, bv.u.y);
            fma2(acc2[1][0], q1, bv.u.x); fma2(acc2[1][1], q1, bv.u.y);
            fma2(acc2[2][0], q2, bv.u.x); fma2(acc2[2][1], q2, bv.u.y);
            fma2(acc2[3][0], q3, bv.u.x); fma2(acc2[3][1], q3, bv.u.y);
            fma2(acc2[4][0], q4, bv.u.x); fma2(acc2[4][1], q4, bv.u.y);
            fma2(acc2[5][0], q5, bv.u.x); fma2(acc2[5][1], q5, bv.u.y);
            fma2(acc2[6][0], q6, bv.u.x); fma2(acc2[6][1], q6, bv.u.y);
            fma2(acc2[7][0], q7, bv.u.x); fma2(acc2[7][1], q7, bv.u.y);
        }
        __syncthreads();
    }
    #pragma unroll
    for (int i = 0; i < 8; i++) {
        F4U v;
        v.u.x = acc2[i][0];
        v.u.y = acc2[i][1];
        *reinterpret_cast<float4*>(
            &C[(size_t)(blockRow + ty * 8 + i) * FDIM + blockCol + tx * 4]) = v.f;
    }
}

// ---------------------------------------------------------------------------
// f1/f2 matvecs
// ---------------------------------------------------------------------------
__global__ void fvec_kernel(const float* __restrict__ Wh,
                            const float* __restrict__ a,
                            float* __restrict__ f1,
                            float* __restrict__ f2) {
    const int warp = threadIdx.x >> 5;
    const int lane = threadIdx.x & 31;
    const int row  = blockIdx.x * 8 + warp;
    float s1 = 0.f, s2 = 0.f;
    #pragma unroll
    for (int k = lane; k < FDIM; k += 32) {
        float w = Wh[row * FDIM + k];
        s1 += w * a[k];
        s2 += w * a[FDIM + k];
    }
    #pragma unroll
    for (int off = 16; off; off >>= 1) {
        s1 += __shfl_xor_sync(0xffffffffu, s1, off);
        s2 += __shfl_xor_sync(0xffffffffu, s2, off);
    }
    if (lane == 0) { f1[row] = s1; f2[row] = s2; }
}

// ---------------------------------------------------------------------------
// Row max via monotonicity
// ---------------------------------------------------------------------------
__global__ __launch_bounds__(256)
void rowmax_kernel(const uint32_t* __restrict__ mask,
                   const float* __restrict__ f1,
                   const float* __restrict__ f2,
                   float* __restrict__ m) {
    __shared__ __align__(16) float f2s[NN];
    __shared__ uint32_t ms[8][128];
    const int tid  = threadIdx.x;
    const int lane = tid & 31;
    const int warp = tid >> 5;
    const int row0 = blockIdx.x * 8;

    #pragma unroll
    for (int k = 0; k < 4; k++) {
        int c = k * 256 + tid;
        reinterpret_cast<float4*>(f2s)[c] =
            reinterpret_cast<const float4*>(f2)[c];
    }
    #pragma unroll
    for (int k = 0; k < 4; k++) {
        int i = k * 256 + tid;
        ms[i >> 7][i & 127] = mask[(size_t)(row0 + (i >> 7)) * 128 + (i & 127)];
    }
    __syncthreads();

    float mx = -1.0e30f;
    #pragma unroll 8
    for (int k = 0; k < 128; k++) {
        uint32_t w = ms[warp][k];
        float v = f2s[k * 32 + lane];
        if ((w >> lane) & 1u) mx = fmaxf(mx, v);
    }
    #pragma unroll
    for (int off = 16; off; off >>= 1)
        mx = fmaxf(mx, __shfl_xor_sync(0xffffffffu, mx, off));
    if (lane == 0) {
        int row = row0 + warp;
        if (mx < -1.0e29f) {
            m[row] = NEG_INF_V;
        } else {
            float s = f1[row] + mx;
            m[row] = s > 0.f ? s : ALPHA_LR * s;
        }
    }
}

// ---------------------------------------------------------------------------
// Convert Wh[j][f] fp32 -> packed bf16x2 j-pair words [f][j/2], hi & lo
// ---------------------------------------------------------------------------
__global__ __launch_bounds__(256)
void wconv_kernel(const float* __restrict__ Wh,
                  uint32_t* __restrict__ whh,
                  uint32_t* __restrict__ whl) {
    __shared__ float tile[64][33];
    const int tid = threadIdx.x;
    const int jt = blockIdx.x * 64;
    const int ft = blockIdx.y * 32;
    {
        int r = tid >> 2;
        int c8 = (tid & 3) * 8;
        float4 v0 = *reinterpret_cast<const float4*>(
            &Wh[(size_t)(jt + r) * FDIM + ft + c8]);
        float4 v1 = *reinterpret_cast<const float4*>(
            &Wh[(size_t)(jt + r) * FDIM + ft + c8 + 4]);
        tile[r][c8 + 0] = v0.x; tile[r][c8 + 1] = v0.y;
        tile[r][c8 + 2] = v0.z; tile[r][c8 + 3] = v0.w;
        tile[r][c8 + 4] = v1.x; tile[r][c8 + 5] = v1.y;
        tile[r][c8 + 6] = v1.z; tile[r][c8 + 7] = v1.w;
    }
    __syncthreads();
    {
        int f = tid >> 3;
        int j2l = (tid & 7) * 4;
        uint32_t hw[4], lw[4];
        #pragma unroll
        for (int q = 0; q < 4; q++) {
            int j = 2 * (j2l + q);
            split2(tile[j][f], tile[j + 1][f], hw[q], lw[q]);
        }
        size_t off = (size_t)(ft + f) * (NN / 2) + (jt >> 1) + j2l;
        *reinterpret_cast<uint4*>(&whh[off]) = make_uint4(hw[0], hw[1], hw[2], hw[3]);
        *reinterpret_cast<uint4*>(&whl[off]) = make_uint4(lw[0], lw[1], lw[2], lw[3]);
    }
}

// ---------------------------------------------------------------------------
// Fused attention on HMMA (mma.sync bf16 hi/lo split).
// CTA: 8 warps, 32 rows x 256 feats; warp w owns feats [32w, 32w+32).
// Per 64-j tile: P produced & split to smem (padded), WhT hi/lo staged by
// cp.async (double-buffered); each warp: 4 k-steps x 4 n-tiles x 2 m-tiles
// x 3 combos of m16n8k16. fp32 accumulation in registers.
// Smem words: B: buf b at b*18432 (hi 9216 [f][36], lo +9216);
//             P: 36864 + b*2240 (ph 1120 [r][35], pl +1120). Total 165376 B.
// ---------------------------------------------------------------------------
__global__ __launch_bounds__(256)
void attn_kernel(const uint32_t* __restrict__ whh,
                 const uint32_t* __restrict__ whl,
                 const uint32_t* __restrict__ mask,
                 const float* __restrict__ f1,
                 const float* __restrict__ f2,
                 const float* __restrict__ m,
                 float* __restrict__ out) {
    extern __shared__ __align__(16) uint32_t ws[];
    __shared__ float l_s[ROWS];

    const int tid  = threadIdx.x;
    const int lane = tid & 31;
    const int warp = tid >> 5;
    const int g    = lane >> 2;
    const int tig  = lane & 3;
    const int row0 = blockIdx.x * ROWS;
    const uint32_t sbase = smem_u32(ws);

    // P production: thread owns row prow, j's [jb, jb+8) of each tile
    const int prow = tid >> 3;
    const int jb   = (tid & 7) * 8;
    const int grow = row0 + prow;
    const float f1r = f1[grow];
    const float mr  = m[grow];
    const uint32_t* mrow = mask + (size_t)grow * 128;
    float ls = 0.f;

    float acc[2][4][4] = {};                      // [m-tile][n-tile][reg]

    float4 fv0, fv1;
    uint32_t mw;

    // ---- prologue: tile 0 ----
    fv0 = *reinterpret_cast<const float4*>(&f2[jb]);
    fv1 = *reinterpret_cast<const float4*>(&f2[jb + 4]);
    mw  = mrow[(jb >> 5)];
    // stage B tile 0 into buf 0
    #pragma unroll
    for (int k = 0; k < 16; k++) {
        int idx = k * 256 + tid;
        int half = idx >> 11;
        int rem  = idx & 2047;
        int f = rem >> 3, c = rem & 7;
        const uint32_t* src = (half ? whl : whh) + (size_t)f * (NN / 2) + c * 4;
        cp_async16(sbase + (half * 9216 + f * 36 + c * 4) * 4, src);
    }
    CP_COMMIT();
    {   // produce p[0] into buf 0
        uint32_t mbyte = (mw >> (jb & 31)) & 0xffu;
        const float fvr[8] = {fv0.x, fv0.y, fv0.z, fv0.w,
                              fv1.x, fv1.y, fv1.z, fv1.w};
        float pv[8];
        #pragma unroll
        for (int q = 0; q < 8; q++) {
            float s = f1r + fvr[q];
            float e = s > 0.f ? s : ALPHA_LR * s;
            float sc = ((mbyte >> q) & 1u) ? e : NEG_INF_V;
            pv[q] = __expf(sc - mr);
            ls += pv[q];
        }
        uint32_t* ph = ws + 36864;
        uint32_t* pl = ph + 1120;
        int base = prow * 35 + (tid & 7) * 4;
        #pragma unroll
        for (int q = 0; q < 4; q++) {
            uint32_t hw, lw;
            split2(pv[2 * q], pv[2 * q + 1], hw, lw);
            ph[base + q] = hw;
            pl[base + q] = lw;
        }
    }
    fv0 = *reinterpret_cast<const float4*>(&f2[64 + jb]);
    fv1 = *reinterpret_cast<const float4*>(&f2[64 + jb + 4]);
    mw  = mrow[2 + (jb >> 5)];
    CP_WAIT0();
    __syncthreads();

    for (int t = 0; t < 64; t++) {
        if (t < 63) {
            const int b = (t + 1) & 1;
            // stage B tile t+1
            #pragma unroll
            for (int k = 0; k < 16; k++) {
                int idx = k * 256 + tid;
                int half = idx >> 11;
                int rem  = idx & 2047;
                int f = rem >> 3, c = rem & 7;
                const uint32_t* src = (half ? whl : whh) +
                    (size_t)f * (NN / 2) + (t + 1) * 32 + c * 4;
                cp_async16(sbase + (b * 18432 + half * 9216 + f * 36 + c * 4) * 4,
                           src);
            }
            CP_COMMIT();
            // produce p[t+1]
            uint32_t mbyte = (mw >> (jb & 31)) & 0xffu;
            const float fvr[8] = {fv0.x, fv0.y, fv0.z, fv0.w,
                                  fv1.x, fv1.y, fv1.z, fv1.w};
            float pv[8];
            #pragma unroll
            for (int q = 0; q < 8; q++) {
                float s = f1r + fvr[q];
                float e = s > 0.f ? s : ALPHA_LR * s;
                float sc = ((mbyte >> q) & 1u) ? e : NEG_INF_V;
                pv[q] = __expf(sc - mr);
                ls += pv[q];
            }
            uint32_t* ph = ws + 36864 + b * 2240;
            uint32_t* pl = ph + 1120;
            int base = prow * 35 + (tid & 7) * 4;
            #pragma unroll
            for (int q = 0; q < 4; q++) {
                uint32_t hw, lw;
                split2(pv[2 * q], pv[2 * q + 1], hw, lw);
                ph[base + q] = hw;
                pl[base + q] = lw;
            }
            int tn = (t + 2) & 63;
            fv0 = *reinterpret_cast<const float4*>(&f2[tn * 64 + jb]);
            fv1 = *reinterpret_cast<const float4*>(&f2[tn * 64 + jb + 4]);
            mw  = mrow[2 * tn + (jb >> 5)];
        }

        // ---- HMMA phase on buffer t&1 ----
        {
            const uint32_t* Bh = ws + (t & 1) * 18432;
            const uint32_t* Bl = Bh + 9216;
            const uint32_t* ph = ws + 36864 + (t & 1) * 2240;
            const uint32_t* pl = ph + 1120;
            #pragma unroll
            for (int ks = 0; ks < 4; ks++) {
                uint32_t ah[2][4], al[2][4];
                #pragma unroll
                for (int mt = 0; mt < 2; mt++) {
                    int r0 = mt * 16 + g;
                    int w0 = ks * 8 + tig;
                    ah[mt][0] = ph[r0 * 35 + w0];
                    ah[mt][1] = ph[(r0 + 8) * 35 + w0];
                    ah[mt][2] = ph[r0 * 35 + w0 + 4];
                    ah[mt][3] = ph[(r0 + 8) * 35 + w0 + 4];
                    al[mt][0] = pl[r0 * 35 + w0];
                    al[mt][1] = pl[(r0 + 8) * 35 + w0];
                    al[mt][2] = pl[r0 * 35 + w0 + 4];
                    al[mt][3] = pl[(r0 + 8) * 35 + w0 + 4];
                }
                #pragma unroll
                for (int nt = 0; nt < 4; nt++) {
                    int f = warp * 32 + nt * 8 + g;
                    int w0 = ks * 8 + tig;
                    uint32_t bh0 = Bh[f * 36 + w0];
                    uint32_t bh1 = Bh[f * 36 + w0 + 4];
                    uint32_t bl0 = Bl[f * 36 + w0];
                    uint32_t bl1 = Bl[f * 36 + w0 + 4];
                    #pragma unroll
                    for (int mt = 0; mt < 2; mt++) {
                        mma_bf16(acc[mt][nt][0], acc[mt][nt][1],
                                 acc[mt][nt][2], acc[mt][nt][3],
                                 ah[mt][0], ah[mt][1], ah[mt][2], ah[mt][3],
                                 bh0, bh1);
                        mma_bf16(acc[mt][nt][0], acc[mt][nt][1],
                                 acc[mt][nt][2], acc[mt][nt][3],
                                 ah[mt][0], ah[mt][1], ah[mt][2], ah[mt][3],
                                 bl0, bl1);
                        mma_bf16(acc[mt][nt][0], acc[mt][nt][1],
                                 acc[mt][nt][2], acc[mt][nt][3],
                                 al[mt][0], al[mt][1], al[mt][2], al[mt][3],
                                 bh0, bh1);
                    }
                }
            }
        }
        if (t < 63) CP_WAIT0();
        __syncthreads();
    }

    // l: reduce over the 8 threads sharing a p-row
    ls += __shfl_xor_sync(0xffffffffu, ls, 1);
    ls += __shfl_xor_sync(0xffffffffu, ls, 2);
    ls += __shfl_xor_sync(0xffffffffu, ls, 4);
    if ((tid & 7) == 0) l_s[prow] = ls;
    __syncthreads();

    // Epilogue: normalize, ELU, store. D frag: c0,c1 = (row g, cols 2tig,2tig+1);
    // c2,c3 = row g+8.
    #pragma unroll
    for (int mt = 0; mt < 2; mt++) {
        int r0 = mt * 16 + g;
        int r1 = r0 + 8;
        float inv0 = 1.f / l_s[r0];
        float inv1 = 1.f / l_s[r1];
        #pragma unroll
        for (int nt = 0; nt < 4; nt++) {
            int f = warp * 32 + nt * 8 + 2 * tig;
            float v0 = acc[mt][nt][0] * inv0;
            float v1 = acc[mt][nt][1] * inv0;
            float v2 = acc[mt][nt][2] * inv1;
            float v3 = acc[mt][nt][3] * inv1;
            v0 = v0 > 0.f ? v0 : (__expf(v0) - 1.f);
            v1 = v1 > 0.f ? v1 : (__expf(v1) - 1.f);
            v2 = v2 > 0.f ? v2 : (__expf(v2) - 1.f);
            v3 = v3 > 0.f ? v3 : (__expf(v3) - 1.f);
            *reinterpret_cast<float2*>(&out[(size_t)(row0 + r0) * FDIM + f]) =
                make_float2(v0, v1);
            *reinterpret_cast<float2*>(&out[(size_t)(row0 + r1) * FDIM + f]) =
                make_float2(v2, v3);
        }
    }
}

// ---------------------------------------------------------------------------
extern "C" void kernel_launch(void* const* d_in, const int* in_sizes, int n_in,
                              void* d_out, int out_size) {
    const float* input = (const float*)d_in[0];
    const int*   adj   = (const int*)  d_in[1];
    const float* W0    = (const float*)d_in[2];
    const float* Wl[3] = {(const float*)d_in[3], (const float*)d_in[5],
                          (const float*)d_in[7]};
    const float* al[3] = {(const float*)d_in[4], (const float*)d_in[6],
                          (const float*)d_in[8]};
    float* out = (float*)d_out;

    float *h, *Wh, *f1, *f2, *m;
    uint32_t *mask, *whh, *whl;
    cudaGetSymbolAddress((void**)&h,    g_h);
    cudaGetSymbolAddress((void**)&Wh,   g_Wh);
    cudaGetSymbolAddress((void**)&f1,   g_f1);
    cudaGetSymbolAddress((void**)&f2,   g_f2);
    cudaGetSymbolAddress((void**)&m,    g_m);
    cudaGetSymbolAddress((void**)&mask, g_mask);
    cudaGetSymbolAddress((void**)&whh,  g_whh);
    cudaGetSymbolAddress((void**)&whl,  g_whl);

    const int ATTN_SMEM = 165376;                  // B 2x36KB + P 2x8.75KB
    static bool attr_set = false;
    if (!attr_set) {
        cudaFuncSetAttribute(attn_kernel,
                             cudaFuncAttributeMaxDynamicSharedMemorySize,
                             ATTN_SMEM);
        attr_set = true;
    }

    dim3 gemmGrid(FDIM / 64, NN / 128);            // (4, 32)
    dim3 wconvGrid(NN / 64, FDIM / 32);            // (64, 8)
    dim3 attnGrid(NN / ROWS);                      // 128 CTAs

    pack_kernel<<<1024, 256>>>(adj, mask);
    gemm_kernel<<<gemmGrid, 256>>>(input, W0, h);

    for (int l = 0; l < 3; l++) {
        gemm_kernel<<<gemmGrid, 256>>>(h, Wl[l], Wh);
        fvec_kernel<<<NN / 8, 256>>>(Wh, al[l], f1, f2);
        rowmax_kernel<<<NN / 8, 256>>>(mask, f1, f2, m);
        wconv_kernel<<<wconvGrid, 256>>>(Wh, whh, whl);
        float* dst = (l == 2) ? out : h;
        attn_kernel<<<attnGrid, 256, ATTN_SMEM>>>(whh, whl, mask, f1, f2, m, dst);
    }
}

// round 13
// speedup vs baseline: 6.0843x; 1.8961x over previous
#include <cuda_runtime.h>
#include <cuda_bf16.h>
#include <cstdint>

#define NN 4096
#define FDIM 256
#define ALPHA_LR 0.01f
#define NEG_INF_V -9.0e15f
#define ROWS 64

// Scratch (allocation-free rule: __device__ globals)
__device__ __align__(16) float g_h[NN * FDIM];
__device__ __align__(16) float g_Wh[NN * FDIM];
__device__ float g_f1[NN];
__device__ float g_f2[NN];
__device__ float g_m[NN];
__device__ __align__(16) uint32_t g_mask[NN * NN / 32];   // 2MB bitmask
__device__ __align__(16) uint32_t g_whh[FDIM * NN / 2];   // WhT hi [f][j/2]
__device__ __align__(16) uint32_t g_whl[FDIM * NN / 2];   // WhT lo [f][j/2]
__device__ __align__(16) float g_pacc[2 * NN * FDIM];     // partial numerators
__device__ float g_lpart[2 * NN];                         // partial l sums

union F4U { float4 f; ulonglong2 u; };

__device__ __forceinline__ void fma2(unsigned long long& d,
                                     unsigned long long a,
                                     unsigned long long b) {
    asm("fma.rn.f32x2 %0, %1, %2, %0;" : "+l"(d) : "l"(a), "l"(b));
}

__device__ __forceinline__ unsigned long long dup2(float b) {
    unsigned long long q;
    asm("mov.b64 %0, {%1, %1};" : "=l"(q) : "r"(__float_as_int(b)));
    return q;
}

__device__ __forceinline__ uint32_t smem_u32(const void* p) {
    uint32_t a;
    asm("{ .reg .u64 t; cvta.to.shared.u64 t, %1; cvt.u32.u64 %0, t; }"
        : "=r"(a) : "l"(p));
    return a;
}

__device__ __forceinline__ void cp_async16(uint32_t s, const void* g) {
    asm volatile("cp.async.cg.shared.global [%0], [%1], 16;" :: "r"(s), "l"(g));
}
#define CP_COMMIT() asm volatile("cp.async.commit_group;" ::: "memory")
#define CP_WAIT0()  asm volatile("cp.async.wait_group 0;" ::: "memory")

__device__ __forceinline__ void split2(float pe, float po,
                                       uint32_t& hw, uint32_t& lw) {
    __nv_bfloat16 he = __float2bfloat16(pe);
    __nv_bfloat16 ho = __float2bfloat16(po);
    float re = pe - __bfloat162float(he);
    float ro = po - __bfloat162float(ho);
    __nv_bfloat162 h2 = __halves2bfloat162(he, ho);
    __nv_bfloat162 l2 = __floats2bfloat162_rn(re, ro);
    hw = *reinterpret_cast<uint32_t*>(&h2);
    lw = *reinterpret_cast<uint32_t*>(&l2);
}

__device__ __forceinline__ void mma_bf16(float& d0, float& d1, float& d2, float& d3,
                                         uint32_t a0, uint32_t a1,
                                         uint32_t a2, uint32_t a3,
                                         uint32_t b0, uint32_t b1) {
    asm volatile(
        "mma.sync.aligned.m16n8k16.row.col.f32.bf16.bf16.f32 "
        "{%0,%1,%2,%3}, {%4,%5,%6,%7}, {%8,%9}, {%0,%1,%2,%3};"
        : "+f"(d0), "+f"(d1), "+f"(d2), "+f"(d3)
        : "r"(a0), "r"(a1), "r"(a2), "r"(a3), "r"(b0), "r"(b1));
}

__device__ __forceinline__ void ldsm_x4(uint32_t& r0, uint32_t& r1,
                                        uint32_t& r2, uint32_t& r3,
                                        uint32_t addr) {
    asm volatile("ldmatrix.sync.aligned.m8n8.x4.shared.b16 {%0,%1,%2,%3}, [%4];"
                 : "=r"(r0), "=r"(r1), "=r"(r2), "=r"(r3) : "r"(addr));
}

// ---------------------------------------------------------------------------
// Pack adj into bitmask
// ---------------------------------------------------------------------------
__global__ void pack_kernel(const int* __restrict__ adj,
                            uint32_t* __restrict__ mask) {
    const int lane = threadIdx.x & 31;
    const int gw = (blockIdx.x * 256 + threadIdx.x) >> 5;
    #pragma unroll 4
    for (int k = 0; k < 64; k++) {
        size_t word = (size_t)gw * 64 + k;
        int v = adj[word * 32 + lane];
        uint32_t b = __ballot_sync(0xffffffffu, v > 0);
        if (lane == 0) mask[word] = b;
    }
}

// ---------------------------------------------------------------------------
// GEMM: C[4096,256] = A[4096,256] @ B[256,256] (128x64 tiles, fma2)
// ---------------------------------------------------------------------------
__global__ __launch_bounds__(256)
void gemm_kernel(const float* __restrict__ A,
                 const float* __restrict__ B,
                 float* __restrict__ C) {
    __shared__ __align__(16) float As[16][128];
    __shared__ __align__(16) float Bs[16][64];
    const int tid = threadIdx.x;
    const int tx = tid & 15;
    const int ty = tid >> 4;
    const int blockRow = blockIdx.y * 128;
    const int blockCol = blockIdx.x * 64;

    unsigned long long acc2[8][2] = {};

    for (int kk = 0; kk < FDIM; kk += 16) {
        {
            int r = tid >> 1;
            int cq = (tid & 1) * 2;
            #pragma unroll
            for (int q = 0; q < 2; q++) {
                float4 v = *reinterpret_cast<const float4*>(
                    &A[(size_t)(blockRow + r) * FDIM + kk + (cq + q) * 4]);
                As[(cq + q) * 4 + 0][r] = v.x;
                As[(cq + q) * 4 + 1][r] = v.y;
                As[(cq + q) * 4 + 2][r] = v.z;
                As[(cq + q) * 4 + 3][r] = v.w;
            }
        }
        {
            int k = tid >> 4;
            int c = (tid & 15) * 4;
            *reinterpret_cast<float4*>(&Bs[k][c]) =
                *reinterpret_cast<const float4*>(
                    &B[(size_t)(kk + k) * FDIM + blockCol + c]);
        }
        __syncthreads();
        #pragma unroll
        for (int k = 0; k < 16; k++) {
            F4U a0, a1, bv;
            a0.f = *reinterpret_cast<float4*>(&As[k][ty * 8]);
            a1.f = *reinterpret_cast<float4*>(&As[k][ty * 8 + 4]);
            bv.f = *reinterpret_cast<float4*>(&Bs[k][tx * 4]);
            unsigned long long q0 = dup2(a0.f.x);
            unsigned long long q1 = dup2(a0.f.y);
            unsigned long long q2 = dup2(a0.f.z);
            unsigned long long q3 = dup2(a0.f.w);
            unsigned long long q4 = dup2(a1.f.x);
            unsigned long long q5 = dup2(a1.f.y);
            unsigned long long q6 = dup2(a1.f.z);
            unsigned long long q7 = dup2(a1.f.w);
            fma2(acc2[0][0], q0, bv.u.x); fma2(acc2[0][1], q0, bv.u.y);
            fma2(acc2[1][0], q1, bv.u.x); fma2(acc2[1][1], q1, bv.u.y);
            fma2(acc2[2][0], q2, bv.u.x); fma2(acc2[2][1], q2, bv.u.y);
            fma2(acc2[3][0], q3, bv.u.x); fma2(acc2[3][1], q3, bv.u.y);
            fma2(acc2[4][0], q4, bv.u.x); fma2(acc2[4][1], q4, bv.u.y);
            fma2(acc2[5][0], q5, bv.u.x); fma2(acc2[5][1], q5, bv.u.y);
            fma2(acc2[6][0], q6, bv.u.x); fma2(acc2[6][1], q6, bv.u.y);
            fma2(acc2[7][0], q7, bv.u.x); fma2(acc2[7][1], q7, bv.u.y);
        }
        __syncthreads();
    }
    #pragma unroll
    for (int i = 0; i < 8; i++) {
        F4U v;
        v.u.x = acc2[i][0];
        v.u.y = acc2[i][1];
        *reinterpret_cast<float4*>(
            &C[(size_t)(blockRow + ty * 8 + i) * FDIM + blockCol + tx * 4]) = v.f;
    }
}

// ---------------------------------------------------------------------------
// f1/f2 matvecs
// ---------------------------------------------------------------------------
__global__ void fvec_kernel(const float* __restrict__ Wh,
                            const float* __restrict__ a,
                            float* __restrict__ f1,
                            float* __restrict__ f2) {
    const int warp = threadIdx.x >> 5;
    const int lane = threadIdx.x & 31;
    const int row  = blockIdx.x * 8 + warp;
    float s1 = 0.f, s2 = 0.f;
    #pragma unroll
    for (int k = lane; k < FDIM; k += 32) {
        float w = Wh[row * FDIM + k];
        s1 += w * a[k];
        s2 += w * a[FDIM + k];
    }
    #pragma unroll
    for (int off = 16; off; off >>= 1) {
        s1 += __shfl_xor_sync(0xffffffffu, s1, off);
        s2 += __shfl_xor_sync(0xffffffffu, s2, off);
    }
    if (lane == 0) { f1[row] = s1; f2[row] = s2; }
}

// ---------------------------------------------------------------------------
// Row max via monotonicity
// ---------------------------------------------------------------------------
__global__ __launch_bounds__(256)
void rowmax_kernel(const uint32_t* __restrict__ mask,
                   const float* __restrict__ f1,
                   const float* __restrict__ f2,
                   float* __restrict__ m) {
    __shared__ __align__(16) float f2s[NN];
    __shared__ uint32_t ms[8][128];
    const int tid  = threadIdx.x;
    const int lane = tid & 31;
    const int warp = tid >> 5;
    const int row0 = blockIdx.x * 8;

    #pragma unroll
    for (int k = 0; k < 4; k++) {
        int c = k * 256 + tid;
        reinterpret_cast<float4*>(f2s)[c] =
            reinterpret_cast<const float4*>(f2)[c];
    }
    #pragma unroll
    for (int k = 0; k < 4; k++) {
        int i = k * 256 + tid;
        ms[i >> 7][i & 127] = mask[(size_t)(row0 + (i >> 7)) * 128 + (i & 127)];
    }
    __syncthreads();

    float mx = -1.0e30f;
    #pragma unroll 8
    for (int k = 0; k < 128; k++) {
        uint32_t w = ms[warp][k];
        float v = f2s[k * 32 + lane];
        if ((w >> lane) & 1u) mx = fmaxf(mx, v);
    }
    #pragma unroll
    for (int off = 16; off; off >>= 1)
        mx = fmaxf(mx, __shfl_xor_sync(0xffffffffu, mx, off));
    if (lane == 0) {
        int row = row0 + warp;
        if (mx < -1.0e29f) {
            m[row] = NEG_INF_V;
        } else {
            float s = f1[row] + mx;
            m[row] = s > 0.f ? s : ALPHA_LR * s;
        }
    }
}

// ---------------------------------------------------------------------------
// Convert Wh[j][f] fp32 -> packed bf16x2 j-pair words [f][j/2], hi & lo
// ---------------------------------------------------------------------------
__global__ __launch_bounds__(256)
void wconv_kernel(const float* __restrict__ Wh,
                  uint32_t* __restrict__ whh,
                  uint32_t* __restrict__ whl) {
    __shared__ float tile[64][33];
    const int tid = threadIdx.x;
    const int jt = blockIdx.x * 64;
    const int ft = blockIdx.y * 32;
    {
        int r = tid >> 2;
        int c8 = (tid & 3) * 8;
        float4 v0 = *reinterpret_cast<const float4*>(
            &Wh[(size_t)(jt + r) * FDIM + ft + c8]);
        float4 v1 = *reinterpret_cast<const float4*>(
            &Wh[(size_t)(jt + r) * FDIM + ft + c8 + 4]);
        tile[r][c8 + 0] = v0.x; tile[r][c8 + 1] = v0.y;
        tile[r][c8 + 2] = v0.z; tile[r][c8 + 3] = v0.w;
        tile[r][c8 + 4] = v1.x; tile[r][c8 + 5] = v1.y;
        tile[r][c8 + 6] = v1.z; tile[r][c8 + 7] = v1.w;
    }
    __syncthreads();
    {
        int f = tid >> 3;
        int j2l = (tid & 7) * 4;
        uint32_t hw[4], lw[4];
        #pragma unroll
        for (int q = 0; q < 4; q++) {
            int j = 2 * (j2l + q);
            split2(tile[j][f], tile[j + 1][f], hw[q], lw[q]);
        }
        size_t off = (size_t)(ft + f) * (NN / 2) + (jt >> 1) + j2l;
        *reinterpret_cast<uint4*>(&whh[off]) = make_uint4(hw[0], hw[1], hw[2], hw[3]);
        *reinterpret_cast<uint4*>(&whl[off]) = make_uint4(lw[0], lw[1], lw[2], lw[3]);
    }
}

// ---------------------------------------------------------------------------
// Fused attention on HMMA, ldmatrix + XOR swizzle, 64 rows x 256 f x j-half.
// grid (64, 2) = 128 CTAs. Warp w owns feats [32w, 32w+32). 32 tiles of 64 j.
// Smem (words): B buf b: b*16384 (hi 8192 = 256f x 32w, lo +8192);
//               P buf b: 32768 + b*4096 (hi 2048 = 64r x 32w, lo +2048).
// 16B-chunk swizzle: chunk ^= (row & 7). Partial numerators/l to gmem.
// ---------------------------------------------------------------------------
__global__ __launch_bounds__(256)
void attn_kernel(const uint32_t* __restrict__ whh,
                 const uint32_t* __restrict__ whl,
                 const uint32_t* __restrict__ mask,
                 const float* __restrict__ f1,
                 const float* __restrict__ f2,
                 const float* __restrict__ m,
                 float* __restrict__ pacc,
                 float* __restrict__ lpart) {
    extern __shared__ __align__(16) uint32_t ws[];

    const int tid  = threadIdx.x;
    const int lane = tid & 31;
    const int warp = tid >> 5;
    const int g    = lane >> 2;
    const int tig  = lane & 3;
    const int row0 = blockIdx.x * ROWS;
    const int jh   = blockIdx.y;
    const uint32_t sbase = smem_u32(ws);

    // P production: thread owns row prow, 16 j's [jb16, jb16+16) of each tile
    const int prow = tid >> 2;                 // 0..63
    const int jb16 = (tid & 3) * 16;
    const int grow = row0 + prow;
    const float f1r = f1[grow];
    const float mr  = m[grow];
    const uint32_t* mrow = mask + (size_t)grow * 128 + jh * 64;
    float ls = 0.f;

    float acc[4][4][4] = {};                   // [mt][nt][reg]

    // ldmatrix per-thread address components
    const int rowA  = lane & 15;               // A: row within 16-row mt block
    const int koA   = lane >> 4;               // A: k-half
    const int mlocB = lane >> 3;
    const int ntlB  = mlocB >> 1;              // B: nt within pair
    const int koB   = mlocB & 1;               // B: k-half
    const int rowBl = lane & 7;

    float4 fvp[4];
    uint32_t mw;

    // ---- production regs + B staging for tile 0 ----
    #pragma unroll
    for (int q = 0; q < 4; q++)
        fvp[q] = *reinterpret_cast<const float4*>(&f2[jh * 2048 + jb16 + 4 * q]);
    mw = mrow[(jb16 >> 5)];
    #pragma unroll
    for (int k = 0; k < 16; k++) {
        int idx = k * 256 + tid;
        int half = idx >> 11;
        int rem  = idx & 2047;
        int f = rem >> 3, c = rem & 7;
        const uint32_t* src = (half ? whl : whh) +
            (size_t)f * (NN / 2) + jh * 1024 + c * 4;
        cp_async16(sbase + (half * 8192 + f * 32 + ((c ^ (f & 7)) * 4)) * 4, src);
    }
    CP_COMMIT();
    // produce p tile 0 into buf 0
    {
        uint32_t bits = (mw >> (jb16 & 31)) & 0xffffu;
        float pv[16];
        #pragma unroll
        for (int q = 0; q < 16; q++) {
            float fv = ((const float*)fvp)[q];
            float s = f1r + fv;
            float e = s > 0.f ? s : ALPHA_LR * s;
            float sc = ((bits >> q) & 1u) ? e : NEG_INF_V;
            pv[q] = __expf(sc - mr);
            ls += pv[q];
        }
        uint32_t hw[8], lw[8];
        #pragma unroll
        for (int u = 0; u < 8; u++) split2(pv[2 * u], pv[2 * u + 1], hw[u], lw[u]);
        int cb = 2 * (tid & 3);
        uint32_t* ph = ws + 32768 + prow * 32;
        uint32_t* pl = ph + 2048;
        *reinterpret_cast<uint4*>(ph + ((cb) ^ (prow & 7)) * 4) =
            make_uint4(hw[0], hw[1], hw[2], hw[3]);
        *reinterpret_cast<uint4*>(ph + ((cb + 1) ^ (prow & 7)) * 4) =
            make_uint4(hw[4], hw[5], hw[6], hw[7]);
        *reinterpret_cast<uint4*>(pl + ((cb) ^ (prow & 7)) * 4) =
            make_uint4(lw[0], lw[1], lw[2], lw[3]);
        *reinterpret_cast<uint4*>(pl + ((cb + 1) ^ (prow & 7)) * 4) =
            make_uint4(lw[4], lw[5], lw[6], lw[7]);
    }
    // production regs for tile 1
    #pragma unroll
    for (int q = 0; q < 4; q++)
        fvp[q] = *reinterpret_cast<const float4*>(&f2[jh * 2048 + 64 + jb16 + 4 * q]);
    mw = mrow[2 + (jb16 >> 5)];
    CP_WAIT0();
    __syncthreads();

    for (int t = 0; t < 32; t++) {
        if (t < 31) {
            const int b = (t + 1) & 1;
            // stage B tile t+1
            #pragma unroll
            for (int k = 0; k < 16; k++) {
                int idx = k * 256 + tid;
                int half = idx >> 11;
                int rem  = idx & 2047;
                int f = rem >> 3, c = rem & 7;
                const uint32_t* src = (half ? whl : whh) +
                    (size_t)f * (NN / 2) + jh * 1024 + (t + 1) * 32 + c * 4;
                cp_async16(sbase +
                    (b * 16384 + half * 8192 + f * 32 + ((c ^ (f & 7)) * 4)) * 4,
                    src);
            }
            CP_COMMIT();
            // produce p tile t+1
            uint32_t bits = (mw >> (jb16 & 31)) & 0xffffu;
            float pv[16];
            #pragma unroll
            for (int q = 0; q < 16; q++) {
                float fv = ((const float*)fvp)[q];
                float s = f1r + fv;
                float e = s > 0.f ? s : ALPHA_LR * s;
                float sc = ((bits >> q) & 1u) ? e : NEG_INF_V;
                pv[q] = __expf(sc - mr);
                ls += pv[q];
            }
            uint32_t hw[8], lw[8];
            #pragma unroll
            for (int u = 0; u < 8; u++)
                split2(pv[2 * u], pv[2 * u + 1], hw[u], lw[u]);
            int cb = 2 * (tid & 3);
            uint32_t* ph = ws + 32768 + b * 4096 + prow * 32;
            uint32_t* pl = ph + 2048;
            *reinterpret_cast<uint4*>(ph + ((cb) ^ (prow & 7)) * 4) =
                make_uint4(hw[0], hw[1], hw[2], hw[3]);
            *reinterpret_cast<uint4*>(ph + ((cb + 1) ^ (prow & 7)) * 4) =
                make_uint4(hw[4], hw[5], hw[6], hw[7]);
            *reinterpret_cast<uint4*>(pl + ((cb) ^ (prow & 7)) * 4) =
                make_uint4(lw[0], lw[1], lw[2], lw[3]);
            *reinterpret_cast<uint4*>(pl + ((cb + 1) ^ (prow & 7)) * 4) =
                make_uint4(lw[4], lw[5], lw[6], lw[7]);
            // regs for tile t+2
            int tn = (t + 2) & 31;
            #pragma unroll
            for (int q = 0; q < 4; q++)
                fvp[q] = *reinterpret_cast<const float4*>(
                    &f2[jh * 2048 + tn * 64 + jb16 + 4 * q]);
            mw = mrow[2 * tn + (jb16 >> 5)];
        }

        // ---- HMMA phase on buffer t&1 ----
        {
            const int b = t & 1;
            const uint32_t BH = sbase + (b * 16384) * 4;
            const uint32_t BL = BH + 8192 * 4;
            const uint32_t PH = sbase + (32768 + b * 4096) * 4;
            const uint32_t PL = PH + 2048 * 4;
            #pragma unroll
            for (int ks = 0; ks < 4; ks++) {
                uint32_t ah[4][4], al[4][4];
                #pragma unroll
                for (int mt = 0; mt < 4; mt++) {
                    int rin = mt * 16 + rowA;
                    uint32_t off = rin * 128 +
                        (((2 * ks + koA) ^ (rin & 7)) << 4);
                    ldsm_x4(ah[mt][0], ah[mt][1], ah[mt][2], ah[mt][3], PH + off);
                    ldsm_x4(al[mt][0], al[mt][1], al[mt][2], al[mt][3], PL + off);
                }
                #pragma unroll
                for (int ntp = 0; ntp < 2; ntp++) {
                    int fin = warp * 32 + ntp * 16 + ntlB * 8 + rowBl;
                    uint32_t off = fin * 128 +
                        (((2 * ks + koB) ^ (fin & 7)) << 4);
                    uint32_t bh0, bh1, bh2, bh3, bl0, bl1, bl2, bl3;
                    ldsm_x4(bh0, bh1, bh2, bh3, BH + off);
                    ldsm_x4(bl0, bl1, bl2, bl3, BL + off);
                    #pragma unroll
                    for (int mt = 0; mt < 4; mt++) {
                        int n0 = ntp * 2;
                        mma_bf16(acc[mt][n0][0], acc[mt][n0][1],
                                 acc[mt][n0][2], acc[mt][n0][3],
                                 ah[mt][0], ah[mt][1], ah[mt][2], ah[mt][3],
                                 bh0, bh1);
                        mma_bf16(acc[mt][n0][0], acc[mt][n0][1],
                                 acc[mt][n0][2], acc[mt][n0][3],
                                 ah[mt][0], ah[mt][1], ah[mt][2], ah[mt][3],
                                 bl0, bl1);
                        mma_bf16(acc[mt][n0][0], acc[mt][n0][1],
                                 acc[mt][n0][2], acc[mt][n0][3],
                                 al[mt][0], al[mt][1], al[mt][2], al[mt][3],
                                 bh0, bh1);
                        mma_bf16(acc[mt][n0 + 1][0], acc[mt][n0 + 1][1],
                                 acc[mt][n0 + 1][2], acc[mt][n0 + 1][3],
                                 ah[mt][0], ah[mt][1], ah[mt][2], ah[mt][3],
                                 bh2, bh3);
                        mma_bf16(acc[mt][n0 + 1][0], acc[mt][n0 + 1][1],
                                 acc[mt][n0 + 1][2], acc[mt][n0 + 1][3],
                                 ah[mt][0], ah[mt][1], ah[mt][2], ah[mt][3],
                                 bl2, bl3);
                        mma_bf16(acc[mt][n0 + 1][0], acc[mt][n0 + 1][1],
                                 acc[mt][n0 + 1][2], acc[mt][n0 + 1][3],
                                 al[mt][0], al[mt][1], al[mt][2], al[mt][3],
                                 bh2, bh3);
                    }
                }
            }
        }
        if (t < 31) CP_WAIT0();
        __syncthreads();
    }

    // l: reduce over the 4 threads sharing a p-row, write partial
    ls += __shfl_xor_sync(0xffffffffu, ls, 1);
    ls += __shfl_xor_sync(0xffffffffu, ls, 2);
    if ((tid & 3) == 0) lpart[(size_t)jh * NN + grow] = ls;

    // Partial numerators to gmem (no normalization; combine divides)
    #pragma unroll
    for (int mt = 0; mt < 4; mt++) {
        int r0 = row0 + mt * 16 + g;
        int r1 = r0 + 8;
        #pragma unroll
        for (int nt = 0; nt < 4; nt++) {
            int f = warp * 32 + nt * 8 + 2 * tig;
            *reinterpret_cast<float2*>(
                &pacc[((size_t)jh * NN + r0) * FDIM + f]) =
                make_float2(acc[mt][nt][0], acc[mt][nt][1]);
            *reinterpret_cast<float2*>(
                &pacc[((size_t)jh * NN + r1) * FDIM + f]) =
                make_float2(acc[mt][nt][2], acc[mt][nt][3]);
        }
    }
}

// ---------------------------------------------------------------------------
// Combine partials: out = ELU((num0+num1)/(l0+l1))
// ---------------------------------------------------------------------------
__global__ void combine_kernel(const float* __restrict__ pacc,
                               const float* __restrict__ lpart,
                               float* __restrict__ out) {
    int v = blockIdx.x * 256 + threadIdx.x;    // float4 index
    int row = v >> 6;
    int c = (v & 63) * 4;
    float4 a = *reinterpret_cast<const float4*>(&pacc[(size_t)row * FDIM + c]);
    float4 b = *reinterpret_cast<const float4*>(
        &pacc[((size_t)NN + row) * FDIM + c]);
    float inv = 1.f / (lpart[row] + lpart[NN + row]);
    float4 o;
    o.x = (a.x + b.x) * inv; o.y = (a.y + b.y) * inv;
    o.z = (a.z + b.z) * inv; o.w = (a.w + b.w) * inv;
    o.x = o.x > 0.f ? o.x : (__expf(o.x) - 1.f);
    o.y = o.y > 0.f ? o.y : (__expf(o.y) - 1.f);
    o.z = o.z > 0.f ? o.z : (__expf(o.z) - 1.f);
    o.w = o.w > 0.f ? o.w : (__expf(o.w) - 1.f);
    *reinterpret_cast<float4*>(&out[(size_t)row * FDIM + c]) = o;
}

// ---------------------------------------------------------------------------
extern "C" void kernel_launch(void* const* d_in, const int* in_sizes, int n_in,
                              void* d_out, int out_size) {
    const float* input = (const float*)d_in[0];
    const int*   adj   = (const int*)  d_in[1];
    const float* W0    = (const float*)d_in[2];
    const float* Wl[3] = {(const float*)d_in[3], (const float*)d_in[5],
                          (const float*)d_in[7]};
    const float* al[3] = {(const float*)d_in[4], (const float*)d_in[6],
                          (const float*)d_in[8]};
    float* out = (float*)d_out;

    float *h, *Wh, *f1, *f2, *m, *pacc, *lpart;
    uint32_t *mask, *whh, *whl;
    cudaGetSymbolAddress((void**)&h,     g_h);
    cudaGetSymbolAddress((void**)&Wh,    g_Wh);
    cudaGetSymbolAddress((void**)&f1,    g_f1);
    cudaGetSymbolAddress((void**)&f2,    g_f2);
    cudaGetSymbolAddress((void**)&m,     g_m);
    cudaGetSymbolAddress((void**)&mask,  g_mask);
    cudaGetSymbolAddress((void**)&whh,   g_whh);
    cudaGetSymbolAddress((void**)&whl,   g_whl);
    cudaGetSymbolAddress((void**)&pacc,  g_pacc);
    cudaGetSymbolAddress((void**)&lpart, g_lpart);

    const int ATTN_SMEM = 40960 * 4;               // 160 KB
    static bool attr_set = false;
    if (!attr_set) {
        cudaFuncSetAttribute(attn_kernel,
                             cudaFuncAttributeMaxDynamicSharedMemorySize,
                             ATTN_SMEM);
        attr_set = true;
    }

    dim3 gemmGrid(FDIM / 64, NN / 128);            // (4, 32)
    dim3 wconvGrid(NN / 64, FDIM / 32);            // (64, 8)
    dim3 attnGrid(NN / ROWS, 2);                   // (64, 2) = 128 CTAs

    pack_kernel<<<1024, 256>>>(adj, mask);
    gemm_kernel<<<gemmGrid, 256>>>(input, W0, h);

    for (int l = 0; l < 3; l++) {
        gemm_kernel<<<gemmGrid, 256>>>(h, Wl[l], Wh);
        fvec_kernel<<<NN / 8, 256>>>(Wh, al[l], f1, f2);
        rowmax_kernel<<<NN / 8, 256>>>(mask, f1, f2, m);
        wconv_kernel<<<wconvGrid, 256>>>(Wh, whh, whl);
        attn_kernel<<<attnGrid, 256, ATTN_SMEM>>>(whh, whl, mask, f1, f2, m,
                                                  pacc, lpart);
        float* dst = (l == 2) ? out : h;
        combine_kernel<<<NN * FDIM / 4 / 256, 256>>>(pacc, lpart, dst);
    }
}

// round 14
// speedup vs baseline: 6.9828x; 1.1477x over previous
#include <cuda_runtime.h>
#include <cuda_bf16.h>
#include <cstdint>

#define NN 4096
#define FDIM 256
#define ALPHA_LR 0.01f
#define NEG_INF_V -9.0e15f
#define ROWS 64

// Scratch (allocation-free rule: __device__ globals)
__device__ __align__(16) float g_Wh[NN * FDIM];
__device__ float g_f1[NN];
__device__ float g_f2[NN];
__device__ float g_m[NN];
__device__ __align__(16) uint32_t g_mask[NN * NN / 32];   // 2MB bitmask
__device__ __align__(16) uint32_t g_whh[FDIM * NN / 2];   // WhT hi [f][j/2]
__device__ __align__(16) uint32_t g_whl[FDIM * NN / 2];   // WhT lo [f][j/2]
__device__ __align__(16) float g_pacc[2 * NN * FDIM];     // partial numerators
__device__ float g_lpart[2 * NN];                         // partial l sums
// packed h buffers (ping/pong): [m][k/2] bf16x2 hi/lo
__device__ __align__(16) uint32_t g_xh[NN * FDIM / 2];
__device__ __align__(16) uint32_t g_xl[NN * FDIM / 2];
__device__ __align__(16) uint32_t g_yh[NN * FDIM / 2];
__device__ __align__(16) uint32_t g_yl[NN * FDIM / 2];
// transposed weights: [4][n][k/2] bf16x2 hi/lo
__device__ __align__(16) uint32_t g_wth[4 * FDIM * FDIM / 2];
__device__ __align__(16) uint32_t g_wtl[4 * FDIM * FDIM / 2];

__device__ __forceinline__ uint32_t smem_u32(const void* p) {
    uint32_t a;
    asm("{ .reg .u64 t; cvta.to.shared.u64 t, %1; cvt.u32.u64 %0, t; }"
        : "=r"(a) : "l"(p));
    return a;
}

__device__ __forceinline__ void cp_async16(uint32_t s, const void* g) {
    asm volatile("cp.async.cg.shared.global [%0], [%1], 16;" :: "r"(s), "l"(g));
}
#define CP_COMMIT() asm volatile("cp.async.commit_group;" ::: "memory")
#define CP_WAIT0()  asm volatile("cp.async.wait_group 0;" ::: "memory")

__device__ __forceinline__ void split2(float pe, float po,
                                       uint32_t& hw, uint32_t& lw) {
    __nv_bfloat16 he = __float2bfloat16(pe);
    __nv_bfloat16 ho = __float2bfloat16(po);
    float re = pe - __bfloat162float(he);
    float ro = po - __bfloat162float(ho);
    __nv_bfloat162 h2 = __halves2bfloat162(he, ho);
    __nv_bfloat162 l2 = __floats2bfloat162_rn(re, ro);
    hw = *reinterpret_cast<uint32_t*>(&h2);
    lw = *reinterpret_cast<uint32_t*>(&l2);
}

__device__ __forceinline__ void mma_bf16(float& d0, float& d1, float& d2, float& d3,
                                         uint32_t a0, uint32_t a1,
                                         uint32_t a2, uint32_t a3,
                                         uint32_t b0, uint32_t b1) {
    asm volatile(
        "mma.sync.aligned.m16n8k16.row.col.f32.bf16.bf16.f32 "
        "{%0,%1,%2,%3}, {%4,%5,%6,%7}, {%8,%9}, {%0,%1,%2,%3};"
        : "+f"(d0), "+f"(d1), "+f"(d2), "+f"(d3)
        : "r"(a0), "r"(a1), "r"(a2), "r"(a3), "r"(b0), "r"(b1));
}

__device__ __forceinline__ void ldsm_x4(uint32_t& r0, uint32_t& r1,
                                        uint32_t& r2, uint32_t& r3,
                                        uint32_t addr) {
    asm volatile("ldmatrix.sync.aligned.m8n8.x4.shared.b16 {%0,%1,%2,%3}, [%4];"
                 : "=r"(r0), "=r"(r1), "=r"(r2), "=r"(r3) : "r"(addr));
}

// ---------------------------------------------------------------------------
// Pack adj into bitmask
// ---------------------------------------------------------------------------
__global__ void pack_kernel(const int* __restrict__ adj,
                            uint32_t* __restrict__ mask) {
    const int lane = threadIdx.x & 31;
    const int gw = (blockIdx.x * 256 + threadIdx.x) >> 5;
    #pragma unroll 4
    for (int k = 0; k < 64; k++) {
        size_t word = (size_t)gw * 64 + k;
        int v = adj[word * 32 + lane];
        uint32_t b = __ballot_sync(0xffffffffu, v > 0);
        if (lane == 0) mask[word] = b;
    }
}

// ---------------------------------------------------------------------------
// hconv: X fp32 [4096][256] -> packed bf16x2 hi/lo [m][k/2] (no transpose)
// ---------------------------------------------------------------------------
__global__ __launch_bounds__(256)
void hconv_kernel(const float* __restrict__ X,
                  uint32_t* __restrict__ xh,
                  uint32_t* __restrict__ xl) {
    int v = blockIdx.x * 256 + threadIdx.x;       // uint4 index (131072 total)
    int row = v >> 5;
    int c = v & 31;                               // uint4 within row (32)
    const float* src = &X[(size_t)row * FDIM + c * 8];
    float4 a = *reinterpret_cast<const float4*>(src);
    float4 b = *reinterpret_cast<const float4*>(src + 4);
    uint32_t hw[4], lw[4];
    split2(a.x, a.y, hw[0], lw[0]);
    split2(a.z, a.w, hw[1], lw[1]);
    split2(b.x, b.y, hw[2], lw[2]);
    split2(b.z, b.w, hw[3], lw[3]);
    size_t off = (size_t)row * 128 + c * 4;
    *reinterpret_cast<uint4*>(&xh[off]) = make_uint4(hw[0], hw[1], hw[2], hw[3]);
    *reinterpret_cast<uint4*>(&xl[off]) = make_uint4(lw[0], lw[1], lw[2], lw[3]);
}

// ---------------------------------------------------------------------------
// wtconv: W fp32 [k=256][n=256] -> WT packed [n][k/2] hi/lo.
// blockIdx.z selects one of 4 weight matrices.
// ---------------------------------------------------------------------------
__global__ __launch_bounds__(256)
void wtconv_kernel(const float* __restrict__ W0, const float* __restrict__ W1,
                   const float* __restrict__ W2, const float* __restrict__ W3,
                   uint32_t* __restrict__ wth, uint32_t* __restrict__ wtl) {
    __shared__ float tile[64][33];
    const float* Ws[4] = {W0, W1, W2, W3};
    const float* W = Ws[blockIdx.z];
    uint32_t* oth = wth + (size_t)blockIdx.z * (FDIM * FDIM / 2);
    uint32_t* otl = wtl + (size_t)blockIdx.z * (FDIM * FDIM / 2);
    const int tid = threadIdx.x;
    const int kt = blockIdx.x * 64;
    const int nt = blockIdx.y * 32;
    {
        int r = tid >> 2;
        int c8 = (tid & 3) * 8;
        float4 v0 = *reinterpret_cast<const float4*>(&W[(size_t)(kt + r) * FDIM + nt + c8]);
        float4 v1 = *reinterpret_cast<const float4*>(&W[(size_t)(kt + r) * FDIM + nt + c8 + 4]);
        tile[r][c8 + 0] = v0.x; tile[r][c8 + 1] = v0.y;
        tile[r][c8 + 2] = v0.z; tile[r][c8 + 3] = v0.w;
        tile[r][c8 + 4] = v1.x; tile[r][c8 + 5] = v1.y;
        tile[r][c8 + 6] = v1.z; tile[r][c8 + 7] = v1.w;
    }
    __syncthreads();
    {
        int n = tid >> 3;
        int kp = (tid & 7) * 4;                   // k-pair base (of 32 per tile)
        uint32_t hw[4], lw[4];
        #pragma unroll
        for (int q = 0; q < 4; q++) {
            int k = 2 * (kp + q);
            split2(tile[k][n], tile[k + 1][n], hw[q], lw[q]);
        }
        size_t off = (size_t)(nt + n) * (FDIM / 2) + (kt >> 1) + kp;
        *reinterpret_cast<uint4*>(&oth[off]) = make_uint4(hw[0], hw[1], hw[2], hw[3]);
        *reinterpret_cast<uint4*>(&otl[off]) = make_uint4(lw[0], lw[1], lw[2], lw[3]);
    }
}

// ---------------------------------------------------------------------------
// HMMA GEMM: C[4096,256] = A @ W. A packed [m][k/2] hi/lo; WT packed [n][k/2].
// CTA 128m x 64n, warp = (mq = w&3, nh = w>>2): 32m x 32n per warp.
// 4 k-chunks of 64, double-buffered cp.async, XOR-16B swizzle (as attn).
// mode 0: write packed hi/lo (oh/ol); mode 1: write fp32 (Cf).
// ---------------------------------------------------------------------------
__global__ __launch_bounds__(256)
void gemm_hmma_kernel(const uint32_t* __restrict__ ah,
                      const uint32_t* __restrict__ al,
                      const uint32_t* __restrict__ wth,
                      const uint32_t* __restrict__ wtl,
                      float* __restrict__ Cf,
                      uint32_t* __restrict__ oh,
                      uint32_t* __restrict__ ol,
                      int mode) {
    extern __shared__ __align__(16) uint32_t ws[];
    const int tid  = threadIdx.x;
    const int lane = tid & 31;
    const int warp = tid >> 5;
    const int mq = warp & 3;
    const int nh = warp >> 2;
    const int m0 = blockIdx.y * 128;
    const int n0 = blockIdx.x * 64;
    const uint32_t sbase = smem_u32(ws);

    const int rowA  = lane & 15;
    const int koA   = lane >> 4;
    const int mlocB = lane >> 3;
    const int ntlB  = mlocB >> 1;
    const int koB   = mlocB & 1;
    const int rowBl = lane & 7;
    const int g    = lane >> 2;
    const int tig  = lane & 3;

    float acc[2][4][4] = {};                      // [mt][nt(ntp*2+nsub)][reg]

    // stage chunk kc into buffer b
    auto stage = [&](int kc, int b) {
        uint32_t base = b * 12288u;
        #pragma unroll
        for (int k = 0; k < 8; k++) {             // A: 2048 uint4
            int idx = k * 256 + tid;
            int half = idx >> 10;
            int rem  = idx & 1023;
            int r = rem >> 3, c = rem & 7;
            const uint32_t* src = (half ? al : ah) +
                (size_t)(m0 + r) * 128 + kc * 32 + c * 4;
            cp_async16(sbase + (base + half * 4096u + r * 32 + ((c ^ (r & 7)) * 4)) * 4,
                       src);
        }
        #pragma unroll
        for (int k = 0; k < 4; k++) {             // B: 1024 uint4
            int idx = k * 256 + tid;
            int half = idx >> 9;
            int rem  = idx & 511;
            int r = rem >> 3, c = rem & 7;
            const uint32_t* src = (half ? wtl : wth) +
                (size_t)(n0 + r) * 128 + kc * 32 + c * 4;
            cp_async16(sbase + (base + 8192u + half * 2048u + r * 32 +
                                ((c ^ (r & 7)) * 4)) * 4,
                       src);
        }
        CP_COMMIT();
    };

    stage(0, 0);
    CP_WAIT0();
    __syncthreads();

    for (int kc = 0; kc < 4; kc++) {
        if (kc < 3) stage(kc + 1, (kc + 1) & 1);
        const int b = kc & 1;
        const uint32_t AH = sbase + (b * 12288u) * 4;
        const uint32_t AL = AH + 4096u * 4;
        const uint32_t BH = sbase + (b * 12288u + 8192u) * 4;
        const uint32_t BL = BH + 2048u * 4;
        #pragma unroll
        for (int ksl = 0; ksl < 4; ksl++) {
            uint32_t ahf[2][4], alf[2][4];
            #pragma unroll
            for (int mt = 0; mt < 2; mt++) {
                int rin = mq * 32 + mt * 16 + rowA;
                uint32_t off = rin * 128 + (((2 * ksl + koA) ^ (rin & 7)) << 4);
                ldsm_x4(ahf[mt][0], ahf[mt][1], ahf[mt][2], ahf[mt][3], AH + off);
                ldsm_x4(alf[mt][0], alf[mt][1], alf[mt][2], alf[mt][3], AL + off);
            }
            #pragma unroll
            for (int ntp = 0; ntp < 2; ntp++) {
                int fin = nh * 32 + ntp * 16 + ntlB * 8 + rowBl;
                uint32_t off = fin * 128 + (((2 * ksl + koB) ^ (fin & 7)) << 4);
                uint32_t bh0, bh1, bh2, bh3, bl0, bl1, bl2, bl3;
                ldsm_x4(bh0, bh1, bh2, bh3, BH + off);
                ldsm_x4(bl0, bl1, bl2, bl3, BL + off);
                #pragma unroll
                for (int mt = 0; mt < 2; mt++) {
                    int nt0 = ntp * 2;
                    mma_bf16(acc[mt][nt0][0], acc[mt][nt0][1],
                             acc[mt][nt0][2], acc[mt][nt0][3],
                             ahf[mt][0], ahf[mt][1], ahf[mt][2], ahf[mt][3],
                             bh0, bh1);
                    mma_bf16(acc[mt][nt0][0], acc[mt][nt0][1],
                             acc[mt][nt0][2], acc[mt][nt0][3],
                             ahf[mt][0], ahf[mt][1], ahf[mt][2], ahf[mt][3],
                             bl0, bl1);
                    mma_bf16(acc[mt][nt0][0], acc[mt][nt0][1],
                             acc[mt][nt0][2], acc[mt][nt0][3],
                             alf[mt][0], alf[mt][1], alf[mt][2], alf[mt][3],
                             bh0, bh1);
                    mma_bf16(acc[mt][nt0 + 1][0], acc[mt][nt0 + 1][1],
                             acc[mt][nt0 + 1][2], acc[mt][nt0 + 1][3],
                             ahf[mt][0], ahf[mt][1], ahf[mt][2], ahf[mt][3],
                             bh2, bh3);
                    mma_bf16(acc[mt][nt0 + 1][0], acc[mt][nt0 + 1][1],
                             acc[mt][nt0 + 1][2], acc[mt][nt0 + 1][3],
                             ahf[mt][0], ahf[mt][1], ahf[mt][2], ahf[mt][3],
                             bl2, bl3);
                    mma_bf16(acc[mt][nt0 + 1][0], acc[mt][nt0 + 1][1],
                             acc[mt][nt0 + 1][2], acc[mt][nt0 + 1][3],
                             alf[mt][0], alf[mt][1], alf[mt][2], alf[mt][3],
                             bh2, bh3);
                }
            }
        }
        if (kc < 3) CP_WAIT0();
        __syncthreads();
    }

    // Epilogue
    #pragma unroll
    for (int mt = 0; mt < 2; mt++) {
        int r0 = m0 + mq * 32 + mt * 16 + g;
        int r1 = r0 + 8;
        #pragma unroll
        for (int nt = 0; nt < 4; nt++) {
            int f = n0 + nh * 32 + nt * 8 + 2 * tig;
            if (mode == 1) {
                *reinterpret_cast<float2*>(&Cf[(size_t)r0 * FDIM + f]) =
                    make_float2(acc[mt][nt][0], acc[mt][nt][1]);
                *reinterpret_cast<float2*>(&Cf[(size_t)r1 * FDIM + f]) =
                    make_float2(acc[mt][nt][2], acc[mt][nt][3]);
            } else {
                uint32_t hw, lw;
                split2(acc[mt][nt][0], acc[mt][nt][1], hw, lw);
                oh[(size_t)r0 * 128 + (f >> 1)] = hw;
                ol[(size_t)r0 * 128 + (f >> 1)] = lw;
                split2(acc[mt][nt][2], acc[mt][nt][3], hw, lw);
                oh[(size_t)r1 * 128 + (f >> 1)] = hw;
                ol[(size_t)r1 * 128 + (f >> 1)] = lw;
            }
        }
    }
}

// ---------------------------------------------------------------------------
// f1/f2 matvecs
// ---------------------------------------------------------------------------
__global__ void fvec_kernel(const float* __restrict__ Wh,
                            const float* __restrict__ a,
                            float* __restrict__ f1,
                            float* __restrict__ f2) {
    const int warp = threadIdx.x >> 5;
    const int lane = threadIdx.x & 31;
    const int row  = blockIdx.x * 8 + warp;
    float s1 = 0.f, s2 = 0.f;
    #pragma unroll
    for (int k = lane; k < FDIM; k += 32) {
        float w = Wh[row * FDIM + k];
        s1 += w * a[k];
        s2 += w * a[FDIM + k];
    }
    #pragma unroll
    for (int off = 16; off; off >>= 1) {
        s1 += __shfl_xor_sync(0xffffffffu, s1, off);
        s2 += __shfl_xor_sync(0xffffffffu, s2, off);
    }
    if (lane == 0) { f1[row] = s1; f2[row] = s2; }
}

// ---------------------------------------------------------------------------
// Row max via monotonicity
// ---------------------------------------------------------------------------
__global__ __launch_bounds__(256)
void rowmax_kernel(const uint32_t* __restrict__ mask,
                   const float* __restrict__ f1,
                   const float* __restrict__ f2,
                   float* __restrict__ m) {
    __shared__ __align__(16) float f2s[NN];
    __shared__ uint32_t ms[8][128];
    const int tid  = threadIdx.x;
    const int lane = tid & 31;
    const int warp = tid >> 5;
    const int row0 = blockIdx.x * 8;

    #pragma unroll
    for (int k = 0; k < 4; k++) {
        int c = k * 256 + tid;
        reinterpret_cast<float4*>(f2s)[c] =
            reinterpret_cast<const float4*>(f2)[c];
    }
    #pragma unroll
    for (int k = 0; k < 4; k++) {
        int i = k * 256 + tid;
        ms[i >> 7][i & 127] = mask[(size_t)(row0 + (i >> 7)) * 128 + (i & 127)];
    }
    __syncthreads();

    float mx = -1.0e30f;
    #pragma unroll 8
    for (int k = 0; k < 128; k++) {
        uint32_t w = ms[warp][k];
        float v = f2s[k * 32 + lane];
        if ((w >> lane) & 1u) mx = fmaxf(mx, v);
    }
    #pragma unroll
    for (int off = 16; off; off >>= 1)
        mx = fmaxf(mx, __shfl_xor_sync(0xffffffffu, mx, off));
    if (lane == 0) {
        int row = row0 + warp;
        if (mx < -1.0e29f) {
            m[row] = NEG_INF_V;
        } else {
            float s = f1[row] + mx;
            m[row] = s > 0.f ? s : ALPHA_LR * s;
        }
    }
}

// ---------------------------------------------------------------------------
// wconv: Wh[j][f] fp32 -> packed bf16x2 j-pair words [f][j/2], hi & lo
// ---------------------------------------------------------------------------
__global__ __launch_bounds__(256)
void wconv_kernel(const float* __restrict__ Wh,
                  uint32_t* __restrict__ whh,
                  uint32_t* __restrict__ whl) {
    __shared__ float tile[64][33];
    const int tid = threadIdx.x;
    const int jt = blockIdx.x * 64;
    const int ft = blockIdx.y * 32;
    {
        int r = tid >> 2;
        int c8 = (tid & 3) * 8;
        float4 v0 = *reinterpret_cast<const float4*>(
            &Wh[(size_t)(jt + r) * FDIM + ft + c8]);
        float4 v1 = *reinterpret_cast<const float4*>(
            &Wh[(size_t)(jt + r) * FDIM + ft + c8 + 4]);
        tile[r][c8 + 0] = v0.x; tile[r][c8 + 1] = v0.y;
        tile[r][c8 + 2] = v0.z; tile[r][c8 + 3] = v0.w;
        tile[r][c8 + 4] = v1.x; tile[r][c8 + 5] = v1.y;
        tile[r][c8 + 6] = v1.z; tile[r][c8 + 7] = v1.w;
    }
    __syncthreads();
    {
        int f = tid >> 3;
        int j2l = (tid & 7) * 4;
        uint32_t hw[4], lw[4];
        #pragma unroll
        for (int q = 0; q < 4; q++) {
            int j = 2 * (j2l + q);
            split2(tile[j][f], tile[j + 1][f], hw[q], lw[q]);
        }
        size_t off = (size_t)(ft + f) * (NN / 2) + (jt >> 1) + j2l;
        *reinterpret_cast<uint4*>(&whh[off]) = make_uint4(hw[0], hw[1], hw[2], hw[3]);
        *reinterpret_cast<uint4*>(&whl[off]) = make_uint4(lw[0], lw[1], lw[2], lw[3]);
    }
}

// ---------------------------------------------------------------------------
// Fused attention on HMMA (unchanged from R13)
// ---------------------------------------------------------------------------
__global__ __launch_bounds__(256)
void attn_kernel(const uint32_t* __restrict__ whh,
                 const uint32_t* __restrict__ whl,
                 const uint32_t* __restrict__ mask,
                 const float* __restrict__ f1,
                 const float* __restrict__ f2,
                 const float* __restrict__ m,
                 float* __restrict__ pacc,
                 float* __restrict__ lpart) {
    extern __shared__ __align__(16) uint32_t ws[];

    const int tid  = threadIdx.x;
    const int lane = tid & 31;
    const int warp = tid >> 5;
    const int g    = lane >> 2;
    const int tig  = lane & 3;
    const int row0 = blockIdx.x * ROWS;
    const int jh   = blockIdx.y;
    const uint32_t sbase = smem_u32(ws);

    const int prow = tid >> 2;
    const int jb16 = (tid & 3) * 16;
    const int grow = row0 + prow;
    const float f1r = f1[grow];
    const float mr  = m[grow];
    const uint32_t* mrow = mask + (size_t)grow * 128 + jh * 64;
    float ls = 0.f;

    float acc[4][4][4] = {};

    const int rowA  = lane & 15;
    const int koA   = lane >> 4;
    const int mlocB = lane >> 3;
    const int ntlB  = mlocB >> 1;
    const int koB   = mlocB & 1;
    const int rowBl = lane & 7;

    float4 fvp[4];
    uint32_t mw;

    #pragma unroll
    for (int q = 0; q < 4; q++)
        fvp[q] = *reinterpret_cast<const float4*>(&f2[jh * 2048 + jb16 + 4 * q]);
    mw = mrow[(jb16 >> 5)];
    #pragma unroll
    for (int k = 0; k < 16; k++) {
        int idx = k * 256 + tid;
        int half = idx >> 11;
        int rem  = idx & 2047;
        int f = rem >> 3, c = rem & 7;
        const uint32_t* src = (half ? whl : whh) +
            (size_t)f * (NN / 2) + jh * 1024 + c * 4;
        cp_async16(sbase + (half * 8192 + f * 32 + ((c ^ (f & 7)) * 4)) * 4, src);
    }
    CP_COMMIT();
    {
        uint32_t bits = (mw >> (jb16 & 31)) & 0xffffu;
        float pv[16];
        #pragma unroll
        for (int q = 0; q < 16; q++) {
            float fv = ((const float*)fvp)[q];
            float s = f1r + fv;
            float e = s > 0.f ? s : ALPHA_LR * s;
            float sc = ((bits >> q) & 1u) ? e : NEG_INF_V;
            pv[q] = __expf(sc - mr);
            ls += pv[q];
        }
        uint32_t hw[8], lw[8];
        #pragma unroll
        for (int u = 0; u < 8; u++) split2(pv[2 * u], pv[2 * u + 1], hw[u], lw[u]);
        int cb = 2 * (tid & 3);
        uint32_t* ph = ws + 32768 + prow * 32;
        uint32_t* pl = ph + 2048;
        *reinterpret_cast<uint4*>(ph + ((cb) ^ (prow & 7)) * 4) =
            make_uint4(hw[0], hw[1], hw[2], hw[3]);
        *reinterpret_cast<uint4*>(ph + ((cb + 1) ^ (prow & 7)) * 4) =
            make_uint4(hw[4], hw[5], hw[6], hw[7]);
        *reinterpret_cast<uint4*>(pl + ((cb) ^ (prow & 7)) * 4) =
            make_uint4(lw[0], lw[1], lw[2], lw[3]);
        *reinterpret_cast<uint4*>(pl + ((cb + 1) ^ (prow & 7)) * 4) =
            make_uint4(lw[4], lw[5], lw[6], lw[7]);
    }
    #pragma unroll
    for (int q = 0; q < 4; q++)
        fvp[q] = *reinterpret_cast<const float4*>(&f2[jh * 2048 + 64 + jb16 + 4 * q]);
    mw = mrow[2 + (jb16 >> 5)];
    CP_WAIT0();
    __syncthreads();

    for (int t = 0; t < 32; t++) {
        if (t < 31) {
            const int b = (t + 1) & 1;
            #pragma unroll
            for (int k = 0; k < 16; k++) {
                int idx = k * 256 + tid;
                int half = idx >> 11;
                int rem  = idx & 2047;
                int f = rem >> 3, c = rem & 7;
                const uint32_t* src = (half ? whl : whh) +
                    (size_t)f * (NN / 2) + jh * 1024 + (t + 1) * 32 + c * 4;
                cp_async16(sbase +
                    (b * 16384 + half * 8192 + f * 32 + ((c ^ (f & 7)) * 4)) * 4,
                    src);
            }
            CP_COMMIT();
            uint32_t bits = (mw >> (jb16 & 31)) & 0xffffu;
            float pv[16];
            #pragma unroll
            for (int q = 0; q < 16; q++) {
                float fv = ((const float*)fvp)[q];
                float s = f1r + fv;
                float e = s > 0.f ? s : ALPHA_LR * s;
                float sc = ((bits >> q) & 1u) ? e : NEG_INF_V;
                pv[q] = __expf(sc - mr);
                ls += pv[q];
            }
            uint32_t hw[8], lw[8];
            #pragma unroll
            for (int u = 0; u < 8; u++)
                split2(pv[2 * u], pv[2 * u + 1], hw[u], lw[u]);
            int cb = 2 * (tid & 3);
            uint32_t* ph = ws + 32768 + b * 4096 + prow * 32;
            uint32_t* pl = ph + 2048;
            *reinterpret_cast<uint4*>(ph + ((cb) ^ (prow & 7)) * 4) =
                make_uint4(hw[0], hw[1], hw[2], hw[3]);
            *reinterpret_cast<uint4*>(ph + ((cb + 1) ^ (prow & 7)) * 4) =
                make_uint4(hw[4], hw[5], hw[6], hw[7]);
            *reinterpret_cast<uint4*>(pl + ((cb) ^ (prow & 7)) * 4) =
                make_uint4(lw[0], lw[1], lw[2], lw[3]);
            *reinterpret_cast<uint4*>(pl + ((cb + 1) ^ (prow & 7)) * 4) =
                make_uint4(lw[4], lw[5], lw[6], lw[7]);
            int tn = (t + 2) & 31;
            #pragma unroll
            for (int q = 0; q < 4; q++)
                fvp[q] = *reinterpret_cast<const float4*>(
                    &f2[jh * 2048 + tn * 64 + jb16 + 4 * q]);
            mw = mrow[2 * tn + (jb16 >> 5)];
        }

        {
            const int b = t & 1;
            const uint32_t BH = sbase + (b * 16384) * 4;
            const uint32_t BL = BH + 8192 * 4;
            const uint32_t PH = sbase + (32768 + b * 4096) * 4;
            const uint32_t PL = PH + 2048 * 4;
            #pragma unroll
            for (int ks = 0; ks < 4; ks++) {
                uint32_t ah[4][4], al[4][4];
                #pragma unroll
                for (int mt = 0; mt < 4; mt++) {
                    int rin = mt * 16 + rowA;
                    uint32_t off = rin * 128 +
                        (((2 * ks + koA) ^ (rin & 7)) << 4);
                    ldsm_x4(ah[mt][0], ah[mt][1], ah[mt][2], ah[mt][3], PH + off);
                    ldsm_x4(al[mt][0], al[mt][1], al[mt][2], al[mt][3], PL + off);
                }
                #pragma unroll
                for (int ntp = 0; ntp < 2; ntp++) {
                    int fin = warp * 32 + ntp * 16 + ntlB * 8 + rowBl;
                    uint32_t off = fin * 128 +
                        (((2 * ks + koB) ^ (fin & 7)) << 4);
                    uint32_t bh0, bh1, bh2, bh3, bl0, bl1, bl2, bl3;
                    ldsm_x4(bh0, bh1, bh2, bh3, BH + off);
                    ldsm_x4(bl0, bl1, bl2, bl3, BL + off);
                    #pragma unroll
                    for (int mt = 0; mt < 4; mt++) {
                        int n0 = ntp * 2;
                        mma_bf16(acc[mt][n0][0], acc[mt][n0][1],
                                 acc[mt][n0][2], acc[mt][n0][3],
                                 ah[mt][0], ah[mt][1], ah[mt][2], ah[mt][3],
                                 bh0, bh1);
                        mma_bf16(acc[mt][n0][0], acc[mt][n0][1],
                                 acc[mt][n0][2], acc[mt][n0][3],
                                 ah[mt][0], ah[mt][1], ah[mt][2], ah[mt][3],
                                 bl0, bl1);
                        mma_bf16(acc[mt][n0][0], acc[mt][n0][1],
                                 acc[mt][n0][2], acc[mt][n0][3],
                                 al[mt][0], al[mt][1], al[mt][2], al[mt][3],
                                 bh0, bh1);
                        mma_bf16(acc[mt][n0 + 1][0], acc[mt][n0 + 1][1],
                                 acc[mt][n0 + 1][2], acc[mt][n0 + 1][3],
                                 ah[mt][0], ah[mt][1], ah[mt][2], ah[mt][3],
                                 bh2, bh3);
                        mma_bf16(acc[mt][n0 + 1][0], acc[mt][n0 + 1][1],
                                 acc[mt][n0 + 1][2], acc[mt][n0 + 1][3],
                                 ah[mt][0], ah[mt][1], ah[mt][2], ah[mt][3],
                                 bl2, bl3);
                        mma_bf16(acc[mt][n0 + 1][0], acc[mt][n0 + 1][1],
                                 acc[mt][n0 + 1][2], acc[mt][n0 + 1][3],
                                 al[mt][0], al[mt][1], al[mt][2], al[mt][3],
                                 bh2, bh3);
                    }
                }
            }
        }
        if (t < 31) CP_WAIT0();
        __syncthreads();
    }

    ls += __shfl_xor_sync(0xffffffffu, ls, 1);
    ls += __shfl_xor_sync(0xffffffffu, ls, 2);
    if ((tid & 3) == 0) lpart[(size_t)jh * NN + grow] = ls;

    #pragma unroll
    for (int mt = 0; mt < 4; mt++) {
        int r0 = row0 + mt * 16 + g;
        int r1 = r0 + 8;
        #pragma unroll
        for (int nt = 0; nt < 4; nt++) {
            int f = warp * 32 + nt * 8 + 2 * tig;
            *reinterpret_cast<float2*>(
                &pacc[((size_t)jh * NN + r0) * FDIM + f]) =
                make_float2(acc[mt][nt][0], acc[mt][nt][1]);
            *reinterpret_cast<float2*>(
                &pacc[((size_t)jh * NN + r1) * FDIM + f]) =
                make_float2(acc[mt][nt][2], acc[mt][nt][3]);
        }
    }
}

// ---------------------------------------------------------------------------
// Combine partials: v = ELU((num0+num1)/(l0+l1)); write fp32 out (mode 1)
// or packed hi/lo h (mode 0).
// ---------------------------------------------------------------------------
__global__ void combine_kernel(const float* __restrict__ pacc,
                               const float* __restrict__ lpart,
                               float* __restrict__ outf,
                               uint32_t* __restrict__ oh,
                               uint32_t* __restrict__ ol,
                               int mode) {
    int v = blockIdx.x * 256 + threadIdx.x;    // float4 index
    int row = v >> 6;
    int c = (v & 63) * 4;
    float4 a = *reinterpret_cast<const float4*>(&pacc[(size_t)row * FDIM + c]);
    float4 b = *reinterpret_cast<const float4*>(
        &pacc[((size_t)NN + row) * FDIM + c]);
    float inv = 1.f / (lpart[row] + lpart[NN + row]);
    float4 o;
    o.x = (a.x + b.x) * inv; o.y = (a.y + b.y) * inv;
    o.z = (a.z + b.z) * inv; o.w = (a.w + b.w) * inv;
    o.x = o.x > 0.f ? o.x : (__expf(o.x) - 1.f);
    o.y = o.y > 0.f ? o.y : (__expf(o.y) - 1.f);
    o.z = o.z > 0.f ? o.z : (__expf(o.z) - 1.f);
    o.w = o.w > 0.f ? o.w : (__expf(o.w) - 1.f);
    if (mode == 1) {
        *reinterpret_cast<float4*>(&outf[(size_t)row * FDIM + c]) = o;
    } else {
        uint32_t h0, l0, h1, l1;
        split2(o.x, o.y, h0, l0);
        split2(o.z, o.w, h1, l1);
        size_t off = (size_t)row * 128 + (c >> 1);
        *reinterpret_cast<uint2*>(&oh[off]) = make_uint2(h0, h1);
        *reinterpret_cast<uint2*>(&ol[off]) = make_uint2(l0, l1);
    }
}

// ---------------------------------------------------------------------------
extern "C" void kernel_launch(void* const* d_in, const int* in_sizes, int n_in,
                              void* d_out, int out_size) {
    const float* input = (const float*)d_in[0];
    const int*   adj   = (const int*)  d_in[1];
    const float* W0    = (const float*)d_in[2];
    const float* Wl[3] = {(const float*)d_in[3], (const float*)d_in[5],
                          (const float*)d_in[7]};
    const float* al[3] = {(const float*)d_in[4], (const float*)d_in[6],
                          (const float*)d_in[8]};
    float* out = (float*)d_out;

    float *Wh, *f1, *f2, *m, *pacc, *lpart;
    uint32_t *mask, *whh, *whl, *xh, *xl, *yh, *yl, *wth, *wtl;
    cudaGetSymbolAddress((void**)&Wh,    g_Wh);
    cudaGetSymbolAddress((void**)&f1,    g_f1);
    cudaGetSymbolAddress((void**)&f2,    g_f2);
    cudaGetSymbolAddress((void**)&m,     g_m);
    cudaGetSymbolAddress((void**)&mask,  g_mask);
    cudaGetSymbolAddress((void**)&whh,   g_whh);
    cudaGetSymbolAddress((void**)&whl,   g_whl);
    cudaGetSymbolAddress((void**)&pacc,  g_pacc);
    cudaGetSymbolAddress((void**)&lpart, g_lpart);
    cudaGetSymbolAddress((void**)&xh,    g_xh);
    cudaGetSymbolAddress((void**)&xl,    g_xl);
    cudaGetSymbolAddress((void**)&yh,    g_yh);
    cudaGetSymbolAddress((void**)&yl,    g_yl);
    cudaGetSymbolAddress((void**)&wth,   g_wth);
    cudaGetSymbolAddress((void**)&wtl,   g_wtl);

    const int ATTN_SMEM = 40960 * 4;               // 160 KB
    const int GEMM_SMEM = 24576 * 4;               // 96 KB
    static bool attr_set = false;
    if (!attr_set) {
        cudaFuncSetAttribute(attn_kernel,
                             cudaFuncAttributeMaxDynamicSharedMemorySize,
                             ATTN_SMEM);
        cudaFuncSetAttribute(gemm_hmma_kernel,
                             cudaFuncAttributeMaxDynamicSharedMemorySize,
                             GEMM_SMEM);
        attr_set = true;
    }

    dim3 gemmGrid(FDIM / 64, NN / 128);            // (4, 32)
    dim3 wconvGrid(NN / 64, FDIM / 32);            // (64, 8)
    dim3 wtGrid(FDIM / 64, FDIM / 32, 4);          // (4, 8, 4)
    dim3 attnGrid(NN / ROWS, 2);                   // (64, 2)

    pack_kernel<<<1024, 256>>>(adj, mask);
    wtconv_kernel<<<wtGrid, 256>>>(W0, Wl[0], Wl[1], Wl[2], wth, wtl);
    hconv_kernel<<<512, 256>>>(input, xh, xl);
    // h0 = input @ W0 -> packed (yh, yl)
    gemm_hmma_kernel<<<gemmGrid, 256, GEMM_SMEM>>>(
        xh, xl, wth, wtl, nullptr, yh, yl, 0);

    uint32_t* curh = yh;
    uint32_t* curl = yl;
    uint32_t* nxth = xh;
    uint32_t* nxtl = xl;
    const size_t WT_OFF = (size_t)FDIM * FDIM / 2;

    for (int l = 0; l < 3; l++) {
        gemm_hmma_kernel<<<gemmGrid, 256, GEMM_SMEM>>>(
            curh, curl, wth + (l + 1) * WT_OFF, wtl + (l + 1) * WT_OFF,
            Wh, nullptr, nullptr, 1);
        fvec_kernel<<<NN / 8, 256>>>(Wh, al[l], f1, f2);
        rowmax_kernel<<<NN / 8, 256>>>(mask, f1, f2, m);
        wconv_kernel<<<wconvGrid, 256>>>(Wh, whh, whl);
        attn_kernel<<<attnGrid, 256, ATTN_SMEM>>>(whh, whl, mask, f1, f2, m,
                                                  pacc, lpart);
        if (l == 2) {
            combine_kernel<<<NN * FDIM / 4 / 256, 256>>>(
                pacc, lpart, out, nullptr, nullptr, 1);
        } else {
            combine_kernel<<<NN * FDIM / 4 / 256, 256>>>(
                pacc, lpart, nullptr, nxth, nxtl, 0);
            uint32_t* th = curh; uint32_t* tl = curl;
            curh = nxth; curl = nxtl;
            nxth = th;  nxtl = tl;
        }
    }
}

// round 15
// speedup vs baseline: 7.3709x; 1.0556x over previous
#include <cuda_runtime.h>
#include <cuda_bf16.h>
#include <cstdint>

#define NN 4096
#define FDIM 256
#define ALPHA_LR 0.01f
#define NEG_INF_V -9.0e15f
#define ROWS 64
#define JSPLIT 4

// Scratch (allocation-free rule: __device__ globals)
__device__ __align__(16) float g_Wh[NN * FDIM];
__device__ float g_f1[NN];
__device__ float g_f2[NN];
__device__ float g_m[NN];
__device__ __align__(16) uint32_t g_mask[NN * NN / 32];   // 2MB bitmask
__device__ __align__(16) uint32_t g_whh[FDIM * NN / 2];   // WhT hi [f][j/2]
__device__ __align__(16) uint32_t g_whl[FDIM * NN / 2];   // WhT lo [f][j/2]
__device__ __align__(16) float g_pacc[JSPLIT * NN * FDIM]; // partial numerators
__device__ float g_lpart[JSPLIT * NN];                     // partial l sums
// packed h buffers (ping/pong): [m][k/2] bf16x2 hi/lo
__device__ __align__(16) uint32_t g_xh[NN * FDIM / 2];
__device__ __align__(16) uint32_t g_xl[NN * FDIM / 2];
__device__ __align__(16) uint32_t g_yh[NN * FDIM / 2];
__device__ __align__(16) uint32_t g_yl[NN * FDIM / 2];
// transposed weights: [4][n][k/2] bf16x2 hi/lo
__device__ __align__(16) uint32_t g_wth[4 * FDIM * FDIM / 2];
__device__ __align__(16) uint32_t g_wtl[4 * FDIM * FDIM / 2];

__device__ __forceinline__ uint32_t smem_u32(const void* p) {
    uint32_t a;
    asm("{ .reg .u64 t; cvta.to.shared.u64 t, %1; cvt.u32.u64 %0, t; }"
        : "=r"(a) : "l"(p));
    return a;
}

__device__ __forceinline__ void cp_async16(uint32_t s, const void* g) {
    asm volatile("cp.async.cg.shared.global [%0], [%1], 16;" :: "r"(s), "l"(g));
}
#define CP_COMMIT() asm volatile("cp.async.commit_group;" ::: "memory")
#define CP_WAIT0()  asm volatile("cp.async.wait_group 0;" ::: "memory")

__device__ __forceinline__ void split2(float pe, float po,
                                       uint32_t& hw, uint32_t& lw) {
    __nv_bfloat16 he = __float2bfloat16(pe);
    __nv_bfloat16 ho = __float2bfloat16(po);
    float re = pe - __bfloat162float(he);
    float ro = po - __bfloat162float(ho);
    __nv_bfloat162 h2 = __halves2bfloat162(he, ho);
    __nv_bfloat162 l2 = __floats2bfloat162_rn(re, ro);
    hw = *reinterpret_cast<uint32_t*>(&h2);
    lw = *reinterpret_cast<uint32_t*>(&l2);
}

__device__ __forceinline__ void mma_bf16(float& d0, float& d1, float& d2, float& d3,
                                         uint32_t a0, uint32_t a1,
                                         uint32_t a2, uint32_t a3,
                                         uint32_t b0, uint32_t b1) {
    asm volatile(
        "mma.sync.aligned.m16n8k16.row.col.f32.bf16.bf16.f32 "
        "{%0,%1,%2,%3}, {%4,%5,%6,%7}, {%8,%9}, {%0,%1,%2,%3};"
        : "+f"(d0), "+f"(d1), "+f"(d2), "+f"(d3)
        : "r"(a0), "r"(a1), "r"(a2), "r"(a3), "r"(b0), "r"(b1));
}

__device__ __forceinline__ void ldsm_x4(uint32_t& r0, uint32_t& r1,
                                        uint32_t& r2, uint32_t& r3,
                                        uint32_t addr) {
    asm volatile("ldmatrix.sync.aligned.m8n8.x4.shared.b16 {%0,%1,%2,%3}, [%4];"
                 : "=r"(r0), "=r"(r1), "=r"(r2), "=r"(r3) : "r"(addr));
}

// ---------------------------------------------------------------------------
// Pack adj into bitmask
// ---------------------------------------------------------------------------
__global__ void pack_kernel(const int* __restrict__ adj,
                            uint32_t* __restrict__ mask) {
    const int lane = threadIdx.x & 31;
    const int gw = (blockIdx.x * 256 + threadIdx.x) >> 5;
    #pragma unroll 4
    for (int k = 0; k < 64; k++) {
        size_t word = (size_t)gw * 64 + k;
        int v = adj[word * 32 + lane];
        uint32_t b = __ballot_sync(0xffffffffu, v > 0);
        if (lane == 0) mask[word] = b;
    }
}

// ---------------------------------------------------------------------------
// hconv: X fp32 [4096][256] -> packed bf16x2 hi/lo [m][k/2]
// ---------------------------------------------------------------------------
__global__ __launch_bounds__(256)
void hconv_kernel(const float* __restrict__ X,
                  uint32_t* __restrict__ xh,
                  uint32_t* __restrict__ xl) {
    int v = blockIdx.x * 256 + threadIdx.x;
    int row = v >> 5;
    int c = v & 31;
    const float* src = &X[(size_t)row * FDIM + c * 8];
    float4 a = *reinterpret_cast<const float4*>(src);
    float4 b = *reinterpret_cast<const float4*>(src + 4);
    uint32_t hw[4], lw[4];
    split2(a.x, a.y, hw[0], lw[0]);
    split2(a.z, a.w, hw[1], lw[1]);
    split2(b.x, b.y, hw[2], lw[2]);
    split2(b.z, b.w, hw[3], lw[3]);
    size_t off = (size_t)row * 128 + c * 4;
    *reinterpret_cast<uint4*>(&xh[off]) = make_uint4(hw[0], hw[1], hw[2], hw[3]);
    *reinterpret_cast<uint4*>(&xl[off]) = make_uint4(lw[0], lw[1], lw[2], lw[3]);
}

// ---------------------------------------------------------------------------
// wtconv: W fp32 [k][n] -> WT packed [n][k/2] hi/lo. blockIdx.z picks matrix.
// ---------------------------------------------------------------------------
__global__ __launch_bounds__(256)
void wtconv_kernel(const float* __restrict__ W0, const float* __restrict__ W1,
                   const float* __restrict__ W2, const float* __restrict__ W3,
                   uint32_t* __restrict__ wth, uint32_t* __restrict__ wtl) {
    __shared__ float tile[64][33];
    const float* Ws[4] = {W0, W1, W2, W3};
    const float* W = Ws[blockIdx.z];
    uint32_t* oth = wth + (size_t)blockIdx.z * (FDIM * FDIM / 2);
    uint32_t* otl = wtl + (size_t)blockIdx.z * (FDIM * FDIM / 2);
    const int tid = threadIdx.x;
    const int kt = blockIdx.x * 64;
    const int nt = blockIdx.y * 32;
    {
        int r = tid >> 2;
        int c8 = (tid & 3) * 8;
        float4 v0 = *reinterpret_cast<const float4*>(&W[(size_t)(kt + r) * FDIM + nt + c8]);
        float4 v1 = *reinterpret_cast<const float4*>(&W[(size_t)(kt + r) * FDIM + nt + c8 + 4]);
        tile[r][c8 + 0] = v0.x; tile[r][c8 + 1] = v0.y;
        tile[r][c8 + 2] = v0.z; tile[r][c8 + 3] = v0.w;
        tile[r][c8 + 4] = v1.x; tile[r][c8 + 5] = v1.y;
        tile[r][c8 + 6] = v1.z; tile[r][c8 + 7] = v1.w;
    }
    __syncthreads();
    {
        int n = tid >> 3;
        int kp = (tid & 7) * 4;
        uint32_t hw[4], lw[4];
        #pragma unroll
        for (int q = 0; q < 4; q++) {
            int k = 2 * (kp + q);
            split2(tile[k][n], tile[k + 1][n], hw[q], lw[q]);
        }
        size_t off = (size_t)(nt + n) * (FDIM / 2) + (kt >> 1) + kp;
        *reinterpret_cast<uint4*>(&oth[off]) = make_uint4(hw[0], hw[1], hw[2], hw[3]);
        *reinterpret_cast<uint4*>(&otl[off]) = make_uint4(lw[0], lw[1], lw[2], lw[3]);
    }
}

// ---------------------------------------------------------------------------
// HMMA GEMM (unchanged from R14): C = A @ W, 128x64 tiles
// ---------------------------------------------------------------------------
__global__ __launch_bounds__(256)
void gemm_hmma_kernel(const uint32_t* __restrict__ ah,
                      const uint32_t* __restrict__ al,
                      const uint32_t* __restrict__ wth,
                      const uint32_t* __restrict__ wtl,
                      float* __restrict__ Cf,
                      uint32_t* __restrict__ oh,
                      uint32_t* __restrict__ ol,
                      int mode) {
    extern __shared__ __align__(16) uint32_t ws[];
    const int tid  = threadIdx.x;
    const int lane = tid & 31;
    const int warp = tid >> 5;
    const int mq = warp & 3;
    const int nh = warp >> 2;
    const int m0 = blockIdx.y * 128;
    const int n0 = blockIdx.x * 64;
    const uint32_t sbase = smem_u32(ws);

    const int rowA  = lane & 15;
    const int koA   = lane >> 4;
    const int mlocB = lane >> 3;
    const int ntlB  = mlocB >> 1;
    const int koB   = mlocB & 1;
    const int rowBl = lane & 7;
    const int g    = lane >> 2;
    const int tig  = lane & 3;

    float acc[2][4][4] = {};

    auto stage = [&](int kc, int b) {
        uint32_t base = b * 12288u;
        #pragma unroll
        for (int k = 0; k < 8; k++) {
            int idx = k * 256 + tid;
            int half = idx >> 10;
            int rem  = idx & 1023;
            int r = rem >> 3, c = rem & 7;
            const uint32_t* src = (half ? al : ah) +
                (size_t)(m0 + r) * 128 + kc * 32 + c * 4;
            cp_async16(sbase + (base + half * 4096u + r * 32 + ((c ^ (r & 7)) * 4)) * 4,
                       src);
        }
        #pragma unroll
        for (int k = 0; k < 4; k++) {
            int idx = k * 256 + tid;
            int half = idx >> 9;
            int rem  = idx & 511;
            int r = rem >> 3, c = rem & 7;
            const uint32_t* src = (half ? wtl : wth) +
                (size_t)(n0 + r) * 128 + kc * 32 + c * 4;
            cp_async16(sbase + (base + 8192u + half * 2048u + r * 32 +
                                ((c ^ (r & 7)) * 4)) * 4,
                       src);
        }
        CP_COMMIT();
    };

    stage(0, 0);
    CP_WAIT0();
    __syncthreads();

    for (int kc = 0; kc < 4; kc++) {
        if (kc < 3) stage(kc + 1, (kc + 1) & 1);
        const int b = kc & 1;
        const uint32_t AH = sbase + (b * 12288u) * 4;
        const uint32_t AL = AH + 4096u * 4;
        const uint32_t BH = sbase + (b * 12288u + 8192u) * 4;
        const uint32_t BL = BH + 2048u * 4;
        #pragma unroll
        for (int ksl = 0; ksl < 4; ksl++) {
            uint32_t ahf[2][4], alf[2][4];
            #pragma unroll
            for (int mt = 0; mt < 2; mt++) {
                int rin = mq * 32 + mt * 16 + rowA;
                uint32_t off = rin * 128 + (((2 * ksl + koA) ^ (rin & 7)) << 4);
                ldsm_x4(ahf[mt][0], ahf[mt][1], ahf[mt][2], ahf[mt][3], AH + off);
                ldsm_x4(alf[mt][0], alf[mt][1], alf[mt][2], alf[mt][3], AL + off);
            }
            #pragma unroll
            for (int ntp = 0; ntp < 2; ntp++) {
                int fin = nh * 32 + ntp * 16 + ntlB * 8 + rowBl;
                uint32_t off = fin * 128 + (((2 * ksl + koB) ^ (fin & 7)) << 4);
                uint32_t bh0, bh1, bh2, bh3, bl0, bl1, bl2, bl3;
                ldsm_x4(bh0, bh1, bh2, bh3, BH + off);
                ldsm_x4(bl0, bl1, bl2, bl3, BL + off);
                #pragma unroll
                for (int mt = 0; mt < 2; mt++) {
                    int nt0 = ntp * 2;
                    mma_bf16(acc[mt][nt0][0], acc[mt][nt0][1],
                             acc[mt][nt0][2], acc[mt][nt0][3],
                             ahf[mt][0], ahf[mt][1], ahf[mt][2], ahf[mt][3],
                             bh0, bh1);
                    mma_bf16(acc[mt][nt0][0], acc[mt][nt0][1],
                             acc[mt][nt0][2], acc[mt][nt0][3],
                             ahf[mt][0], ahf[mt][1], ahf[mt][2], ahf[mt][3],
                             bl0, bl1);
                    mma_bf16(acc[mt][nt0][0], acc[mt][nt0][1],
                             acc[mt][nt0][2], acc[mt][nt0][3],
                             alf[mt][0], alf[mt][1], alf[mt][2], alf[mt][3],
                             bh0, bh1);
                    mma_bf16(acc[mt][nt0 + 1][0], acc[mt][nt0 + 1][1],
                             acc[mt][nt0 + 1][2], acc[mt][nt0 + 1][3],
                             ahf[mt][0], ahf[mt][1], ahf[mt][2], ahf[mt][3],
                             bh2, bh3);
                    mma_bf16(acc[mt][nt0 + 1][0], acc[mt][nt0 + 1][1],
                             acc[mt][nt0 + 1][2], acc[mt][nt0 + 1][3],
                             ahf[mt][0], ahf[mt][1], ahf[mt][2], ahf[mt][3],
                             bl2, bl3);
                    mma_bf16(acc[mt][nt0 + 1][0], acc[mt][nt0 + 1][1],
                             acc[mt][nt0 + 1][2], acc[mt][nt0 + 1][3],
                             alf[mt][0], alf[mt][1], alf[mt][2], alf[mt][3],
                             bh2, bh3);
                }
            }
        }
        if (kc < 3) CP_WAIT0();
        __syncthreads();
    }

    #pragma unroll
    for (int mt = 0; mt < 2; mt++) {
        int r0 = m0 + mq * 32 + mt * 16 + g;
        int r1 = r0 + 8;
        #pragma unroll
        for (int nt = 0; nt < 4; nt++) {
            int f = n0 + nh * 32 + nt * 8 + 2 * tig;
            if (mode == 1) {
                *reinterpret_cast<float2*>(&Cf[(size_t)r0 * FDIM + f]) =
                    make_float2(acc[mt][nt][0], acc[mt][nt][1]);
                *reinterpret_cast<float2*>(&Cf[(size_t)r1 * FDIM + f]) =
                    make_float2(acc[mt][nt][2], acc[mt][nt][3]);
            } else {
                uint32_t hw, lw;
                split2(acc[mt][nt][0], acc[mt][nt][1], hw, lw);
                oh[(size_t)r0 * 128 + (f >> 1)] = hw;
                ol[(size_t)r0 * 128 + (f >> 1)] = lw;
                split2(acc[mt][nt][2], acc[mt][nt][3], hw, lw);
                oh[(size_t)r1 * 128 + (f >> 1)] = hw;
                ol[(size_t)r1 * 128 + (f >> 1)] = lw;
            }
        }
    }
}

// ---------------------------------------------------------------------------
// f1/f2 matvecs
// ---------------------------------------------------------------------------
__global__ void fvec_kernel(const float* __restrict__ Wh,
                            const float* __restrict__ a,
                            float* __restrict__ f1,
                            float* __restrict__ f2) {
    const int warp = threadIdx.x >> 5;
    const int lane = threadIdx.x & 31;
    const int row  = blockIdx.x * 8 + warp;
    float s1 = 0.f, s2 = 0.f;
    #pragma unroll
    for (int k = lane; k < FDIM; k += 32) {
        float w = Wh[row * FDIM + k];
        s1 += w * a[k];
        s2 += w * a[FDIM + k];
    }
    #pragma unroll
    for (int off = 16; off; off >>= 1) {
        s1 += __shfl_xor_sync(0xffffffffu, s1, off);
        s2 += __shfl_xor_sync(0xffffffffu, s2, off);
    }
    if (lane == 0) { f1[row] = s1; f2[row] = s2; }
}

// ---------------------------------------------------------------------------
// Row max via monotonicity
// ---------------------------------------------------------------------------
__global__ __launch_bounds__(256)
void rowmax_kernel(const uint32_t* __restrict__ mask,
                   const float* __restrict__ f1,
                   const float* __restrict__ f2,
                   float* __restrict__ m) {
    __shared__ __align__(16) float f2s[NN];
    __shared__ uint32_t ms[8][128];
    const int tid  = threadIdx.x;
    const int lane = tid & 31;
    const int warp = tid >> 5;
    const int row0 = blockIdx.x * 8;

    #pragma unroll
    for (int k = 0; k < 4; k++) {
        int c = k * 256 + tid;
        reinterpret_cast<float4*>(f2s)[c] =
            reinterpret_cast<const float4*>(f2)[c];
    }
    #pragma unroll
    for (int k = 0; k < 4; k++) {
        int i = k * 256 + tid;
        ms[i >> 7][i & 127] = mask[(size_t)(row0 + (i >> 7)) * 128 + (i & 127)];
    }
    __syncthreads();

    float mx = -1.0e30f;
    #pragma unroll 8
    for (int k = 0; k < 128; k++) {
        uint32_t w = ms[warp][k];
        float v = f2s[k * 32 + lane];
        if ((w >> lane) & 1u) mx = fmaxf(mx, v);
    }
    #pragma unroll
    for (int off = 16; off; off >>= 1)
        mx = fmaxf(mx, __shfl_xor_sync(0xffffffffu, mx, off));
    if (lane == 0) {
        int row = row0 + warp;
        if (mx < -1.0e29f) {
            m[row] = NEG_INF_V;
        } else {
            float s = f1[row] + mx;
            m[row] = s > 0.f ? s : ALPHA_LR * s;
        }
    }
}

// ---------------------------------------------------------------------------
// wconv: Wh[j][f] fp32 -> packed bf16x2 j-pair words [f][j/2], hi & lo
// ---------------------------------------------------------------------------
__global__ __launch_bounds__(256)
void wconv_kernel(const float* __restrict__ Wh,
                  uint32_t* __restrict__ whh,
                  uint32_t* __restrict__ whl) {
    __shared__ float tile[64][33];
    const int tid = threadIdx.x;
    const int jt = blockIdx.x * 64;
    const int ft = blockIdx.y * 32;
    {
        int r = tid >> 2;
        int c8 = (tid & 3) * 8;
        float4 v0 = *reinterpret_cast<const float4*>(
            &Wh[(size_t)(jt + r) * FDIM + ft + c8]);
        float4 v1 = *reinterpret_cast<const float4*>(
            &Wh[(size_t)(jt + r) * FDIM + ft + c8 + 4]);
        tile[r][c8 + 0] = v0.x; tile[r][c8 + 1] = v0.y;
        tile[r][c8 + 2] = v0.z; tile[r][c8 + 3] = v0.w;
        tile[r][c8 + 4] = v1.x; tile[r][c8 + 5] = v1.y;
        tile[r][c8 + 6] = v1.z; tile[r][c8 + 7] = v1.w;
    }
    __syncthreads();
    {
        int f = tid >> 3;
        int j2l = (tid & 7) * 4;
        uint32_t hw[4], lw[4];
        #pragma unroll
        for (int q = 0; q < 4; q++) {
            int j = 2 * (j2l + q);
            split2(tile[j][f], tile[j + 1][f], hw[q], lw[q]);
        }
        size_t off = (size_t)(ft + f) * (NN / 2) + (jt >> 1) + j2l;
        *reinterpret_cast<uint4*>(&whh[off]) = make_uint4(hw[0], hw[1], hw[2], hw[3]);
        *reinterpret_cast<uint4*>(&whl[off]) = make_uint4(lw[0], lw[1], lw[2], lw[3]);
    }
}

// ---------------------------------------------------------------------------
// Fused attention on HMMA: 64 rows x 256 f x j-quarter (1024 j, 32 tiles of
// 32 j). grid (64, 4) = 256 CTAs, 2 CTAs/SM (80 KB smem).
// Smem words: B buf b at b*8192 (hi 4096 = 256f x 16w, lo +4096);
//             P buf b at 16384 + b*2048 (hi 1024 = 64r x 16w, lo +1024).
// Row stride 64B (4 chunks); swizzle: chunk ^= (row>>1)&3 (conflict-free).
// ---------------------------------------------------------------------------
__global__ __launch_bounds__(256, 2)
void attn_kernel(const uint32_t* __restrict__ whh,
                 const uint32_t* __restrict__ whl,
                 const uint32_t* __restrict__ mask,
                 const float* __restrict__ f1,
                 const float* __restrict__ f2,
                 const float* __restrict__ m,
                 float* __restrict__ pacc,
                 float* __restrict__ lpart) {
    extern __shared__ __align__(16) uint32_t ws[];

    const int tid  = threadIdx.x;
    const int lane = tid & 31;
    const int warp = tid >> 5;
    const int g    = lane >> 2;
    const int tig  = lane & 3;
    const int row0 = blockIdx.x * ROWS;
    const int jq   = blockIdx.y;               // j quarter (1024 j)
    const uint32_t sbase = smem_u32(ws);

    // P production: thread owns row prow, 8 j's [jb8, jb8+8) of each tile
    const int prow = tid >> 2;                 // 0..63
    const int jb8  = (tid & 3) * 8;
    const int grow = row0 + prow;
    const float f1r = f1[grow];
    const float mr  = m[grow];
    const uint32_t* mrow = mask + (size_t)grow * 128 + jq * 32;
    float ls = 0.f;

    float acc[4][4][4] = {};                   // [mt][nt][reg]

    const int rowA  = lane & 15;
    const int koA   = lane >> 4;
    const int mlocB = lane >> 3;
    const int ntlB  = mlocB >> 1;
    const int koB   = mlocB & 1;
    const int rowBl = lane & 7;

    float4 fv0, fv1;
    uint32_t mw;

    // ---- prologue: tile 0 ----
    fv0 = *reinterpret_cast<const float4*>(&f2[jq * 1024 + jb8]);
    fv1 = *reinterpret_cast<const float4*>(&f2[jq * 1024 + jb8 + 4]);
    mw  = mrow[0];
    #pragma unroll
    for (int k = 0; k < 8; k++) {              // B: 2048 uint4
        int idx = k * 256 + tid;
        int half = idx >> 10;
        int rem  = idx & 1023;
        int f = rem >> 2, c = rem & 3;
        const uint32_t* src = (half ? whl : whh) +
            (size_t)f * (NN / 2) + jq * 512 + c * 4;
        cp_async16(sbase + (half * 4096 + f * 16 + ((c ^ ((f >> 1) & 3)) * 4)) * 4,
                   src);
    }
    CP_COMMIT();
    {   // produce p tile 0 into buf 0
        uint32_t bits = (mw >> jb8) & 0xffu;
        const float fvr[8] = {fv0.x, fv0.y, fv0.z, fv0.w,
                              fv1.x, fv1.y, fv1.z, fv1.w};
        float pv[8];
        #pragma unroll
        for (int q = 0; q < 8; q++) {
            float s = f1r + fvr[q];
            float e = s > 0.f ? s : ALPHA_LR * s;
            float sc = ((bits >> q) & 1u) ? e : NEG_INF_V;
            pv[q] = __expf(sc - mr);
            ls += pv[q];
        }
        uint32_t hw[4], lw[4];
        #pragma unroll
        for (int u = 0; u < 4; u++) split2(pv[2 * u], pv[2 * u + 1], hw[u], lw[u]);
        int cb = tid & 3;
        uint32_t* ph = ws + 16384 + prow * 16;
        uint32_t* pl = ph + 1024;
        uint32_t so = (cb ^ ((prow >> 1) & 3)) * 4;
        *reinterpret_cast<uint4*>(ph + so) = make_uint4(hw[0], hw[1], hw[2], hw[3]);
        *reinterpret_cast<uint4*>(pl + so) = make_uint4(lw[0], lw[1], lw[2], lw[3]);
    }
    fv0 = *reinterpret_cast<const float4*>(&f2[jq * 1024 + 32 + jb8]);
    fv1 = *reinterpret_cast<const float4*>(&f2[jq * 1024 + 32 + jb8 + 4]);
    mw  = mrow[1];
    CP_WAIT0();
    __syncthreads();

    for (int t = 0; t < 32; t++) {
        if (t < 31) {
            const int b = (t + 1) & 1;
            // stage B tile t+1
            #pragma unroll
            for (int k = 0; k < 8; k++) {
                int idx = k * 256 + tid;
                int half = idx >> 10;
                int rem  = idx & 1023;
                int f = rem >> 2, c = rem & 3;
                const uint32_t* src = (half ? whl : whh) +
                    (size_t)f * (NN / 2) + jq * 512 + (t + 1) * 16 + c * 4;
                cp_async16(sbase + (b * 8192 + half * 4096 + f * 16 +
                                    ((c ^ ((f >> 1) & 3)) * 4)) * 4,
                           src);
            }
            CP_COMMIT();
            // produce p tile t+1
            uint32_t bits = (mw >> jb8) & 0xffu;
            const float fvr[8] = {fv0.x, fv0.y, fv0.z, fv0.w,
                                  fv1.x, fv1.y, fv1.z, fv1.w};
            float pv[8];
            #pragma unroll
            for (int q = 0; q < 8; q++) {
                float s = f1r + fvr[q];
                float e = s > 0.f ? s : ALPHA_LR * s;
                float sc = ((bits >> q) & 1u) ? e : NEG_INF_V;
                pv[q] = __expf(sc - mr);
                ls += pv[q];
            }
            uint32_t hw[4], lw[4];
            #pragma unroll
            for (int u = 0; u < 4; u++)
                split2(pv[2 * u], pv[2 * u + 1], hw[u], lw[u]);
            int cb = tid & 3;
            uint32_t* ph = ws + 16384 + b * 2048 + prow * 16;
            uint32_t* pl = ph + 1024;
            uint32_t so = (cb ^ ((prow >> 1) & 3)) * 4;
            *reinterpret_cast<uint4*>(ph + so) =
                make_uint4(hw[0], hw[1], hw[2], hw[3]);
            *reinterpret_cast<uint4*>(pl + so) =
                make_uint4(lw[0], lw[1], lw[2], lw[3]);
            // regs for tile t+2
            int tn = (t + 2) & 31;
            fv0 = *reinterpret_cast<const float4*>(&f2[jq * 1024 + tn * 32 + jb8]);
            fv1 = *reinterpret_cast<const float4*>(&f2[jq * 1024 + tn * 32 + jb8 + 4]);
            mw  = mrow[tn];
        }

        // ---- HMMA phase on buffer t&1 (k-dim 32 -> 2 k16 steps) ----
        {
            const int b = t & 1;
            const uint32_t BH = sbase + (b * 8192) * 4;
            const uint32_t BL = BH + 4096 * 4;
            const uint32_t PH = sbase + (16384 + b * 2048) * 4;
            const uint32_t PL = PH + 1024 * 4;
            #pragma unroll
            for (int ks = 0; ks < 2; ks++) {
                uint32_t ah[4][4], al[4][4];
                #pragma unroll
                for (int mt = 0; mt < 4; mt++) {
                    int rin = mt * 16 + rowA;
                    uint32_t off = rin * 64 +
                        (((2 * ks + koA) ^ ((rin >> 1) & 3)) << 4);
                    ldsm_x4(ah[mt][0], ah[mt][1], ah[mt][2], ah[mt][3], PH + off);
                    ldsm_x4(al[mt][0], al[mt][1], al[mt][2], al[mt][3], PL + off);
                }
                #pragma unroll
                for (int ntp = 0; ntp < 2; ntp++) {
                    int fin = warp * 32 + ntp * 16 + ntlB * 8 + rowBl;
                    uint32_t off = fin * 64 +
                        (((2 * ks + koB) ^ ((fin >> 1) & 3)) << 4);
                    uint32_t bh0, bh1, bh2, bh3, bl0, bl1, bl2, bl3;
                    ldsm_x4(bh0, bh1, bh2, bh3, BH + off);
                    ldsm_x4(bl0, bl1, bl2, bl3, BL + off);
                    #pragma unroll
                    for (int mt = 0; mt < 4; mt++) {
                        int n0 = ntp * 2;
                        mma_bf16(acc[mt][n0][0], acc[mt][n0][1],
                                 acc[mt][n0][2], acc[mt][n0][3],
                                 ah[mt][0], ah[mt][1], ah[mt][2], ah[mt][3],
                                 bh0, bh1);
                        mma_bf16(acc[mt][n0][0], acc[mt][n0][1],
                                 acc[mt][n0][2], acc[mt][n0][3],
                                 ah[mt][0], ah[mt][1], ah[mt][2], ah[mt][3],
                                 bl0, bl1);
                        mma_bf16(acc[mt][n0][0], acc[mt][n0][1],
                                 acc[mt][n0][2], acc[mt][n0][3],
                                 al[mt][0], al[mt][1], al[mt][2], al[mt][3],
                                 bh0, bh1);
                        mma_bf16(acc[mt][n0 + 1][0], acc[mt][n0 + 1][1],
                                 acc[mt][n0 + 1][2], acc[mt][n0 + 1][3],
                                 ah[mt][0], ah[mt][1], ah[mt][2], ah[mt][3],
                                 bh2, bh3);
                        mma_bf16(acc[mt][n0 + 1][0], acc[mt][n0 + 1][1],
                                 acc[mt][n0 + 1][2], acc[mt][n0 + 1][3],
                                 ah[mt][0], ah[mt][1], ah[mt][2], ah[mt][3],
                                 bl2, bl3);
                        mma_bf16(acc[mt][n0 + 1][0], acc[mt][n0 + 1][1],
                                 acc[mt][n0 + 1][2], acc[mt][n0 + 1][3],
                                 al[mt][0], al[mt][1], al[mt][2], al[mt][3],
                                 bh2, bh3);
                    }
                }
            }
        }
        if (t < 31) CP_WAIT0();
        __syncthreads();
    }

    // l: reduce over the 4 threads sharing a p-row, write partial
    ls += __shfl_xor_sync(0xffffffffu, ls, 1);
    ls += __shfl_xor_sync(0xffffffffu, ls, 2);
    if ((tid & 3) == 0) lpart[(size_t)jq * NN + grow] = ls;

    // Partial numerators to gmem
    #pragma unroll
    for (int mt = 0; mt < 4; mt++) {
        int r0 = row0 + mt * 16 + g;
        int r1 = r0 + 8;
        #pragma unroll
        for (int nt = 0; nt < 4; nt++) {
            int f = warp * 32 + nt * 8 + 2 * tig;
            *reinterpret_cast<float2*>(
                &pacc[((size_t)jq * NN + r0) * FDIM + f]) =
                make_float2(acc[mt][nt][0], acc[mt][nt][1]);
            *reinterpret_cast<float2*>(
                &pacc[((size_t)jq * NN + r1) * FDIM + f]) =
                make_float2(acc[mt][nt][2], acc[mt][nt][3]);
        }
    }
}

// ---------------------------------------------------------------------------
// Combine 4 partials: v = ELU(Σnum/Σl); fp32 out (mode 1) or packed h (mode 0)
// ---------------------------------------------------------------------------
__global__ void combine_kernel(const float* __restrict__ pacc,
                               const float* __restrict__ lpart,
                               float* __restrict__ outf,
                               uint32_t* __restrict__ oh,
                               uint32_t* __restrict__ ol,
                               int mode) {
    int v = blockIdx.x * 256 + threadIdx.x;    // float4 index
    int row = v >> 6;
    int c = (v & 63) * 4;
    float4 o = make_float4(0.f, 0.f, 0.f, 0.f);
    float lsum = 0.f;
    #pragma unroll
    for (int q = 0; q < JSPLIT; q++) {
        float4 a = *reinterpret_cast<const float4*>(
            &pacc[((size_t)q * NN + row) * FDIM + c]);
        o.x += a.x; o.y += a.y; o.z += a.z; o.w += a.w;
        lsum += lpart[(size_t)q * NN + row];
    }
    float inv = 1.f / lsum;
    o.x *= inv; o.y *= inv; o.z *= inv; o.w *= inv;
    o.x = o.x > 0.f ? o.x : (__expf(o.x) - 1.f);
    o.y = o.y > 0.f ? o.y : (__expf(o.y) - 1.f);
    o.z = o.z > 0.f ? o.z : (__expf(o.z) - 1.f);
    o.w = o.w > 0.f ? o.w : (__expf(o.w) - 1.f);
    if (mode == 1) {
        *reinterpret_cast<float4*>(&outf[(size_t)row * FDIM + c]) = o;
    } else {
        uint32_t h0, l0, h1, l1;
        split2(o.x, o.y, h0, l0);
        split2(o.z, o.w, h1, l1);
        size_t off = (size_t)row * 128 + (c >> 1);
        *reinterpret_cast<uint2*>(&oh[off]) = make_uint2(h0, h1);
        *reinterpret_cast<uint2*>(&ol[off]) = make_uint2(l0, l1);
    }
}

// ---------------------------------------------------------------------------
extern "C" void kernel_launch(void* const* d_in, const int* in_sizes, int n_in,
                              void* d_out, int out_size) {
    const float* input = (const float*)d_in[0];
    const int*   adj   = (const int*)  d_in[1];
    const float* W0    = (const float*)d_in[2];
    const float* Wl[3] = {(const float*)d_in[3], (const float*)d_in[5],
                          (const float*)d_in[7]};
    const float* al[3] = {(const float*)d_in[4], (const float*)d_in[6],
                          (const float*)d_in[8]};
    float* out = (float*)d_out;

    float *Wh, *f1, *f2, *m, *pacc, *lpart;
    uint32_t *mask, *whh, *whl, *xh, *xl, *yh, *yl, *wth, *wtl;
    cudaGetSymbolAddress((void**)&Wh,    g_Wh);
    cudaGetSymbolAddress((void**)&f1,    g_f1);
    cudaGetSymbolAddress((void**)&f2,    g_f2);
    cudaGetSymbolAddress((void**)&m,     g_m);
    cudaGetSymbolAddress((void**)&mask,  g_mask);
    cudaGetSymbolAddress((void**)&whh,   g_whh);
    cudaGetSymbolAddress((void**)&whl,   g_whl);
    cudaGetSymbolAddress((void**)&pacc,  g_pacc);
    cudaGetSymbolAddress((void**)&lpart, g_lpart);
    cudaGetSymbolAddress((void**)&xh,    g_xh);
    cudaGetSymbolAddress((void**)&xl,    g_xl);
    cudaGetSymbolAddress((void**)&yh,    g_yh);
    cudaGetSymbolAddress((void**)&yl,    g_yl);
    cudaGetSymbolAddress((void**)&wth,   g_wth);
    cudaGetSymbolAddress((void**)&wtl,   g_wtl);

    const int ATTN_SMEM = 20480 * 4;               // 80 KB -> 2 CTAs/SM
    const int GEMM_SMEM = 24576 * 4;               // 96 KB
    static bool attr_set = false;
    if (!attr_set) {
        cudaFuncSetAttribute(attn_kernel,
                             cudaFuncAttributeMaxDynamicSharedMemorySize,
                             ATTN_SMEM);
        cudaFuncSetAttribute(gemm_hmma_kernel,
                             cudaFuncAttributeMaxDynamicSharedMemorySize,
                             GEMM_SMEM);
        attr_set = true;
    }

    dim3 gemmGrid(FDIM / 64, NN / 128);            // (4, 32)
    dim3 wconvGrid(NN / 64, FDIM / 32);            // (64, 8)
    dim3 wtGrid(FDIM / 64, FDIM / 32, 4);          // (4, 8, 4)
    dim3 attnGrid(NN / ROWS, JSPLIT);              // (64, 4) = 256 CTAs

    pack_kernel<<<1024, 256>>>(adj, mask);
    wtconv_kernel<<<wtGrid, 256>>>(W0, Wl[0], Wl[1], Wl[2], wth, wtl);
    hconv_kernel<<<512, 256>>>(input, xh, xl);
    gemm_hmma_kernel<<<gemmGrid, 256, GEMM_SMEM>>>(
        xh, xl, wth, wtl, nullptr, yh, yl, 0);

    uint32_t* curh = yh;
    uint32_t* curl = yl;
    uint32_t* nxth = xh;
    uint32_t* nxtl = xl;
    const size_t WT_OFF = (size_t)FDIM * FDIM / 2;

    for (int l = 0; l < 3; l++) {
        gemm_hmma_kernel<<<gemmGrid, 256, GEMM_SMEM>>>(
            curh, curl, wth + (l + 1) * WT_OFF, wtl + (l + 1) * WT_OFF,
            Wh, nullptr, nullptr, 1);
        fvec_kernel<<<NN / 8, 256>>>(Wh, al[l], f1, f2);
        rowmax_kernel<<<NN / 8, 256>>>(mask, f1, f2, m);
        wconv_kernel<<<wconvGrid, 256>>>(Wh, whh, whl);
        attn_kernel<<<attnGrid, 256, ATTN_SMEM>>>(whh, whl, mask, f1, f2, m,
                                                  pacc, lpart);
        if (l == 2) {
            combine_kernel<<<NN * FDIM / 4 / 256, 256>>>(
                pacc, lpart, out, nullptr, nullptr, 1);
        } else {
            combine_kernel<<<NN * FDIM / 4 / 256, 256>>>(
                pacc, lpart, nullptr, nxth, nxtl, 0);
            uint32_t* th = curh; uint32_t* tl = curl;
            curh = nxth; curl = nxtl;
            nxth = th;  nxtl = tl;
        }
    }
}